// round 5
// baseline (speedup 1.0000x reference)
#include <cuda_runtime.h>
#include <cuda_bf16.h>
#include <cstdint>
#include <math.h>

// Problem constants
#define Bb   4
#define Tt   2048
#define Cc   2048
#define Hh   32
#define Nn   64
#define BT   (Bb*Tt)          // 8192
#define DMIX 32
#define DDEC 64
#define BIGN (BT*Cc)          // 16,777,216
#define WN   (Cc*Cc)          // 4,194,304

// ---------------- scratch (device globals; no runtime allocation) ----------
__device__ float g_dxprev[BIGN];
__device__ float g_xxx  [BIGN];
__device__ float g_xw   [BIGN];
__device__ float g_xv2  [BIGN];
__device__ float g_r    [BIGN];
__device__ float g_k    [BIGN];
__device__ float g_v    [BIGN];
__device__ float g_v2   [BIGN];
__device__ float g_decay[BIGN];
__device__ float g_ys   [BIGN];
__device__ float g_hpre [BT*160];
__device__ float g_tmpw [BT*DDEC];
__device__ float g_tmpv [BT*DDEC];

// bf16 hi/lo planes: [0..N) = hi, [N..2N) = lo
__device__ __nv_bfloat16 g_pxr [2*BIGN];
__device__ __nv_bfloat16 g_pxk [2*BIGN];
__device__ __nv_bfloat16 g_pxv [2*BIGN];
__device__ __nv_bfloat16 g_pxv2[2*BIGN];
__device__ __nv_bfloat16 g_pyn [2*BIGN];
__device__ __nv_bfloat16 g_pwr [2*WN];
__device__ __nv_bfloat16 g_pwk [2*WN];
__device__ __nv_bfloat16 g_pwv [2*WN];
__device__ __nv_bfloat16 g_pwo [2*WN];

__device__ __forceinline__ void split2(float f, __nv_bfloat16& h, __nv_bfloat16& l) {
    h = __float2bfloat16_rn(f);
    l = __float2bfloat16_rn(f - __bfloat162float(h));
}

// ---------------- E1: token shift ------------------------------------------
__global__ void k_shift(const float* __restrict__ x,
                        const float* __restrict__ shift,
                        const float* __restrict__ maa_x) {
    int idx = blockIdx.x * 256 + threadIdx.x;
    if (idx >= BIGN) return;
    int c  = idx % Cc;
    int bt = idx / Cc;
    int t  = bt % Tt;
    int b  = bt / Tt;
    float xv   = x[idx];
    float prev = (t == 0) ? shift[b * Cc + c] : x[idx - Cc];
    float dx   = prev - xv;
    g_dxprev[idx] = dx;
    g_xxx[idx]    = xv + dx * maa_x[c];
}

// ---------------- weight fp32 -> bf16 hi/lo planes --------------------------
__global__ void k_conv(const float* __restrict__ src,
                       __nv_bfloat16* __restrict__ dst, int n) {
    int i = blockIdx.x * 256 + threadIdx.x;
    if (i >= n) return;
    __nv_bfloat16 h, l;
    split2(src[i], h, l);
    dst[i]     = h;
    dst[n + i] = l;
}

// =============================================================================
// Plane GEMM: C[M,N] = A*B, A/B given as bf16 hi/lo planes.
// bf16x3: a*b ~= ah*bh + ah*bl + al*bh. Tile 128x128, BK=32, 4-stage cp.async.
// =============================================================================
#define PASTR 40
#define PBSTR 136
#define SA_H 0
#define SA_L 5120
#define SB_H 10240
#define SB_L 14592
#define PSTG 18944
#define PSTGB (PSTG*2)
#define PSTAGES 4

__device__ __forceinline__ void ldsm4(unsigned int* r, unsigned int addr) {
    asm volatile("ldmatrix.sync.aligned.m8n8.x4.shared.b16 {%0,%1,%2,%3},[%4];"
                 : "=r"(r[0]), "=r"(r[1]), "=r"(r[2]), "=r"(r[3]) : "r"(addr));
}
__device__ __forceinline__ void ldsm4t(unsigned int* r, unsigned int addr) {
    asm volatile("ldmatrix.sync.aligned.m8n8.x4.trans.shared.b16 {%0,%1,%2,%3},[%4];"
                 : "=r"(r[0]), "=r"(r[1]), "=r"(r[2]), "=r"(r[3]) : "r"(addr));
}
__device__ __forceinline__ void mma16816(float* c, const unsigned int* a,
                                         unsigned int b0, unsigned int b1) {
    asm volatile("mma.sync.aligned.m16n8k16.row.col.f32.bf16.bf16.f32 "
                 "{%0,%1,%2,%3},{%4,%5,%6,%7},{%8,%9},{%0,%1,%2,%3};"
                 : "+f"(c[0]), "+f"(c[1]), "+f"(c[2]), "+f"(c[3])
                 : "r"(a[0]), "r"(a[1]), "r"(a[2]), "r"(a[3]), "r"(b0), "r"(b1));
}
__device__ __forceinline__ void cpasync16(unsigned int daddr, const void* gp) {
    asm volatile("cp.async.ca.shared.global [%0], [%1], 16;"
                 :: "r"(daddr), "l"(gp));
}

__global__ __launch_bounds__(256, 1)
void k_gemm_p(const __nv_bfloat16* __restrict__ A, size_t aOff,
              const __nv_bfloat16* __restrict__ B, size_t bOff,
              float* __restrict__ C, int M, int N, int K) {
    extern __shared__ __nv_bfloat16 smem[];
    const int tid  = threadIdx.x;
    const int lane = tid & 31;
    const int wid  = tid >> 5;
    const int wm   = wid >> 2;
    const int wn   = wid & 3;
    const int mBase = blockIdx.y * 128;
    const int nBase = blockIdx.x * 128;

    const unsigned int smB = (unsigned int)__cvta_generic_to_shared(smem);

    // cp.async mappings: 8 x 16B per thread per stage
    const int aRow = tid >> 1;          // 0..127
    const int aSeg = (tid & 1) * 2;     // {0,2}
    const int bRow = tid >> 3;          // 0..31
    const int bSeg = (tid & 7) * 2;     // {0..14}

    const __nv_bfloat16* Ah = A;
    const __nv_bfloat16* Al = A + aOff;
    const __nv_bfloat16* Bh = B;
    const __nv_bfloat16* Bl = B + bOff;

    const int kChunks = K >> 5;

    auto issue = [&](int ch) {
        if (ch < kChunks) {
            const unsigned int base = smB + (unsigned int)(ch % PSTAGES) * PSTGB;
            const size_t aG = (size_t)(mBase + aRow) * K + ch * 32;
            const size_t bG = (size_t)(ch * 32 + bRow) * N + nBase;
#pragma unroll
            for (int q = 0; q < 2; q++) {
                int as = aSeg + q, bs = bSeg + q;
                cpasync16(base + (unsigned int)(SA_H + aRow*PASTR + as*8) * 2, Ah + aG + as*8);
                cpasync16(base + (unsigned int)(SA_L + aRow*PASTR + as*8) * 2, Al + aG + as*8);
                cpasync16(base + (unsigned int)(SB_H + bRow*PBSTR + bs*8) * 2, Bh + bG + bs*8);
                cpasync16(base + (unsigned int)(SB_L + bRow*PBSTR + bs*8) * 2, Bl + bG + bs*8);
            }
        }
        asm volatile("cp.async.commit_group;");
    };

    float acc[4][4][4];
#pragma unroll
    for (int i = 0; i < 4; i++)
#pragma unroll
        for (int j = 0; j < 4; j++)
#pragma unroll
            for (int q = 0; q < 4; q++) acc[i][j][q] = 0.f;

    // prologue: fill STAGES-1 stages
    issue(0); issue(1); issue(2);

    for (int ch = 0; ch < kChunks; ch++) {
        asm volatile("cp.async.wait_group 2;" ::: "memory");
        __syncthreads();
        issue(ch + PSTAGES - 1);

        const unsigned int sb = smB + (unsigned int)(ch % PSTAGES) * PSTGB;
#pragma unroll
        for (int ks = 0; ks < 2; ks++) {
            const int k0 = ks * 16;
            unsigned int ah[4][4], al[4][4], bh[2][4], bl[2][4];
#pragma unroll
            for (int mf = 0; mf < 4; mf++) {
                int row = wm * 64 + mf * 16 + (lane & 15);
                int col = k0 + (lane >> 4) * 8;
                unsigned int ad = sb + (unsigned int)(row * PASTR + col) * 2;
                ldsm4(ah[mf], ad + SA_H * 2);
                ldsm4(al[mf], ad + SA_L * 2);
            }
#pragma unroll
            for (int nf2 = 0; nf2 < 2; nf2++) {
                int rowk = k0 + (lane & 15);
                int coln = wn * 32 + nf2 * 16 + (lane >> 4) * 8;
                unsigned int bd = sb + (unsigned int)(rowk * PBSTR + coln) * 2;
                ldsm4t(bh[nf2], bd + SB_H * 2);
                ldsm4t(bl[nf2], bd + SB_L * 2);
            }
#pragma unroll
            for (int mf = 0; mf < 4; mf++) {
#pragma unroll
                for (int nf = 0; nf < 4; nf++) {
                    unsigned int b0h = bh[nf >> 1][(nf & 1) * 2];
                    unsigned int b1h = bh[nf >> 1][(nf & 1) * 2 + 1];
                    unsigned int b0l = bl[nf >> 1][(nf & 1) * 2];
                    unsigned int b1l = bl[nf >> 1][(nf & 1) * 2 + 1];
                    mma16816(acc[mf][nf], ah[mf], b0h, b1h);
                    mma16816(acc[mf][nf], ah[mf], b0l, b1l);
                    mma16816(acc[mf][nf], al[mf], b0h, b1h);
                }
            }
        }
    }

    // epilogue
#pragma unroll
    for (int mf = 0; mf < 4; mf++) {
#pragma unroll
        for (int nf = 0; nf < 4; nf++) {
            int r = mBase + wm * 64 + mf * 16 + (lane >> 2);
            int c = nBase + wn * 32 + nf * 8 + (lane & 3) * 2;
            float2 v0 = make_float2(acc[mf][nf][0], acc[mf][nf][1]);
            float2 v1 = make_float2(acc[mf][nf][2], acc[mf][nf][3]);
            *(float2*)&C[(size_t)r * N + c] = v0;
            *(float2*)&C[(size_t)(r + 8) * N + c] = v1;
        }
    }
}

// ---------------- small-N fp32 GEMM: BM=32, BN=64, BK=32, 256 threads -------
__global__ __launch_bounds__(256)
void k_gemm_small(const float* __restrict__ A, int lda,
                  const float* __restrict__ B, int ldb,
                  float* __restrict__ Cd, int ldc,
                  int M, int N, int K, int act) {
    __shared__ float As[32][36];
    __shared__ float Bs[32][64];
    const int tid = threadIdx.x;
    const int mBase = blockIdx.y * 32;
    const int nBase = blockIdx.x * 64;

    const int r  = tid >> 3;
    const int cg = tid & 7;

    const int arow  = tid >> 3;
    const int acol4 = (tid & 7) * 4;
    const int brow  = tid >> 4;
    const int bcol4 = (tid & 15) * 4;

    float acc[8];
#pragma unroll
    for (int i = 0; i < 8; i++) acc[i] = 0.f;

    const float* Ab = A + (size_t)(mBase + arow) * lda + acol4;

    for (int k0 = 0; k0 < K; k0 += 32) {
        float4 a4 = *(const float4*)(Ab + k0);
        *(float4*)&As[arow][acol4] = a4;

#pragma unroll
        for (int p = 0; p < 2; p++) {
            int row = brow + p * 16;
            int col = nBase + bcol4;
            float4 b4 = make_float4(0.f, 0.f, 0.f, 0.f);
            if (col < N)
                b4 = *(const float4*)(B + (size_t)(k0 + row) * ldb + col);
            *(float4*)&Bs[row][bcol4] = b4;
        }
        __syncthreads();

#pragma unroll
        for (int kk = 0; kk < 32; kk++) {
            float a = As[r][kk];
            float4 b0 = *(const float4*)&Bs[kk][cg * 8];
            float4 b1 = *(const float4*)&Bs[kk][cg * 8 + 4];
            acc[0] += a * b0.x; acc[1] += a * b0.y;
            acc[2] += a * b0.z; acc[3] += a * b0.w;
            acc[4] += a * b1.x; acc[5] += a * b1.y;
            acc[6] += a * b1.z; acc[7] += a * b1.w;
        }
        __syncthreads();
    }

    int row = mBase + r;
#pragma unroll
    for (int j = 0; j < 8; j++) {
        int col = nBase + cg * 8 + j;
        if (col < N) {
            float vv = acc[j];
            if (act == 1) vv = tanhf(vv);
            Cd[(size_t)row * ldc + col] = vv;
        }
    }
}

// ---------------- E2: 5-way LoRA mix -> planes + fp32 xw/xv2 ---------------
__global__ void k_mix(const float* __restrict__ x,
                      const float* __restrict__ w2,
                      const float* __restrict__ mr, const float* __restrict__ mk,
                      const float* __restrict__ mv, const float* __restrict__ mw,
                      const float* __restrict__ mv2) {
    __shared__ float hs[32][160];
    __shared__ float ws[160][32];
    int rowBase = blockIdx.x * 32;
    int colBase = blockIdx.y * 32;
    int tid = threadIdx.x;

    for (int l = tid; l < 32 * 160; l += 256) {
        int rr = l / 160, d = l % 160;
        hs[rr][d] = g_hpre[(rowBase + rr) * 160 + d];
    }
    for (int l = tid; l < 160 * 32; l += 256) {
        int fd = l / 32, cc = l % 32;
        ws[fd][cc] = w2[fd * Cc + colBase + cc];
    }
    __syncthreads();

    int cc = tid % 32;
    int r0 = tid / 32;
    int c  = colBase + cc;
    float tr = mr[c], tk = mk[c], tv = mv[c], tw = mw[c], tv2 = mv2[c];

    for (int rr = r0; rr < 32; rr += 8) {
        float m0 = 0, m1 = 0, m2 = 0, m3 = 0, m4 = 0;
#pragma unroll
        for (int d = 0; d < 32; d++) {
            float h0 = hs[rr][d];
            float h1 = hs[rr][32 + d];
            float h2 = hs[rr][64 + d];
            float h3 = hs[rr][96 + d];
            float h4 = hs[rr][128 + d];
            m0 += h0 * ws[d][cc];
            m1 += h1 * ws[32 + d][cc];
            m2 += h2 * ws[64 + d][cc];
            m3 += h3 * ws[96 + d][cc];
            m4 += h4 * ws[128 + d][cc];
        }
        int idx = (rowBase + rr) * Cc + c;
        float xval = x[idx], dx = g_dxprev[idx];
        float vr  = xval + dx * (tr  + m0);
        float vk  = xval + dx * (tk  + m1);
        float vv  = xval + dx * (tv  + m2);
        float vw  = xval + dx * (tw  + m3);
        float vv2 = xval + dx * (tv2 + m4);

        __nv_bfloat16 h, l;
        split2(vr,  h, l); g_pxr [idx] = h; g_pxr [BIGN + idx] = l;
        split2(vk,  h, l); g_pxk [idx] = h; g_pxk [BIGN + idx] = l;
        split2(vv,  h, l); g_pxv [idx] = h; g_pxv [BIGN + idx] = l;
        split2(vv2, h, l); g_pxv2[idx] = h; g_pxv2[BIGN + idx] = l;
        g_xw [idx] = vw;
        g_xv2[idx] = vv2;
    }
}

// ---------------- E3: decay ---------------------------------------------------
__global__ void k_decay(const float* __restrict__ tdec,
                        const float* __restrict__ w2) {
    __shared__ float tw[32][64];
    __shared__ float w2s[64][64];
    int rowBase = blockIdx.x * 32;
    int colBase = blockIdx.y * 64;
    int tid = threadIdx.x;

    for (int l = tid; l < 32 * 64; l += 256) {
        int rr = l / 64, d = l % 64;
        tw[rr][d] = g_tmpw[(rowBase + rr) * 64 + d];
    }
    for (int l = tid; l < 64 * 64; l += 256) {
        int d = l / 64, cc = l % 64;
        w2s[d][cc] = w2[d * Cc + colBase + cc];
    }
    __syncthreads();

    int cc = tid % 64;
    int r0 = tid / 64;
    float td = tdec[colBase + cc];
    for (int rr = r0; rr < 32; rr += 4) {
        float s = td;
#pragma unroll
        for (int d = 0; d < 64; d++) s += tw[rr][d] * w2s[d][cc];
        float dec = expf(-expf(s));
        int idx = (rowBase + rr) * Cc + colBase + cc;
        g_decay[idx] = dec;
        g_k[idx] *= (1.f - dec);
    }
}

// ---------------- E4: v2 += tmpv @ value2_w2 --------------------------------
__global__ void k_v2add(const float* __restrict__ w2) {
    __shared__ float tw[32][64];
    __shared__ float w2s[64][64];
    int rowBase = blockIdx.x * 32;
    int colBase = blockIdx.y * 64;
    int tid = threadIdx.x;

    for (int l = tid; l < 32 * 64; l += 256) {
        int rr = l / 64, d = l % 64;
        tw[rr][d] = g_tmpv[(rowBase + rr) * 64 + d];
    }
    for (int l = tid; l < 64 * 64; l += 256) {
        int d = l / 64, cc = l % 64;
        w2s[d][cc] = w2[d * Cc + colBase + cc];
    }
    __syncthreads();

    int cc = tid % 64;
    int r0 = tid / 64;
    for (int rr = r0; rr < 32; rr += 4) {
        float s = 0.f;
#pragma unroll
        for (int d = 0; d < 64; d++) s += tw[rr][d] * w2s[d][cc];
        int idx = (rowBase + rr) * Cc + colBase + cc;
        g_v2[idx] += s;
    }
}

// ---------------- S: WKV scan, chunked cp.async double-buffered -------------
#define CHUNK 8
__global__ __launch_bounds__(64)
void k_scan(const float* __restrict__ wkv_in,
            float* __restrict__ wkv_out) {
    const int h = blockIdx.x, b = blockIdx.y;
    const int j = threadIdx.x;

    __shared__ float sbuf[2][4][CHUNK][64];
    const unsigned int sb = (unsigned int)__cvta_generic_to_shared(&sbuf[0][0][0][0]);

    float state[64];
#pragma unroll
    for (int i = 0; i < 64; i++)
        state[i] = wkv_in[(size_t)((b * Hh + h) * Nn + i) * Nn + j];

    const float* srcs[4] = { g_r, g_k, g_decay, g_v };
    const size_t rowOff = (size_t)h * Nn;

    auto issue = [&](int buf, int t0) {
#pragma unroll
        for (int p = 0; p < 8; p++) {
            int l   = threadIdx.x + 64 * p;
            int arr = l >> 7;
            int rem = l & 127;
            int t   = rem >> 4;
            int seg = rem & 15;
            const float* gp = srcs[arr] +
                (size_t)(b * Tt + t0 + t) * Cc + rowOff + seg * 4;
            unsigned int da = sb +
                (unsigned int)((((buf * 4 + arr) * CHUNK + t) * 64) + seg * 4) * 4;
            cpasync16(da, gp);
        }
        asm volatile("cp.async.commit_group;");
    };

    issue(0, 0);
    asm volatile("cp.async.wait_group 0;" ::: "memory");
    __syncthreads();

    const int nch = Tt / CHUNK;
    for (int ch = 0; ch < nch; ch++) {
        const int cur = ch & 1;
        if (ch + 1 < nch) issue(cur ^ 1, (ch + 1) * CHUNK);

        const int t0 = ch * CHUNK;
#pragma unroll
        for (int tt = 0; tt < CHUNK; tt++) {
            const float4* rs4 = (const float4*)&sbuf[cur][0][tt][0];
            const float4* ks4 = (const float4*)&sbuf[cur][1][tt][0];
            const float4* ds4 = (const float4*)&sbuf[cur][2][tt][0];
            const float vj = sbuf[cur][3][tt][j];

            float y = 0.f;
#pragma unroll
            for (int i4 = 0; i4 < 16; i4++) {
                float4 r4 = rs4[i4], k4 = ks4[i4], d4 = ds4[i4];
                float s0 = state[4*i4+0], s1 = state[4*i4+1];
                float s2 = state[4*i4+2], s3 = state[4*i4+3];
                y += r4.x * s0; y += r4.y * s1;
                y += r4.z * s2; y += r4.w * s3;
                state[4*i4+0] = s0 * d4.x + k4.x * vj;
                state[4*i4+1] = s1 * d4.y + k4.y * vj;
                state[4*i4+2] = s2 * d4.z + k4.z * vj;
                state[4*i4+3] = s3 * d4.w + k4.w * vj;
            }
            g_ys[(size_t)(b * Tt + t0 + tt) * Cc + rowOff + j] = y;
        }

        asm volatile("cp.async.wait_group 0;" ::: "memory");
        __syncthreads();
    }

#pragma unroll
    for (int i = 0; i < 64; i++)
        wkv_out[(size_t)((b * Hh + h) * Nn + i) * Nn + j] = state[i];
}

// ---------------- E5: y = LN(ys + v2) -> bf16 planes -------------------------
__global__ void k_ln(const float* __restrict__ lnw,
                     const float* __restrict__ lnb) {
    int row = blockIdx.x;
    int tid = threadIdx.x;
    const float* a  = g_ys + (size_t)row * Cc;
    const float* bp = g_v2 + (size_t)row * Cc;
    float s = 0.f, ss = 0.f;
    for (int c = tid; c < Cc; c += 256) {
        float v = a[c] + bp[c];
        s += v; ss += v * v;
    }
    __shared__ float sh1[256], sh2[256];
    sh1[tid] = s; sh2[tid] = ss;
    __syncthreads();
    for (int st = 128; st > 0; st >>= 1) {
        if (tid < st) { sh1[tid] += sh1[tid + st]; sh2[tid] += sh2[tid + st]; }
        __syncthreads();
    }
    float mu  = sh1[0] / Cc;
    float var = sh2[0] / Cc - mu * mu;
    float rstd = rsqrtf(var + 1e-5f);
    for (int c = tid; c < Cc; c += 256) {
        float v = a[c] + bp[c];
        float res = (v - mu) * rstd * lnw[c] + lnb[c];
        __nv_bfloat16 h, l;
        split2(res, h, l);
        size_t idx = (size_t)row * Cc + c;
        g_pyn[idx] = h; g_pyn[BIGN + idx] = l;
    }
}

// ---------------- E6: shift_state_out ---------------------------------------
__global__ void k_copyshift(const float* __restrict__ x, float* __restrict__ out) {
    int i = blockIdx.x * 256 + threadIdx.x;
    if (i >= Bb * Cc) return;
    int b = i / Cc, c = i % Cc;
    out[i] = x[(size_t)(b * Tt + Tt - 1) * Cc + c];
}

// ---------------- launcher ---------------------------------------------------
extern "C" void kernel_launch(void* const* d_in, const int* in_sizes, int n_in,
                              void* d_out, int out_size) {
    const float* x        = (const float*)d_in[0];
    const float* shift_in = (const float*)d_in[1];
    const float* wkv_in   = (const float*)d_in[2];
    const float* maa_x    = (const float*)d_in[3];
    const float* maa_r    = (const float*)d_in[4];
    const float* maa_k    = (const float*)d_in[5];
    const float* maa_v    = (const float*)d_in[6];
    const float* maa_w    = (const float*)d_in[7];
    const float* maa_v2   = (const float*)d_in[8];
    const float* maa_w1   = (const float*)d_in[9];
    const float* maa_w2   = (const float*)d_in[10];
    const float* tdecay   = (const float*)d_in[11];
    const float* dec_w1   = (const float*)d_in[12];
    const float* dec_w2   = (const float*)d_in[13];
    const float* v2_w1    = (const float*)d_in[14];
    const float* v2_w2    = (const float*)d_in[15];
    const float* W_r      = (const float*)d_in[16];
    const float* W_k      = (const float*)d_in[17];
    const float* W_v      = (const float*)d_in[18];
    const float* W_o      = (const float*)d_in[19];
    const float* ln_w     = (const float*)d_in[20];
    const float* ln_b     = (const float*)d_in[21];

    float* out_y     = (float*)d_out;
    float* out_shift = out_y + (size_t)BT * Cc;
    float* out_wkv   = out_shift + (size_t)Bb * Cc;

    float *xxx = 0, *xw = 0, *xv2 = 0;
    float *rb = 0, *kb = 0, *vb = 0, *v2b = 0, *hpre = 0, *tmpw = 0, *tmpv = 0;
    __nv_bfloat16 *pxr = 0, *pxk = 0, *pxv = 0, *pxv2 = 0, *pyn = 0;
    __nv_bfloat16 *pwr = 0, *pwk = 0, *pwv = 0, *pwo = 0;
    cudaGetSymbolAddress((void**)&xxx,   g_xxx);
    cudaGetSymbolAddress((void**)&xw,    g_xw);
    cudaGetSymbolAddress((void**)&xv2,   g_xv2);
    cudaGetSymbolAddress((void**)&rb,    g_r);
    cudaGetSymbolAddress((void**)&kb,    g_k);
    cudaGetSymbolAddress((void**)&vb,    g_v);
    cudaGetSymbolAddress((void**)&v2b,   g_v2);
    cudaGetSymbolAddress((void**)&hpre,  g_hpre);
    cudaGetSymbolAddress((void**)&tmpw,  g_tmpw);
    cudaGetSymbolAddress((void**)&tmpv,  g_tmpv);
    cudaGetSymbolAddress((void**)&pxr,   g_pxr);
    cudaGetSymbolAddress((void**)&pxk,   g_pxk);
    cudaGetSymbolAddress((void**)&pxv,   g_pxv);
    cudaGetSymbolAddress((void**)&pxv2,  g_pxv2);
    cudaGetSymbolAddress((void**)&pyn,   g_pyn);
    cudaGetSymbolAddress((void**)&pwr,   g_pwr);
    cudaGetSymbolAddress((void**)&pwk,   g_pwk);
    cudaGetSymbolAddress((void**)&pwv,   g_pwv);
    cudaGetSymbolAddress((void**)&pwo,   g_pwo);

    cudaFuncSetAttribute(k_gemm_p,
                         cudaFuncAttributeMaxDynamicSharedMemorySize,
                         PSTAGES * PSTGB);

    const dim3 gemmGrid(Cc / 128, BT / 128);
    const int  gemmSmem = PSTAGES * PSTGB;

    // weight conversions (independent of data pipeline)
    k_conv<<<WN / 256, 256>>>(W_r, pwr, WN);
    k_conv<<<WN / 256, 256>>>(W_k, pwk, WN);
    k_conv<<<WN / 256, 256>>>(W_v, pwv, WN);
    k_conv<<<WN / 256, 256>>>(W_o, pwo, WN);

    // E1: token shift
    k_shift<<<BIGN / 256, 256>>>(x, shift_in, maa_x);

    // G1: hpre = tanh(xxx @ maa_w1)  [8192,160]
    k_gemm_small<<<dim3(3, BT / 32), 256>>>(xxx, Cc, maa_w1, 160, hpre, 160,
                                            BT, 160, Cc, 1);

    // E2: 5-way mix -> bf16 planes + fp32 xw/xv2
    k_mix<<<dim3(BT / 32, Cc / 32), 256>>>(x, maa_w2, maa_r, maa_k, maa_v,
                                           maa_w, maa_v2);

    // Big GEMMs on tensor cores (bf16x3, cp.async pipeline)
    k_gemm_p<<<gemmGrid, 256, gemmSmem>>>(pxr,  (size_t)BIGN, pwr, (size_t)WN, rb,  BT, Cc, Cc);
    k_gemm_p<<<gemmGrid, 256, gemmSmem>>>(pxk,  (size_t)BIGN, pwk, (size_t)WN, kb,  BT, Cc, Cc);
    k_gemm_p<<<gemmGrid, 256, gemmSmem>>>(pxv,  (size_t)BIGN, pwv, (size_t)WN, vb,  BT, Cc, Cc);
    k_gemm_p<<<gemmGrid, 256, gemmSmem>>>(pxv2, (size_t)BIGN, pwv, (size_t)WN, v2b, BT, Cc, Cc);

    // Small LoRA GEMMs (tanh)
    k_gemm_small<<<dim3(1, BT / 32), 256>>>(xw,  Cc, dec_w1, 64, tmpw, 64,
                                            BT, 64, Cc, 1);
    k_gemm_small<<<dim3(1, BT / 32), 256>>>(xv2, Cc, v2_w1,  64, tmpv, 64,
                                            BT, 64, Cc, 1);

    // E3/E4 epilogues
    k_decay<<<dim3(BT / 32, Cc / 64), 256>>>(tdecay, dec_w2);
    k_v2add<<<dim3(BT / 32, Cc / 64), 256>>>(v2_w2);

    // WKV scan
    k_scan<<<dim3(Hh, Bb), 64>>>(wkv_in, out_wkv);

    // LayerNorm(ys + v2) -> bf16 planes
    k_ln<<<BT, 256>>>(ln_w, ln_b);

    // Output GEMM: y = ynorm @ W_o
    k_gemm_p<<<gemmGrid, 256, gemmSmem>>>(pyn, (size_t)BIGN, pwo, (size_t)WN, out_y, BT, Cc, Cc);

    // shift state out
    k_copyshift<<<(Bb * Cc + 255) / 256, 256>>>(x, out_shift);
}

// round 6
// speedup vs baseline: 1.1778x; 1.1778x over previous
#include <cuda_runtime.h>
#include <cuda_bf16.h>
#include <cstdint>
#include <math.h>

// Problem constants
#define Bb   4
#define Tt   2048
#define Cc   2048
#define Hh   32
#define Nn   64
#define BT   (Bb*Tt)          // 8192
#define DMIX 32
#define DDEC 64
#define BIGN (BT*Cc)          // 16,777,216

// ---------------- scratch (device globals; no runtime allocation) ----------
__device__ float g_xxx  [BIGN];
__device__ float g_xr   [BIGN];
__device__ float g_xk   [BIGN];
__device__ float g_xv   [BIGN];
__device__ float g_xw   [BIGN];
__device__ float g_xv2  [BIGN];
__device__ float g_r    [BIGN];
__device__ float g_k    [BIGN];
__device__ float g_v    [BIGN];
__device__ float g_v2   [BIGN];
__device__ float g_decay[BIGN];
__device__ float g_ys   [BIGN];
__device__ float g_ynorm[BIGN];
__device__ float g_hpre [BT*160];     // tanh applied in k_red
__device__ float g_tmpw [BT*DDEC];
__device__ float g_tmpv [BT*DDEC];
__device__ float g_part [4*BT*160];   // split-K partials

// ---------------- E1: token shift ------------------------------------------
__global__ void k_shift(const float* __restrict__ x,
                        const float* __restrict__ shift,
                        const float* __restrict__ maa_x) {
    int idx = blockIdx.x * 256 + threadIdx.x;
    if (idx >= BIGN) return;
    int c  = idx % Cc;
    int bt = idx / Cc;
    int t  = bt % Tt;
    int b  = bt / Tt;
    float xv   = x[idx];
    float prev = (t == 0) ? shift[b * Cc + c] : x[idx - Cc];
    g_xxx[idx] = xv + (prev - xv) * maa_x[c];
}

// =============================================================================
// Tensor-core GEMM (bf16x3 split, fp32 accumulate) -- R4 proven version
// =============================================================================
#define ASTR 40
#define BSTR 136
#define SA_H 0
#define SA_L 5120
#define SB_H 10240
#define SB_L 14592
#define STG  18944
#define STG_BYTES (STG*2)

__device__ __forceinline__ void ldsm4(unsigned int* r, unsigned int addr) {
    asm volatile("ldmatrix.sync.aligned.m8n8.x4.shared.b16 {%0,%1,%2,%3},[%4];"
                 : "=r"(r[0]), "=r"(r[1]), "=r"(r[2]), "=r"(r[3]) : "r"(addr));
}
__device__ __forceinline__ void ldsm4t(unsigned int* r, unsigned int addr) {
    asm volatile("ldmatrix.sync.aligned.m8n8.x4.trans.shared.b16 {%0,%1,%2,%3},[%4];"
                 : "=r"(r[0]), "=r"(r[1]), "=r"(r[2]), "=r"(r[3]) : "r"(addr));
}
__device__ __forceinline__ void mma16816(float* c, const unsigned int* a,
                                         unsigned int b0, unsigned int b1) {
    asm volatile("mma.sync.aligned.m16n8k16.row.col.f32.bf16.bf16.f32 "
                 "{%0,%1,%2,%3},{%4,%5,%6,%7},{%8,%9},{%0,%1,%2,%3};"
                 : "+f"(c[0]), "+f"(c[1]), "+f"(c[2]), "+f"(c[3])
                 : "r"(a[0]), "r"(a[1]), "r"(a[2]), "r"(a[3]), "r"(b0), "r"(b1));
}
__device__ __forceinline__ void split2(float f, __nv_bfloat16& h, __nv_bfloat16& l) {
    h = __float2bfloat16_rn(f);
    l = __float2bfloat16_rn(f - __bfloat162float(h));
}
__device__ __forceinline__ void cpasync16(unsigned int daddr, const void* gp) {
    asm volatile("cp.async.ca.shared.global [%0], [%1], 16;"
                 :: "r"(daddr), "l"(gp));
}

__global__ __launch_bounds__(256, 1)
void k_mma_gemm(const float* __restrict__ A,
                const float* __restrict__ B,
                float* __restrict__ C,
                int M, int N, int K) {
    extern __shared__ __nv_bfloat16 smbuf[];
    const int tid  = threadIdx.x;
    const int lane = tid & 31;
    const int wid  = tid >> 5;
    const int wm   = wid >> 2;
    const int wn   = wid & 3;
    const int mBase = blockIdx.y * 128;
    const int nBase = blockIdx.x * 128;

    const unsigned int smB = (unsigned int)__cvta_generic_to_shared(smbuf);

    const int arow = tid >> 3;
    const int acol = (tid & 7) * 4;
    const int brow = tid >> 5;
    const int bcol = (tid & 31) * 4;

    const float* Ap = A + (size_t)(mBase + arow) * K + acol;
    const float* Bp = B + (size_t)brow * N + nBase + bcol;

    float acc[4][4][4];
#pragma unroll
    for (int i = 0; i < 4; i++)
#pragma unroll
        for (int j = 0; j < 4; j++)
#pragma unroll
            for (int q = 0; q < 4; q++) acc[i][j][q] = 0.f;

    float4 aR[4], bR[4];
    const int kChunks = K >> 5;

#pragma unroll
    for (int p = 0; p < 4; p++) aR[p] = *(const float4*)(Ap + (size_t)(p * 32) * K);
#pragma unroll
    for (int p = 0; p < 4; p++) bR[p] = *(const float4*)(Bp + (size_t)(p * 8) * N);

    {
        __nv_bfloat16* st = smbuf;
#pragma unroll
        for (int p = 0; p < 4; p++) {
            int row = arow + p * 32;
            __nv_bfloat16 h0,h1,h2,h3,l0,l1,l2,l3;
            split2(aR[p].x,h0,l0); split2(aR[p].y,h1,l1);
            split2(aR[p].z,h2,l2); split2(aR[p].w,h3,l3);
            __nv_bfloat162 *ph = (__nv_bfloat162*)(st + SA_H + row*ASTR + acol);
            __nv_bfloat162 *pl = (__nv_bfloat162*)(st + SA_L + row*ASTR + acol);
            ph[0] = __halves2bfloat162(h0,h1); ph[1] = __halves2bfloat162(h2,h3);
            pl[0] = __halves2bfloat162(l0,l1); pl[1] = __halves2bfloat162(l2,l3);
        }
#pragma unroll
        for (int p = 0; p < 4; p++) {
            int row = brow + p * 8;
            __nv_bfloat16 h0,h1,h2,h3,l0,l1,l2,l3;
            split2(bR[p].x,h0,l0); split2(bR[p].y,h1,l1);
            split2(bR[p].z,h2,l2); split2(bR[p].w,h3,l3);
            __nv_bfloat162 *ph = (__nv_bfloat162*)(st + SB_H + row*BSTR + bcol);
            __nv_bfloat162 *pl = (__nv_bfloat162*)(st + SB_L + row*BSTR + bcol);
            ph[0] = __halves2bfloat162(h0,h1); ph[1] = __halves2bfloat162(h2,h3);
            pl[0] = __halves2bfloat162(l0,l1); pl[1] = __halves2bfloat162(l2,l3);
        }
    }
    __syncthreads();

#pragma unroll 1
    for (int ch = 0; ch < kChunks; ch++) {
        const int cur = ch & 1;
        const bool more = (ch + 1) < kChunks;

        if (more) {
            const float* Apn = Ap + (ch + 1) * 32;
            const float* Bpn = Bp + (size_t)(ch + 1) * 32 * N;
#pragma unroll
            for (int p = 0; p < 4; p++) aR[p] = *(const float4*)(Apn + (size_t)(p * 32) * K);
#pragma unroll
            for (int p = 0; p < 4; p++) bR[p] = *(const float4*)(Bpn + (size_t)(p * 8) * N);
        }

        const unsigned int sb = smB + cur * STG_BYTES;
#pragma unroll
        for (int ks = 0; ks < 2; ks++) {
            const int k0 = ks * 16;
            unsigned int ah[4][4], al[4][4], bh[2][4], bl[2][4];
#pragma unroll
            for (int mf = 0; mf < 4; mf++) {
                int row = wm * 64 + mf * 16 + (lane & 15);
                int col = k0 + (lane >> 4) * 8;
                unsigned int ad = sb + (unsigned int)(row * ASTR + col) * 2;
                ldsm4(ah[mf], ad + SA_H * 2);
                ldsm4(al[mf], ad + SA_L * 2);
            }
#pragma unroll
            for (int nf2 = 0; nf2 < 2; nf2++) {
                int rowk = k0 + (lane & 15);
                int coln = wn * 32 + nf2 * 16 + (lane >> 4) * 8;
                unsigned int bd = sb + (unsigned int)(rowk * BSTR + coln) * 2;
                ldsm4t(bh[nf2], bd + SB_H * 2);
                ldsm4t(bl[nf2], bd + SB_L * 2);
            }
#pragma unroll
            for (int mf = 0; mf < 4; mf++) {
#pragma unroll
                for (int nf = 0; nf < 4; nf++) {
                    unsigned int b0h = bh[nf >> 1][(nf & 1) * 2];
                    unsigned int b1h = bh[nf >> 1][(nf & 1) * 2 + 1];
                    unsigned int b0l = bl[nf >> 1][(nf & 1) * 2];
                    unsigned int b1l = bl[nf >> 1][(nf & 1) * 2 + 1];
                    mma16816(acc[mf][nf], ah[mf], b0h, b1h);
                    mma16816(acc[mf][nf], ah[mf], b0l, b1l);
                    mma16816(acc[mf][nf], al[mf], b0h, b1h);
                }
            }
        }

        if (more) {
            __nv_bfloat16* st = smbuf + (cur ^ 1) * STG;
#pragma unroll
            for (int p = 0; p < 4; p++) {
                int row = arow + p * 32;
                __nv_bfloat16 h0,h1,h2,h3,l0,l1,l2,l3;
                split2(aR[p].x,h0,l0); split2(aR[p].y,h1,l1);
                split2(aR[p].z,h2,l2); split2(aR[p].w,h3,l3);
                __nv_bfloat162 *ph = (__nv_bfloat162*)(st + SA_H + row*ASTR + acol);
                __nv_bfloat162 *pl = (__nv_bfloat162*)(st + SA_L + row*ASTR + acol);
                ph[0] = __halves2bfloat162(h0,h1); ph[1] = __halves2bfloat162(h2,h3);
                pl[0] = __halves2bfloat162(l0,l1); pl[1] = __halves2bfloat162(l2,l3);
            }
#pragma unroll
            for (int p = 0; p < 4; p++) {
                int row = brow + p * 8;
                __nv_bfloat16 h0,h1,h2,h3,l0,l1,l2,l3;
                split2(bR[p].x,h0,l0); split2(bR[p].y,h1,l1);
                split2(bR[p].z,h2,l2); split2(bR[p].w,h3,l3);
                __nv_bfloat162 *ph = (__nv_bfloat162*)(st + SB_H + row*BSTR + bcol);
                __nv_bfloat162 *pl = (__nv_bfloat162*)(st + SB_L + row*BSTR + bcol);
                ph[0] = __halves2bfloat162(h0,h1); ph[1] = __halves2bfloat162(h2,h3);
                pl[0] = __halves2bfloat162(l0,l1); pl[1] = __halves2bfloat162(l2,l3);
            }
        }
        __syncthreads();
    }

#pragma unroll
    for (int mf = 0; mf < 4; mf++) {
#pragma unroll
        for (int nf = 0; nf < 4; nf++) {
            int r = mBase + wm * 64 + mf * 16 + (lane >> 2);
            int c = nBase + wn * 32 + nf * 8 + (lane & 3) * 2;
            float2 v0 = make_float2(acc[mf][nf][0], acc[mf][nf][1]);
            float2 v1 = make_float2(acc[mf][nf][2], acc[mf][nf][3]);
            *(float2*)&C[(size_t)r * N + c] = v0;
            *(float2*)&C[(size_t)(r + 8) * N + c] = v1;
        }
    }
}

// ---------------- split-K small GEMM: BM=128, BN=64, BK=16, KS partials -----
// Writes partial (no activation) to part[z*M*N + ...]. Deterministic.
__global__ __launch_bounds__(256)
void k_gemm_sk(const float* __restrict__ A, int lda,
               const float* __restrict__ B, int ldb,
               float* __restrict__ part,
               int M, int N, int K, int KS) {
    __shared__ float As[16][136];
    __shared__ float Bs[16][68];
    const int tid = threadIdx.x;
    const int mBase = blockIdx.y * 128;
    const int nBase = blockIdx.x * 64;
    const int kz = blockIdx.z;
    const int kLen = K / KS;
    const int kStart = kz * kLen;

    const int aRow = tid >> 1;         // 0..127
    const int aCol = (tid & 1) * 8;    // 0 or 8
    const int bRow = tid >> 4;         // 0..15
    const int bCol = (tid & 15) * 4;   // 0..60

    const int ty = tid >> 3;           // 0..31
    const int tx = tid & 7;            // 0..7

    float acc[4][8];
#pragma unroll
    for (int m = 0; m < 4; m++)
#pragma unroll
        for (int j = 0; j < 8; j++) acc[m][j] = 0.f;

    const float* Ab = A + (size_t)(mBase + aRow) * lda + aCol;

    for (int k0 = kStart; k0 < kStart + kLen; k0 += 16) {
        float4 a0 = *(const float4*)(Ab + k0);
        float4 a1 = *(const float4*)(Ab + k0 + 4);
        As[aCol + 0][aRow] = a0.x; As[aCol + 1][aRow] = a0.y;
        As[aCol + 2][aRow] = a0.z; As[aCol + 3][aRow] = a0.w;
        As[aCol + 4][aRow] = a1.x; As[aCol + 5][aRow] = a1.y;
        As[aCol + 6][aRow] = a1.z; As[aCol + 7][aRow] = a1.w;

        float4 b4 = make_float4(0.f, 0.f, 0.f, 0.f);
        int col = nBase + bCol;
        if (col < N)
            b4 = *(const float4*)(B + (size_t)(k0 + bRow) * ldb + col);
        *(float4*)&Bs[bRow][bCol] = b4;
        __syncthreads();

#pragma unroll
        for (int kk = 0; kk < 16; kk++) {
            float a0v = As[kk][ty];
            float a1v = As[kk][ty + 32];
            float a2v = As[kk][ty + 64];
            float a3v = As[kk][ty + 96];
            float4 b0 = *(const float4*)&Bs[kk][tx * 8];
            float4 b1 = *(const float4*)&Bs[kk][tx * 8 + 4];
            float bv[8] = {b0.x,b0.y,b0.z,b0.w,b1.x,b1.y,b1.z,b1.w};
            float av[4] = {a0v,a1v,a2v,a3v};
#pragma unroll
            for (int m = 0; m < 4; m++)
#pragma unroll
                for (int j = 0; j < 8; j++)
                    acc[m][j] += av[m] * bv[j];
        }
        __syncthreads();
    }

    float* Cd = part + (size_t)kz * M * N;
#pragma unroll
    for (int m = 0; m < 4; m++) {
        int row = mBase + ty + 32 * m;
#pragma unroll
        for (int j = 0; j < 8; j++) {
            int col = nBase + tx * 8 + j;
            if (col < N) Cd[(size_t)row * N + col] = acc[m][j];
        }
    }
}

// ---------------- reduce split-K partials + tanh ----------------------------
__global__ void k_red(const float* __restrict__ p, float* __restrict__ out, int n) {
    int i = blockIdx.x * 256 + threadIdx.x;
    if (i >= n) return;
    float s = p[i] + p[n + i] + p[2 * n + i] + p[3 * n + i];
    out[i] = tanhf(s);
}

// ---------------- E2: 5-way LoRA mix (dxprev recomputed) --------------------
__global__ void k_mix(const float* __restrict__ x,
                      const float* __restrict__ shift,
                      const float* __restrict__ w2,
                      const float* __restrict__ mr, const float* __restrict__ mk,
                      const float* __restrict__ mv, const float* __restrict__ mw,
                      const float* __restrict__ mv2) {
    __shared__ float hs[32][160];
    __shared__ float ws[160][32];
    int rowBase = blockIdx.x * 32;
    int colBase = blockIdx.y * 32;
    int tid = threadIdx.x;

    for (int l = tid; l < 32 * 160; l += 256) {
        int rr = l / 160, d = l % 160;
        hs[rr][d] = g_hpre[(rowBase + rr) * 160 + d];
    }
    for (int l = tid; l < 160 * 32; l += 256) {
        int fd = l / 32, cc = l % 32;
        ws[fd][cc] = w2[fd * Cc + colBase + cc];
    }
    __syncthreads();

    int cc = tid % 32;
    int r0 = tid / 32;
    int c  = colBase + cc;
    float tr = mr[c], tk = mk[c], tv = mv[c], tw = mw[c], tv2 = mv2[c];

    for (int rr = r0; rr < 32; rr += 8) {
        float m0 = 0, m1 = 0, m2 = 0, m3 = 0, m4 = 0;
#pragma unroll
        for (int d = 0; d < 32; d++) {
            float h0 = hs[rr][d];
            float h1 = hs[rr][32 + d];
            float h2 = hs[rr][64 + d];
            float h3 = hs[rr][96 + d];
            float h4 = hs[rr][128 + d];
            m0 += h0 * ws[d][cc];
            m1 += h1 * ws[32 + d][cc];
            m2 += h2 * ws[64 + d][cc];
            m3 += h3 * ws[96 + d][cc];
            m4 += h4 * ws[128 + d][cc];
        }
        int bt  = rowBase + rr;
        int t   = bt % Tt;
        int b   = bt / Tt;
        int idx = bt * Cc + c;
        float xval = x[idx];
        float prev = (t == 0) ? shift[b * Cc + c] : x[idx - Cc];
        float dx   = prev - xval;
        g_xr [idx] = xval + dx * (tr  + m0);
        g_xk [idx] = xval + dx * (tk  + m1);
        g_xv [idx] = xval + dx * (tv  + m2);
        g_xw [idx] = xval + dx * (tw  + m3);
        g_xv2[idx] = xval + dx * (tv2 + m4);
    }
}

// ---------------- E3: decay only (k-scaling fused into scan) ----------------
__global__ void k_decay(const float* __restrict__ tdec,
                        const float* __restrict__ w2) {
    __shared__ float tw[32][64];
    __shared__ float w2s[64][64];
    int rowBase = blockIdx.x * 32;
    int colBase = blockIdx.y * 64;
    int tid = threadIdx.x;

    for (int l = tid; l < 32 * 64; l += 256) {
        int rr = l / 64, d = l % 64;
        tw[rr][d] = g_tmpw[(rowBase + rr) * 64 + d];
    }
    for (int l = tid; l < 64 * 64; l += 256) {
        int d = l / 64, cc = l % 64;
        w2s[d][cc] = w2[d * Cc + colBase + cc];
    }
    __syncthreads();

    int cc = tid % 64;
    int r0 = tid / 64;
    float td = tdec[colBase + cc];
    for (int rr = r0; rr < 32; rr += 4) {
        float s = td;
#pragma unroll
        for (int d = 0; d < 64; d++) s += tw[rr][d] * w2s[d][cc];
        g_decay[(rowBase + rr) * Cc + colBase + cc] = expf(-expf(s));
    }
}

// ---------------- E4: v2 += tmpv @ value2_w2 --------------------------------
__global__ void k_v2add(const float* __restrict__ w2) {
    __shared__ float tw[32][64];
    __shared__ float w2s[64][64];
    int rowBase = blockIdx.x * 32;
    int colBase = blockIdx.y * 64;
    int tid = threadIdx.x;

    for (int l = tid; l < 32 * 64; l += 256) {
        int rr = l / 64, d = l % 64;
        tw[rr][d] = g_tmpv[(rowBase + rr) * 64 + d];
    }
    for (int l = tid; l < 64 * 64; l += 256) {
        int d = l / 64, cc = l % 64;
        w2s[d][cc] = w2[d * Cc + colBase + cc];
    }
    __syncthreads();

    int cc = tid % 64;
    int r0 = tid / 64;
    for (int rr = r0; rr < 32; rr += 4) {
        float s = 0.f;
#pragma unroll
        for (int d = 0; d < 64; d++) s += tw[rr][d] * w2s[d][cc];
        g_v2[(rowBase + rr) * Cc + colBase + cc] += s;
    }
}

// ---------------- S: WKV scan, 256 threads, 4 lanes/column ------------------
// k*(1-decay) fused here. Double-buffered cp.async prefetch of CHUNK steps.
#define CHUNK 8
__global__ __launch_bounds__(256)
void k_scan(const float* __restrict__ wkv_in,
            float* __restrict__ wkv_out) {
    const int h = blockIdx.x, b = blockIdx.y;
    const int tid  = threadIdx.x;
    const int lane = tid & 31;
    const int wid  = tid >> 5;
    const int jj   = wid * 8 + (lane >> 2);   // column 0..63
    const int q    = lane & 3;                // row quarter

    __shared__ float sbuf[2][4][CHUNK][64];   // [buf][r,k,d,v][t][i]
    const unsigned int sb = (unsigned int)__cvta_generic_to_shared(&sbuf[0][0][0][0]);

    float state[16];
#pragma unroll
    for (int i = 0; i < 16; i++)
        state[i] = wkv_in[(size_t)((b * Hh + h) * Nn + q * 16 + i) * Nn + jj];

    const float* srcs[4] = { g_r, g_k, g_decay, g_v };
    const size_t rowOff = (size_t)h * Nn;

    auto issue = [&](int buf, int t0) {
#pragma unroll
        for (int p = 0; p < 2; p++) {
            int l   = tid + 256 * p;          // 0..511
            int arr = l >> 7;
            int rem = l & 127;
            int t   = rem >> 4;
            int seg = rem & 15;
            const float* gp = srcs[arr] +
                (size_t)(b * Tt + t0 + t) * Cc + rowOff + seg * 4;
            unsigned int da = sb +
                (unsigned int)((((buf * 4 + arr) * CHUNK + t) * 64) + seg * 4) * 4;
            cpasync16(da, gp);
        }
        asm volatile("cp.async.commit_group;");
    };

    issue(0, 0);
    asm volatile("cp.async.wait_group 0;" ::: "memory");
    __syncthreads();

    const int nch = Tt / CHUNK;
    for (int ch = 0; ch < nch; ch++) {
        const int cur = ch & 1;
        if (ch + 1 < nch) issue(cur ^ 1, (ch + 1) * CHUNK);

        const int t0 = ch * CHUNK;
#pragma unroll
        for (int tt = 0; tt < CHUNK; tt++) {
            const float4* rs4 = (const float4*)&sbuf[cur][0][tt][q * 16];
            const float4* ks4 = (const float4*)&sbuf[cur][1][tt][q * 16];
            const float4* ds4 = (const float4*)&sbuf[cur][2][tt][q * 16];
            const float vj = sbuf[cur][3][tt][jj];

            float y = 0.f;
#pragma unroll
            for (int i4 = 0; i4 < 4; i4++) {
                float4 r4 = rs4[i4], k4 = ks4[i4], d4 = ds4[i4];
                float kx, kv;
                float s0 = state[4*i4+0], s1 = state[4*i4+1];
                float s2 = state[4*i4+2], s3 = state[4*i4+3];
                y = fmaf(r4.x, s0, y);
                kx = fmaf(-k4.x, d4.x, k4.x); kv = kx * vj;
                state[4*i4+0] = fmaf(s0, d4.x, kv);
                y = fmaf(r4.y, s1, y);
                kx = fmaf(-k4.y, d4.y, k4.y); kv = kx * vj;
                state[4*i4+1] = fmaf(s1, d4.y, kv);
                y = fmaf(r4.z, s2, y);
                kx = fmaf(-k4.z, d4.z, k4.z); kv = kx * vj;
                state[4*i4+2] = fmaf(s2, d4.z, kv);
                y = fmaf(r4.w, s3, y);
                kx = fmaf(-k4.w, d4.w, k4.w); kv = kx * vj;
                state[4*i4+3] = fmaf(s3, d4.w, kv);
            }
            y += __shfl_xor_sync(0xffffffffu, y, 1);
            y += __shfl_xor_sync(0xffffffffu, y, 2);
            if (q == 0)
                g_ys[(size_t)(b * Tt + t0 + tt) * Cc + rowOff + jj] = y;
        }

        asm volatile("cp.async.wait_group 0;" ::: "memory");
        __syncthreads();
    }

#pragma unroll
    for (int i = 0; i < 16; i++)
        wkv_out[(size_t)((b * Hh + h) * Nn + q * 16 + i) * Nn + jj] = state[i];
}

// ---------------- E5: y = LN(ys + v2) ---------------------------------------
__global__ void k_ln(const float* __restrict__ lnw,
                     const float* __restrict__ lnb) {
    int row = blockIdx.x;
    int tid = threadIdx.x;
    const float* a  = g_ys + (size_t)row * Cc;
    const float* bp = g_v2 + (size_t)row * Cc;
    float s = 0.f, ss = 0.f;
    for (int c = tid; c < Cc; c += 256) {
        float v = a[c] + bp[c];
        s += v; ss += v * v;
    }
    __shared__ float sh1[256], sh2[256];
    sh1[tid] = s; sh2[tid] = ss;
    __syncthreads();
    for (int st = 128; st > 0; st >>= 1) {
        if (tid < st) { sh1[tid] += sh1[tid + st]; sh2[tid] += sh2[tid + st]; }
        __syncthreads();
    }
    float mu  = sh1[0] / Cc;
    float var = sh2[0] / Cc - mu * mu;
    float rstd = rsqrtf(var + 1e-5f);
    for (int c = tid; c < Cc; c += 256) {
        float v = a[c] + bp[c];
        g_ynorm[(size_t)row * Cc + c] = (v - mu) * rstd * lnw[c] + lnb[c];
    }
}

// ---------------- E6: shift_state_out ---------------------------------------
__global__ void k_copyshift(const float* __restrict__ x, float* __restrict__ out) {
    int i = blockIdx.x * 256 + threadIdx.x;
    if (i >= Bb * Cc) return;
    int b = i / Cc, c = i % Cc;
    out[i] = x[(size_t)(b * Tt + Tt - 1) * Cc + c];
}

// ---------------- launcher ---------------------------------------------------
extern "C" void kernel_launch(void* const* d_in, const int* in_sizes, int n_in,
                              void* d_out, int out_size) {
    const float* x        = (const float*)d_in[0];
    const float* shift_in = (const float*)d_in[1];
    const float* wkv_in   = (const float*)d_in[2];
    const float* maa_x    = (const float*)d_in[3];
    const float* maa_r    = (const float*)d_in[4];
    const float* maa_k    = (const float*)d_in[5];
    const float* maa_v    = (const float*)d_in[6];
    const float* maa_w    = (const float*)d_in[7];
    const float* maa_v2   = (const float*)d_in[8];
    const float* maa_w1   = (const float*)d_in[9];
    const float* maa_w2   = (const float*)d_in[10];
    const float* tdecay   = (const float*)d_in[11];
    const float* dec_w1   = (const float*)d_in[12];
    const float* dec_w2   = (const float*)d_in[13];
    const float* v2_w1    = (const float*)d_in[14];
    const float* v2_w2    = (const float*)d_in[15];
    const float* W_r      = (const float*)d_in[16];
    const float* W_k      = (const float*)d_in[17];
    const float* W_v      = (const float*)d_in[18];
    const float* W_o      = (const float*)d_in[19];
    const float* ln_w     = (const float*)d_in[20];
    const float* ln_b     = (const float*)d_in[21];

    float* out_y     = (float*)d_out;
    float* out_shift = out_y + (size_t)BT * Cc;
    float* out_wkv   = out_shift + (size_t)Bb * Cc;

    float *xxx = 0, *xr = 0, *xk = 0, *xv = 0, *xw = 0, *xv2 = 0;
    float *rb = 0, *kb = 0, *vb = 0, *v2b = 0;
    float *hpre = 0, *tmpw = 0, *tmpv = 0, *ynorm = 0, *part = 0;
    cudaGetSymbolAddress((void**)&xxx,   g_xxx);
    cudaGetSymbolAddress((void**)&xr,    g_xr);
    cudaGetSymbolAddress((void**)&xk,    g_xk);
    cudaGetSymbolAddress((void**)&xv,    g_xv);
    cudaGetSymbolAddress((void**)&xw,    g_xw);
    cudaGetSymbolAddress((void**)&xv2,   g_xv2);
    cudaGetSymbolAddress((void**)&rb,    g_r);
    cudaGetSymbolAddress((void**)&kb,    g_k);
    cudaGetSymbolAddress((void**)&vb,    g_v);
    cudaGetSymbolAddress((void**)&v2b,   g_v2);
    cudaGetSymbolAddress((void**)&hpre,  g_hpre);
    cudaGetSymbolAddress((void**)&tmpw,  g_tmpw);
    cudaGetSymbolAddress((void**)&tmpv,  g_tmpv);
    cudaGetSymbolAddress((void**)&ynorm, g_ynorm);
    cudaGetSymbolAddress((void**)&part,  g_part);

    cudaFuncSetAttribute(k_mma_gemm,
                         cudaFuncAttributeMaxDynamicSharedMemorySize,
                         2 * STG_BYTES);

    const dim3 gemmGrid(Cc / 128, BT / 128);
    const int  gemmSmem = 2 * STG_BYTES;

    // E1: token shift -> xxx
    k_shift<<<BIGN / 256, 256>>>(x, shift_in, maa_x);

    // G1: hpre = tanh(xxx @ maa_w1)  via split-K + reduce
    k_gemm_sk<<<dim3(3, BT / 128, 4), 256>>>(xxx, Cc, maa_w1, 160, part,
                                             BT, 160, Cc, 4);
    k_red<<<(BT * 160 + 255) / 256, 256>>>(part, hpre, BT * 160);

    // E2: 5-way mix
    k_mix<<<dim3(BT / 32, Cc / 32), 256>>>(x, shift_in, maa_w2,
                                           maa_r, maa_k, maa_v, maa_w, maa_v2);

    // Big GEMMs on tensor cores (bf16x3)
    k_mma_gemm<<<gemmGrid, 256, gemmSmem>>>(xr,  W_r, rb,  BT, Cc, Cc);
    k_mma_gemm<<<gemmGrid, 256, gemmSmem>>>(xk,  W_k, kb,  BT, Cc, Cc);
    k_mma_gemm<<<gemmGrid, 256, gemmSmem>>>(xv,  W_v, vb,  BT, Cc, Cc);
    k_mma_gemm<<<gemmGrid, 256, gemmSmem>>>(xv2, W_v, v2b, BT, Cc, Cc);

    // Small LoRA GEMMs via split-K + tanh reduce
    k_gemm_sk<<<dim3(1, BT / 128, 4), 256>>>(xw, Cc, dec_w1, 64, part,
                                             BT, 64, Cc, 4);
    k_red<<<(BT * 64 + 255) / 256, 256>>>(part, tmpw, BT * 64);
    k_gemm_sk<<<dim3(1, BT / 128, 4), 256>>>(xv2, Cc, v2_w1, 64, part,
                                             BT, 64, Cc, 4);
    k_red<<<(BT * 64 + 255) / 256, 256>>>(part, tmpv, BT * 64);

    // E3/E4 epilogues
    k_decay<<<dim3(BT / 32, Cc / 64), 256>>>(tdecay, dec_w2);
    k_v2add<<<dim3(BT / 32, Cc / 64), 256>>>(v2_w2);

    // WKV scan (k * (1-decay) fused)
    k_scan<<<dim3(Hh, Bb), 256>>>(wkv_in, out_wkv);

    // LayerNorm(ys + v2)
    k_ln<<<BT, 256>>>(ln_w, ln_b);

    // Output GEMM: y = ynorm @ W_o
    k_mma_gemm<<<gemmGrid, 256, gemmSmem>>>(ynorm, W_o, out_y, BT, Cc, Cc);

    // shift state out
    k_copyshift<<<(Bb * Cc + 255) / 256, 256>>>(x, out_shift);
}

// round 7
// speedup vs baseline: 1.3470x; 1.1437x over previous
#include <cuda_runtime.h>
#include <cuda_bf16.h>
#include <cstdint>
#include <math.h>

// Problem constants
#define Bb   4
#define Tt   2048
#define Cc   2048
#define Hh   32
#define Nn   64
#define BT   (Bb*Tt)          // 8192
#define DMIX 32
#define DDEC 64
#define BIGN (BT*Cc)          // 16,777,216

// ---------------- scratch (device globals; no runtime allocation) ----------
__device__ float g_xxx  [BIGN];
__device__ float g_xr   [BIGN];
__device__ float g_xk   [BIGN];
__device__ float g_xv   [BIGN];
__device__ float g_xw   [BIGN];
__device__ float g_xv2  [BIGN];
__device__ float g_r    [BIGN];
__device__ float g_k    [BIGN];
__device__ float g_v    [BIGN];
__device__ float g_v2   [BIGN];
__device__ float g_decay[BIGN];
__device__ float g_ys   [BIGN];
__device__ float g_ynorm[BIGN];
__device__ float g_hpre [BT*160];     // tanh(xxx @ maa_w1)
__device__ float g_tmpw [BT*DDEC];    // tanh(xw @ decay_w1)
__device__ float g_tmpv [BT*DDEC];    // tanh(xv2 @ value2_w1)

// ---------------- E1: token shift ------------------------------------------
__global__ void k_shift(const float* __restrict__ x,
                        const float* __restrict__ shift,
                        const float* __restrict__ maa_x) {
    int idx = blockIdx.x * 256 + threadIdx.x;
    if (idx >= BIGN) return;
    int c  = idx % Cc;
    int bt = idx / Cc;
    int t  = bt % Tt;
    int b  = bt / Tt;
    float xv   = x[idx];
    float prev = (t == 0) ? shift[b * Cc + c] : x[idx - Cc];
    g_xxx[idx] = xv + (prev - xv) * maa_x[c];
}

// =============================================================================
// Tensor-core GEMM (bf16x3 split, fp32 accumulate), generalized:
// C[M,N] = act(A[M,K] * B[K,N]); M%128==0, K%32==0, N%4==0 (bounds-checked).
// grid = (ceil(N/128), M/128). ldc = row stride of C. act: 0=none, 1=tanh.
// =============================================================================
#define ASTR 40
#define BSTR 136
#define SA_H 0
#define SA_L 5120
#define SB_H 10240
#define SB_L 14592
#define STG  18944
#define STG_BYTES (STG*2)

__device__ __forceinline__ void ldsm4(unsigned int* r, unsigned int addr) {
    asm volatile("ldmatrix.sync.aligned.m8n8.x4.shared.b16 {%0,%1,%2,%3},[%4];"
                 : "=r"(r[0]), "=r"(r[1]), "=r"(r[2]), "=r"(r[3]) : "r"(addr));
}
__device__ __forceinline__ void ldsm4t(unsigned int* r, unsigned int addr) {
    asm volatile("ldmatrix.sync.aligned.m8n8.x4.trans.shared.b16 {%0,%1,%2,%3},[%4];"
                 : "=r"(r[0]), "=r"(r[1]), "=r"(r[2]), "=r"(r[3]) : "r"(addr));
}
__device__ __forceinline__ void mma16816(float* c, const unsigned int* a,
                                         unsigned int b0, unsigned int b1) {
    asm volatile("mma.sync.aligned.m16n8k16.row.col.f32.bf16.bf16.f32 "
                 "{%0,%1,%2,%3},{%4,%5,%6,%7},{%8,%9},{%0,%1,%2,%3};"
                 : "+f"(c[0]), "+f"(c[1]), "+f"(c[2]), "+f"(c[3])
                 : "r"(a[0]), "r"(a[1]), "r"(a[2]), "r"(a[3]), "r"(b0), "r"(b1));
}
__device__ __forceinline__ void split2(float f, __nv_bfloat16& h, __nv_bfloat16& l) {
    h = __float2bfloat16_rn(f);
    l = __float2bfloat16_rn(f - __bfloat162float(h));
}
__device__ __forceinline__ void cpasync16(unsigned int daddr, const void* gp) {
    asm volatile("cp.async.ca.shared.global [%0], [%1], 16;"
                 :: "r"(daddr), "l"(gp));
}

__global__ __launch_bounds__(256, 1)
void k_mma_gemm(const float* __restrict__ A,
                const float* __restrict__ B,
                float* __restrict__ C,
                int M, int N, int K, int ldc, int act) {
    extern __shared__ __nv_bfloat16 smbuf[];
    const int tid  = threadIdx.x;
    const int lane = tid & 31;
    const int wid  = tid >> 5;
    const int wm   = wid >> 2;
    const int wn   = wid & 3;
    const int mBase = blockIdx.y * 128;
    const int nBase = blockIdx.x * 128;

    const unsigned int smB = (unsigned int)__cvta_generic_to_shared(smbuf);

    const int arow = tid >> 3;
    const int acol = (tid & 7) * 4;
    const int brow = tid >> 5;
    const int bcol = (tid & 31) * 4;
    const bool bOk = (nBase + bcol) < N;   // N%4==0 => full float4 valid

    const float* Ap = A + (size_t)(mBase + arow) * K + acol;
    const float* Bp = B + (size_t)brow * N + nBase + bcol;

    float acc[4][4][4];
#pragma unroll
    for (int i = 0; i < 4; i++)
#pragma unroll
        for (int j = 0; j < 4; j++)
#pragma unroll
            for (int q = 0; q < 4; q++) acc[i][j][q] = 0.f;

    float4 aR[4], bR[4];
    const int kChunks = K >> 5;

    auto gload = [&](int ch) {
#pragma unroll
        for (int p = 0; p < 4; p++)
            aR[p] = *(const float4*)(Ap + (size_t)(p * 32) * K + ch * 32);
#pragma unroll
        for (int p = 0; p < 4; p++)
            bR[p] = bOk ? *(const float4*)(Bp + (size_t)(ch * 32 + p * 8) * N)
                        : make_float4(0.f, 0.f, 0.f, 0.f);
    };

    auto sstore = [&](int stg) {
        __nv_bfloat16* st = smbuf + stg * STG;
#pragma unroll
        for (int p = 0; p < 4; p++) {
            int row = arow + p * 32;
            __nv_bfloat16 h0,h1,h2,h3,l0,l1,l2,l3;
            split2(aR[p].x,h0,l0); split2(aR[p].y,h1,l1);
            split2(aR[p].z,h2,l2); split2(aR[p].w,h3,l3);
            __nv_bfloat162 *ph = (__nv_bfloat162*)(st + SA_H + row*ASTR + acol);
            __nv_bfloat162 *pl = (__nv_bfloat162*)(st + SA_L + row*ASTR + acol);
            ph[0] = __halves2bfloat162(h0,h1); ph[1] = __halves2bfloat162(h2,h3);
            pl[0] = __halves2bfloat162(l0,l1); pl[1] = __halves2bfloat162(l2,l3);
        }
#pragma unroll
        for (int p = 0; p < 4; p++) {
            int row = brow + p * 8;
            __nv_bfloat16 h0,h1,h2,h3,l0,l1,l2,l3;
            split2(bR[p].x,h0,l0); split2(bR[p].y,h1,l1);
            split2(bR[p].z,h2,l2); split2(bR[p].w,h3,l3);
            __nv_bfloat162 *ph = (__nv_bfloat162*)(st + SB_H + row*BSTR + bcol);
            __nv_bfloat162 *pl = (__nv_bfloat162*)(st + SB_L + row*BSTR + bcol);
            ph[0] = __halves2bfloat162(h0,h1); ph[1] = __halves2bfloat162(h2,h3);
            pl[0] = __halves2bfloat162(l0,l1); pl[1] = __halves2bfloat162(l2,l3);
        }
    };

    gload(0);
    sstore(0);
    __syncthreads();

#pragma unroll 1
    for (int ch = 0; ch < kChunks; ch++) {
        const int cur = ch & 1;
        const bool more = (ch + 1) < kChunks;

        if (more) gload(ch + 1);

        const unsigned int sb = smB + cur * STG_BYTES;
#pragma unroll
        for (int ks = 0; ks < 2; ks++) {
            const int k0 = ks * 16;
            unsigned int ah[4][4], al[4][4], bh[2][4], bl[2][4];
#pragma unroll
            for (int mf = 0; mf < 4; mf++) {
                int row = wm * 64 + mf * 16 + (lane & 15);
                int col = k0 + (lane >> 4) * 8;
                unsigned int ad = sb + (unsigned int)(row * ASTR + col) * 2;
                ldsm4(ah[mf], ad + SA_H * 2);
                ldsm4(al[mf], ad + SA_L * 2);
            }
#pragma unroll
            for (int nf2 = 0; nf2 < 2; nf2++) {
                int rowk = k0 + (lane & 15);
                int coln = wn * 32 + nf2 * 16 + (lane >> 4) * 8;
                unsigned int bd = sb + (unsigned int)(rowk * BSTR + coln) * 2;
                ldsm4t(bh[nf2], bd + SB_H * 2);
                ldsm4t(bl[nf2], bd + SB_L * 2);
            }
#pragma unroll
            for (int mf = 0; mf < 4; mf++) {
#pragma unroll
                for (int nf = 0; nf < 4; nf++) {
                    unsigned int b0h = bh[nf >> 1][(nf & 1) * 2];
                    unsigned int b1h = bh[nf >> 1][(nf & 1) * 2 + 1];
                    unsigned int b0l = bl[nf >> 1][(nf & 1) * 2];
                    unsigned int b1l = bl[nf >> 1][(nf & 1) * 2 + 1];
                    mma16816(acc[mf][nf], ah[mf], b0h, b1h);
                    mma16816(acc[mf][nf], ah[mf], b0l, b1l);
                    mma16816(acc[mf][nf], al[mf], b0h, b1h);
                }
            }
        }

        if (more) sstore(cur ^ 1);
        __syncthreads();
    }

#pragma unroll
    for (int mf = 0; mf < 4; mf++) {
#pragma unroll
        for (int nf = 0; nf < 4; nf++) {
            int r = mBase + wm * 64 + mf * 16 + (lane >> 2);
            int c = nBase + wn * 32 + nf * 8 + (lane & 3) * 2;
            if (c < N) {
                float a0 = acc[mf][nf][0], a1 = acc[mf][nf][1];
                float a2 = acc[mf][nf][2], a3 = acc[mf][nf][3];
                if (act == 1) {
                    a0 = tanhf(a0); a1 = tanhf(a1);
                    a2 = tanhf(a2); a3 = tanhf(a3);
                }
                *(float2*)&C[(size_t)r * ldc + c] = make_float2(a0, a1);
                *(float2*)&C[(size_t)(r + 8) * ldc + c] = make_float2(a2, a3);
            }
        }
    }
}

// ---------------- E2: 5-way LoRA mix (register-pressure capped) -------------
__global__ __launch_bounds__(256, 3)
void k_mix(const float* __restrict__ x,
           const float* __restrict__ shift,
           const float* __restrict__ w2,
           const float* __restrict__ mr, const float* __restrict__ mk,
           const float* __restrict__ mv, const float* __restrict__ mw,
           const float* __restrict__ mv2) {
    __shared__ float hs[32][160];
    __shared__ float ws[160][32];
    int rowBase = blockIdx.x * 32;
    int colBase = blockIdx.y * 32;
    int tid = threadIdx.x;

    for (int l = tid; l < 32 * 160; l += 256) {
        int rr = l / 160, d = l % 160;
        hs[rr][d] = g_hpre[(rowBase + rr) * 160 + d];
    }
    for (int l = tid; l < 160 * 32; l += 256) {
        int fd = l / 32, cc = l % 32;
        ws[fd][cc] = w2[fd * Cc + colBase + cc];
    }
    __syncthreads();

    int cc = tid % 32;
    int r0 = tid / 32;
    int c  = colBase + cc;
    float tr = mr[c], tk = mk[c], tv = mv[c], tw = mw[c], tv2 = mv2[c];

    for (int rr = r0; rr < 32; rr += 8) {
        float m0 = 0, m1 = 0, m2 = 0, m3 = 0, m4 = 0;
#pragma unroll 8
        for (int d = 0; d < 32; d++) {
            m0 = fmaf(hs[rr][d],       ws[d][cc],       m0);
            m1 = fmaf(hs[rr][32 + d],  ws[32 + d][cc],  m1);
            m2 = fmaf(hs[rr][64 + d],  ws[64 + d][cc],  m2);
            m3 = fmaf(hs[rr][96 + d],  ws[96 + d][cc],  m3);
            m4 = fmaf(hs[rr][128 + d], ws[128 + d][cc], m4);
        }
        int bt  = rowBase + rr;
        int t   = bt % Tt;
        int b   = bt / Tt;
        int idx = bt * Cc + c;
        float xval = x[idx];
        float prev = (t == 0) ? shift[b * Cc + c] : x[idx - Cc];
        float dx   = prev - xval;
        g_xr [idx] = xval + dx * (tr  + m0);
        g_xk [idx] = xval + dx * (tk  + m1);
        g_xv [idx] = xval + dx * (tv  + m2);
        g_xw [idx] = xval + dx * (tw  + m3);
        g_xv2[idx] = xval + dx * (tv2 + m4);
    }
}

// ---------------- E3+E4 fused: decay & v2 epilogues -------------------------
__global__ __launch_bounds__(256)
void k_epi(const float* __restrict__ tdec,
           const float* __restrict__ w2d,
           const float* __restrict__ w2v) {
    __shared__ float tw[32][64];
    __shared__ float tv[32][64];
    __shared__ float wd[64][64];
    __shared__ float wv[64][64];
    int rowBase = blockIdx.x * 32;
    int colBase = blockIdx.y * 64;
    int tid = threadIdx.x;

    for (int l = tid; l < 32 * 64; l += 256) {
        int rr = l / 64, d = l % 64;
        tw[rr][d] = g_tmpw[(rowBase + rr) * 64 + d];
        tv[rr][d] = g_tmpv[(rowBase + rr) * 64 + d];
    }
    for (int l = tid; l < 64 * 64; l += 256) {
        int d = l / 64, cc = l % 64;
        wd[d][cc] = w2d[d * Cc + colBase + cc];
        wv[d][cc] = w2v[d * Cc + colBase + cc];
    }
    __syncthreads();

    int cc = tid % 64;
    int r0 = tid / 64;
    float td = tdec[colBase + cc];
    for (int rr = r0; rr < 32; rr += 4) {
        float sd = td, sv = 0.f;
#pragma unroll 16
        for (int d = 0; d < 64; d++) {
            sd = fmaf(tw[rr][d], wd[d][cc], sd);
            sv = fmaf(tv[rr][d], wv[d][cc], sv);
        }
        int idx = (rowBase + rr) * Cc + colBase + cc;
        g_decay[idx] = expf(-expf(sd));
        g_v2[idx] += sv;
    }
}

// ---------------- S: WKV scan, 256 threads, 4 lanes/column ------------------
#define CHUNK 8
__global__ __launch_bounds__(256)
void k_scan(const float* __restrict__ wkv_in,
            float* __restrict__ wkv_out) {
    const int h = blockIdx.x, b = blockIdx.y;
    const int tid  = threadIdx.x;
    const int lane = tid & 31;
    const int wid  = tid >> 5;
    const int jj   = wid * 8 + (lane >> 2);
    const int q    = lane & 3;

    __shared__ float sbuf[2][4][CHUNK][64];
    const unsigned int sb = (unsigned int)__cvta_generic_to_shared(&sbuf[0][0][0][0]);

    float state[16];
#pragma unroll
    for (int i = 0; i < 16; i++)
        state[i] = wkv_in[(size_t)((b * Hh + h) * Nn + q * 16 + i) * Nn + jj];

    const float* srcs[4] = { g_r, g_k, g_decay, g_v };
    const size_t rowOff = (size_t)h * Nn;

    auto issue = [&](int buf, int t0) {
#pragma unroll
        for (int p = 0; p < 2; p++) {
            int l   = tid + 256 * p;
            int arr = l >> 7;
            int rem = l & 127;
            int t   = rem >> 4;
            int seg = rem & 15;
            const float* gp = srcs[arr] +
                (size_t)(b * Tt + t0 + t) * Cc + rowOff + seg * 4;
            unsigned int da = sb +
                (unsigned int)((((buf * 4 + arr) * CHUNK + t) * 64) + seg * 4) * 4;
            cpasync16(da, gp);
        }
        asm volatile("cp.async.commit_group;");
    };

    issue(0, 0);
    asm volatile("cp.async.wait_group 0;" ::: "memory");
    __syncthreads();

    const int nch = Tt / CHUNK;
    for (int ch = 0; ch < nch; ch++) {
        const int cur = ch & 1;
        if (ch + 1 < nch) issue(cur ^ 1, (ch + 1) * CHUNK);

        const int t0 = ch * CHUNK;
#pragma unroll
        for (int tt = 0; tt < CHUNK; tt++) {
            const float4* rs4 = (const float4*)&sbuf[cur][0][tt][q * 16];
            const float4* ks4 = (const float4*)&sbuf[cur][1][tt][q * 16];
            const float4* ds4 = (const float4*)&sbuf[cur][2][tt][q * 16];
            const float vj = sbuf[cur][3][tt][jj];

            float y = 0.f;
#pragma unroll
            for (int i4 = 0; i4 < 4; i4++) {
                float4 r4 = rs4[i4], k4 = ks4[i4], d4 = ds4[i4];
                float kx, kv;
                float s0 = state[4*i4+0], s1 = state[4*i4+1];
                float s2 = state[4*i4+2], s3 = state[4*i4+3];
                y = fmaf(r4.x, s0, y);
                kx = fmaf(-k4.x, d4.x, k4.x); kv = kx * vj;
                state[4*i4+0] = fmaf(s0, d4.x, kv);
                y = fmaf(r4.y, s1, y);
                kx = fmaf(-k4.y, d4.y, k4.y); kv = kx * vj;
                state[4*i4+1] = fmaf(s1, d4.y, kv);
                y = fmaf(r4.z, s2, y);
                kx = fmaf(-k4.z, d4.z, k4.z); kv = kx * vj;
                state[4*i4+2] = fmaf(s2, d4.z, kv);
                y = fmaf(r4.w, s3, y);
                kx = fmaf(-k4.w, d4.w, k4.w); kv = kx * vj;
                state[4*i4+3] = fmaf(s3, d4.w, kv);
            }
            y += __shfl_xor_sync(0xffffffffu, y, 1);
            y += __shfl_xor_sync(0xffffffffu, y, 2);
            if (q == 0)
                g_ys[(size_t)(b * Tt + t0 + tt) * Cc + rowOff + jj] = y;
        }

        asm volatile("cp.async.wait_group 0;" ::: "memory");
        __syncthreads();
    }

#pragma unroll
    for (int i = 0; i < 16; i++)
        wkv_out[(size_t)((b * Hh + h) * Nn + q * 16 + i) * Nn + jj] = state[i];
}

// ---------------- E5: y = LN(ys + v2) ---------------------------------------
__global__ void k_ln(const float* __restrict__ lnw,
                     const float* __restrict__ lnb) {
    int row = blockIdx.x;
    int tid = threadIdx.x;
    const float* a  = g_ys + (size_t)row * Cc;
    const float* bp = g_v2 + (size_t)row * Cc;
    float s = 0.f, ss = 0.f;
    for (int c = tid; c < Cc; c += 256) {
        float v = a[c] + bp[c];
        s += v; ss += v * v;
    }
    __shared__ float sh1[256], sh2[256];
    sh1[tid] = s; sh2[tid] = ss;
    __syncthreads();
    for (int st = 128; st > 0; st >>= 1) {
        if (tid < st) { sh1[tid] += sh1[tid + st]; sh2[tid] += sh2[tid + st]; }
        __syncthreads();
    }
    float mu  = sh1[0] / Cc;
    float var = sh2[0] / Cc - mu * mu;
    float rstd = rsqrtf(var + 1e-5f);
    for (int c = tid; c < Cc; c += 256) {
        float v = a[c] + bp[c];
        g_ynorm[(size_t)row * Cc + c] = (v - mu) * rstd * lnw[c] + lnb[c];
    }
}

// ---------------- E6: shift_state_out ---------------------------------------
__global__ void k_copyshift(const float* __restrict__ x, float* __restrict__ out) {
    int i = blockIdx.x * 256 + threadIdx.x;
    if (i >= Bb * Cc) return;
    int b = i / Cc, c = i % Cc;
    out[i] = x[(size_t)(b * Tt + Tt - 1) * Cc + c];
}

// ---------------- launcher ---------------------------------------------------
extern "C" void kernel_launch(void* const* d_in, const int* in_sizes, int n_in,
                              void* d_out, int out_size) {
    const float* x        = (const float*)d_in[0];
    const float* shift_in = (const float*)d_in[1];
    const float* wkv_in   = (const float*)d_in[2];
    const float* maa_x    = (const float*)d_in[3];
    const float* maa_r    = (const float*)d_in[4];
    const float* maa_k    = (const float*)d_in[5];
    const float* maa_v    = (const float*)d_in[6];
    const float* maa_w    = (const float*)d_in[7];
    const float* maa_v2   = (const float*)d_in[8];
    const float* maa_w1   = (const float*)d_in[9];
    const float* maa_w2   = (const float*)d_in[10];
    const float* tdecay   = (const float*)d_in[11];
    const float* dec_w1   = (const float*)d_in[12];
    const float* dec_w2   = (const float*)d_in[13];
    const float* v2_w1    = (const float*)d_in[14];
    const float* v2_w2    = (const float*)d_in[15];
    const float* W_r      = (const float*)d_in[16];
    const float* W_k      = (const float*)d_in[17];
    const float* W_v      = (const float*)d_in[18];
    const float* W_o      = (const float*)d_in[19];
    const float* ln_w     = (const float*)d_in[20];
    const float* ln_b     = (const float*)d_in[21];

    float* out_y     = (float*)d_out;
    float* out_shift = out_y + (size_t)BT * Cc;
    float* out_wkv   = out_shift + (size_t)Bb * Cc;

    float *xxx = 0, *xr = 0, *xk = 0, *xv = 0, *xw = 0, *xv2 = 0;
    float *rb = 0, *kb = 0, *vb = 0, *v2b = 0;
    float *hpre = 0, *tmpw = 0, *tmpv = 0, *ynorm = 0;
    cudaGetSymbolAddress((void**)&xxx,   g_xxx);
    cudaGetSymbolAddress((void**)&xr,    g_xr);
    cudaGetSymbolAddress((void**)&xk,    g_xk);
    cudaGetSymbolAddress((void**)&xv,    g_xv);
    cudaGetSymbolAddress((void**)&xw,    g_xw);
    cudaGetSymbolAddress((void**)&xv2,   g_xv2);
    cudaGetSymbolAddress((void**)&rb,    g_r);
    cudaGetSymbolAddress((void**)&kb,    g_k);
    cudaGetSymbolAddress((void**)&vb,    g_v);
    cudaGetSymbolAddress((void**)&v2b,   g_v2);
    cudaGetSymbolAddress((void**)&hpre,  g_hpre);
    cudaGetSymbolAddress((void**)&tmpw,  g_tmpw);
    cudaGetSymbolAddress((void**)&tmpv,  g_tmpv);
    cudaGetSymbolAddress((void**)&ynorm, g_ynorm);

    cudaFuncSetAttribute(k_mma_gemm,
                         cudaFuncAttributeMaxDynamicSharedMemorySize,
                         2 * STG_BYTES);

    const dim3 gemmGrid(Cc / 128, BT / 128);
    const int  gemmSmem = 2 * STG_BYTES;

    // E1: token shift -> xxx
    k_shift<<<BIGN / 256, 256>>>(x, shift_in, maa_x);

    // G1: hpre = tanh(xxx @ maa_w1)  [8192,160]  (tensor cores)
    k_mma_gemm<<<dim3(2, BT / 128), 256, gemmSmem>>>(xxx, maa_w1, hpre,
                                                     BT, 160, Cc, 160, 1);

    // E2: 5-way mix
    k_mix<<<dim3(BT / 32, Cc / 32), 256>>>(x, shift_in, maa_w2,
                                           maa_r, maa_k, maa_v, maa_w, maa_v2);

    // Big GEMMs on tensor cores (bf16x3)
    k_mma_gemm<<<gemmGrid, 256, gemmSmem>>>(xr,  W_r, rb,  BT, Cc, Cc, Cc, 0);
    k_mma_gemm<<<gemmGrid, 256, gemmSmem>>>(xk,  W_k, kb,  BT, Cc, Cc, Cc, 0);
    k_mma_gemm<<<gemmGrid, 256, gemmSmem>>>(xv,  W_v, vb,  BT, Cc, Cc, Cc, 0);
    k_mma_gemm<<<gemmGrid, 256, gemmSmem>>>(xv2, W_v, v2b, BT, Cc, Cc, Cc, 0);

    // Small LoRA GEMMs (tensor cores, fused tanh)
    k_mma_gemm<<<dim3(1, BT / 128), 256, gemmSmem>>>(xw,  dec_w1, tmpw,
                                                     BT, 64, Cc, 64, 1);
    k_mma_gemm<<<dim3(1, BT / 128), 256, gemmSmem>>>(xv2, v2_w1,  tmpv,
                                                     BT, 64, Cc, 64, 1);

    // E3+E4 fused epilogues
    k_epi<<<dim3(BT / 32, Cc / 64), 256>>>(tdecay, dec_w2, v2_w2);

    // WKV scan (k * (1-decay) fused)
    k_scan<<<dim3(Hh, Bb), 256>>>(wkv_in, out_wkv);

    // LayerNorm(ys + v2)
    k_ln<<<BT, 256>>>(ln_w, ln_b);

    // Output GEMM: y = ynorm @ W_o
    k_mma_gemm<<<gemmGrid, 256, gemmSmem>>>(ynorm, W_o, out_y, BT, Cc, Cc, Cc, 0);

    // shift state out
    k_copyshift<<<(Bb * Cc + 255) / 256, 256>>>(x, out_shift);
}

// round 8
// speedup vs baseline: 1.3869x; 1.0296x over previous
#include <cuda_runtime.h>
#include <cuda_bf16.h>
#include <cstdint>
#include <math.h>

// Problem constants
#define Bb   4
#define Tt   2048
#define Cc   2048
#define Hh   32
#define Nn   64
#define BT   (Bb*Tt)          // 8192
#define DMIX 32
#define DDEC 64
#define BIGN (BT*Cc)          // 16,777,216
#define WN   (Cc*Cc)          // 4,194,304

// ---------------- scratch (device globals; no runtime allocation) ----------
__device__ float g_xxx  [BIGN];
__device__ float g_xr   [BIGN];
__device__ float g_xk   [BIGN];
__device__ float g_xv   [BIGN];
__device__ float g_xw   [BIGN];
__device__ float g_xv2  [BIGN];
__device__ float g_r    [BIGN];
__device__ float g_k    [BIGN];
__device__ float g_v    [BIGN];
__device__ float g_v2   [BIGN];
__device__ float g_decay[BIGN];
__device__ float g_ys   [BIGN];
__device__ float g_ynorm[BIGN];
__device__ float g_hpre [BT*160];
__device__ float g_tmpw [BT*DDEC];
__device__ float g_tmpv [BT*DDEC];

// bf16 hi/lo weight planes: [0..n) = hi, [n..2n) = lo
__device__ __nv_bfloat16 g_pWr[2*WN];
__device__ __nv_bfloat16 g_pWk[2*WN];
__device__ __nv_bfloat16 g_pWv[2*WN];
__device__ __nv_bfloat16 g_pWo[2*WN];
__device__ __nv_bfloat16 g_pW1[2*Cc*160];
__device__ __nv_bfloat16 g_pWd[2*Cc*64];
__device__ __nv_bfloat16 g_pWe[2*Cc*64];

__device__ __forceinline__ void split2(float f, __nv_bfloat16& h, __nv_bfloat16& l) {
    h = __float2bfloat16_rn(f);
    l = __float2bfloat16_rn(f - __bfloat162float(h));
}

// ---------------- E1: token shift ------------------------------------------
__global__ void k_shift(const float* __restrict__ x,
                        const float* __restrict__ shift,
                        const float* __restrict__ maa_x) {
    int idx = blockIdx.x * 256 + threadIdx.x;
    if (idx >= BIGN) return;
    int c  = idx % Cc;
    int bt = idx / Cc;
    int t  = bt % Tt;
    int b  = bt / Tt;
    float xv   = x[idx];
    float prev = (t == 0) ? shift[b * Cc + c] : x[idx - Cc];
    g_xxx[idx] = xv + (prev - xv) * maa_x[c];
}

// ---------------- weight fp32 -> bf16 hi/lo planes --------------------------
__global__ void k_conv(const float* __restrict__ src,
                       __nv_bfloat16* __restrict__ dst, int n) {
    int i = blockIdx.x * 256 + threadIdx.x;
    if (i >= n) return;
    __nv_bfloat16 h, l;
    split2(src[i], h, l);
    dst[i]     = h;
    dst[n + i] = l;
}

// =============================================================================
// Tensor-core GEMM v2 (bf16x3, fp32 accumulate):
//   A fp32 [M,K] (split on the fly), B bf16 hi/lo planes [K,N] (cp.async).
//   C = act(A*B). M%128==0, K%32==0, N%8==0. Tile 128x128, BK=32, 2-stage.
//   gridDim.z==2 selects the (A2,B2,C2) problem for z=1 (dual small GEMMs).
// =============================================================================
#define ASTR 40
#define BSTR 136
#define SA_H 0
#define SA_L 5120
#define SB_H 10240
#define SB_L 14592
#define STG  18944
#define STG_BYTES (STG*2)

__device__ __forceinline__ void ldsm4(unsigned int* r, unsigned int addr) {
    asm volatile("ldmatrix.sync.aligned.m8n8.x4.shared.b16 {%0,%1,%2,%3},[%4];"
                 : "=r"(r[0]), "=r"(r[1]), "=r"(r[2]), "=r"(r[3]) : "r"(addr));
}
__device__ __forceinline__ void ldsm4t(unsigned int* r, unsigned int addr) {
    asm volatile("ldmatrix.sync.aligned.m8n8.x4.trans.shared.b16 {%0,%1,%2,%3},[%4];"
                 : "=r"(r[0]), "=r"(r[1]), "=r"(r[2]), "=r"(r[3]) : "r"(addr));
}
__device__ __forceinline__ void mma16816(float* c, const unsigned int* a,
                                         unsigned int b0, unsigned int b1) {
    asm volatile("mma.sync.aligned.m16n8k16.row.col.f32.bf16.bf16.f32 "
                 "{%0,%1,%2,%3},{%4,%5,%6,%7},{%8,%9},{%0,%1,%2,%3};"
                 : "+f"(c[0]), "+f"(c[1]), "+f"(c[2]), "+f"(c[3])
                 : "r"(a[0]), "r"(a[1]), "r"(a[2]), "r"(a[3]), "r"(b0), "r"(b1));
}
__device__ __forceinline__ void cpasync16z(unsigned int daddr, const void* gp, int sz) {
    asm volatile("cp.async.ca.shared.global [%0], [%1], 16, %2;"
                 :: "r"(daddr), "l"(gp), "r"(sz));
}

__global__ __launch_bounds__(256, 1)
void k_gemm2(const float* __restrict__ A1,
             const __nv_bfloat16* __restrict__ B1,
             float* __restrict__ C1,
             const float* __restrict__ A2,
             const __nv_bfloat16* __restrict__ B2,
             float* __restrict__ C2,
             size_t bPlane, int M, int N, int K, int ldc, int act) {
    const float* A         = (blockIdx.z == 0) ? A1 : A2;
    const __nv_bfloat16* B = (blockIdx.z == 0) ? B1 : B2;
    float* C               = (blockIdx.z == 0) ? C1 : C2;

    extern __shared__ __nv_bfloat16 smbuf[];
    const int tid  = threadIdx.x;
    const int lane = tid & 31;
    const int wid  = tid >> 5;
    const int wm   = wid >> 2;
    const int wn   = wid & 3;
    const int mBase = blockIdx.y * 128;
    const int nBase = blockIdx.x * 128;

    const unsigned int smB = (unsigned int)__cvta_generic_to_shared(smbuf);

    // A staging (fp32 -> split -> STS)
    const int arow = tid >> 3;
    const int acol = (tid & 7) * 4;
    const float* Ap = A + (size_t)(mBase + arow) * K + acol;

    // B cp.async mapping: 4 x 16B per thread per stage (2 planes x 32 rows x 16 segs)
    const __nv_bfloat16* Bh = B;
    const __nv_bfloat16* Bl = B + bPlane;

    float acc[4][4][4];
#pragma unroll
    for (int i = 0; i < 4; i++)
#pragma unroll
        for (int j = 0; j < 4; j++)
#pragma unroll
            for (int q = 0; q < 4; q++) acc[i][j][q] = 0.f;

    float4 aR[4];
    const int kChunks = K >> 5;

    auto issueB = [&](int ch) {
        const unsigned int base = smB + (unsigned int)(ch & 1) * STG_BYTES;
#pragma unroll
        for (int q2 = 0; q2 < 4; q2++) {
            int idx = tid + 256 * q2;
            int pl  = idx >> 9;
            int rem = idx & 511;
            int row = rem >> 4;
            int seg = rem & 15;
            int gcol = nBase + seg * 8;
            int ok = gcol < N;
            const __nv_bfloat16* gp = (pl ? Bl : Bh) +
                (ok ? ((size_t)(ch * 32 + row) * N + gcol) : (size_t)0);
            unsigned int da = base +
                (unsigned int)((pl ? SB_L : SB_H) + row * BSTR + seg * 8) * 2;
            cpasync16z(da, gp, ok ? 16 : 0);
        }
        asm volatile("cp.async.commit_group;");
    };

    auto gloadA = [&](int ch) {
#pragma unroll
        for (int p = 0; p < 4; p++)
            aR[p] = *(const float4*)(Ap + (size_t)(p * 32) * K + ch * 32);
    };

    auto sstoreA = [&](int stg) {
        __nv_bfloat16* st = smbuf + stg * STG;
#pragma unroll
        for (int p = 0; p < 4; p++) {
            int row = arow + p * 32;
            __nv_bfloat16 h0,h1,h2,h3,l0,l1,l2,l3;
            split2(aR[p].x,h0,l0); split2(aR[p].y,h1,l1);
            split2(aR[p].z,h2,l2); split2(aR[p].w,h3,l3);
            __nv_bfloat162 *ph = (__nv_bfloat162*)(st + SA_H + row*ASTR + acol);
            __nv_bfloat162 *pl = (__nv_bfloat162*)(st + SA_L + row*ASTR + acol);
            ph[0] = __halves2bfloat162(h0,h1); ph[1] = __halves2bfloat162(h2,h3);
            pl[0] = __halves2bfloat162(l0,l1); pl[1] = __halves2bfloat162(l2,l3);
        }
    };

    // prologue
    gloadA(0);
    issueB(0);
    sstoreA(0);
    asm volatile("cp.async.wait_group 0;" ::: "memory");
    __syncthreads();

#pragma unroll 1
    for (int ch = 0; ch < kChunks; ch++) {
        const int cur = ch & 1;
        const bool more = (ch + 1) < kChunks;

        if (more) {
            issueB(ch + 1);
            gloadA(ch + 1);
        }

        const unsigned int sb = smB + cur * STG_BYTES;
#pragma unroll
        for (int ks = 0; ks < 2; ks++) {
            const int k0 = ks * 16;
            unsigned int ah[4][4], al[4][4], bh[2][4], bl[2][4];
#pragma unroll
            for (int mf = 0; mf < 4; mf++) {
                int row = wm * 64 + mf * 16 + (lane & 15);
                int col = k0 + (lane >> 4) * 8;
                unsigned int ad = sb + (unsigned int)(row * ASTR + col) * 2;
                ldsm4(ah[mf], ad + SA_H * 2);
                ldsm4(al[mf], ad + SA_L * 2);
            }
#pragma unroll
            for (int nf2 = 0; nf2 < 2; nf2++) {
                int rowk = k0 + (lane & 15);
                int coln = wn * 32 + nf2 * 16 + (lane >> 4) * 8;
                unsigned int bd = sb + (unsigned int)(rowk * BSTR + coln) * 2;
                ldsm4t(bh[nf2], bd + SB_H * 2);
                ldsm4t(bl[nf2], bd + SB_L * 2);
            }
#pragma unroll
            for (int mf = 0; mf < 4; mf++) {
#pragma unroll
                for (int nf = 0; nf < 4; nf++) {
                    unsigned int b0h = bh[nf >> 1][(nf & 1) * 2];
                    unsigned int b1h = bh[nf >> 1][(nf & 1) * 2 + 1];
                    unsigned int b0l = bl[nf >> 1][(nf & 1) * 2];
                    unsigned int b1l = bl[nf >> 1][(nf & 1) * 2 + 1];
                    mma16816(acc[mf][nf], ah[mf], b0h, b1h);
                    mma16816(acc[mf][nf], ah[mf], b0l, b1l);
                    mma16816(acc[mf][nf], al[mf], b0h, b1h);
                }
            }
        }

        if (more) sstoreA(cur ^ 1);
        asm volatile("cp.async.wait_group 0;" ::: "memory");
        __syncthreads();
    }

    // epilogue
#pragma unroll
    for (int mf = 0; mf < 4; mf++) {
#pragma unroll
        for (int nf = 0; nf < 4; nf++) {
            int r = mBase + wm * 64 + mf * 16 + (lane >> 2);
            int c = nBase + wn * 32 + nf * 8 + (lane & 3) * 2;
            if (c < N) {
                float a0 = acc[mf][nf][0], a1 = acc[mf][nf][1];
                float a2 = acc[mf][nf][2], a3 = acc[mf][nf][3];
                if (act == 1) {
                    a0 = tanhf(a0); a1 = tanhf(a1);
                    a2 = tanhf(a2); a3 = tanhf(a3);
                }
                *(float2*)&C[(size_t)r * ldc + c] = make_float2(a0, a1);
                *(float2*)&C[(size_t)(r + 8) * ldc + c] = make_float2(a2, a3);
            }
        }
    }
}

// ---------------- E2: 5-way LoRA mix (register-pressure capped) -------------
__global__ __launch_bounds__(256, 3)
void k_mix(const float* __restrict__ x,
           const float* __restrict__ shift,
           const float* __restrict__ w2,
           const float* __restrict__ mr, const float* __restrict__ mk,
           const float* __restrict__ mv, const float* __restrict__ mw,
           const float* __restrict__ mv2) {
    __shared__ float hs[32][160];
    __shared__ float ws[160][32];
    int rowBase = blockIdx.x * 32;
    int colBase = blockIdx.y * 32;
    int tid = threadIdx.x;

    for (int l = tid; l < 32 * 160; l += 256) {
        int rr = l / 160, d = l % 160;
        hs[rr][d] = g_hpre[(rowBase + rr) * 160 + d];
    }
    for (int l = tid; l < 160 * 32; l += 256) {
        int fd = l / 32, cc = l % 32;
        ws[fd][cc] = w2[fd * Cc + colBase + cc];
    }
    __syncthreads();

    int cc = tid % 32;
    int r0 = tid / 32;
    int c  = colBase + cc;
    float tr = mr[c], tk = mk[c], tv = mv[c], tw = mw[c], tv2 = mv2[c];

    for (int rr = r0; rr < 32; rr += 8) {
        float m0 = 0, m1 = 0, m2 = 0, m3 = 0, m4 = 0;
#pragma unroll 8
        for (int d = 0; d < 32; d++) {
            m0 = fmaf(hs[rr][d],       ws[d][cc],       m0);
            m1 = fmaf(hs[rr][32 + d],  ws[32 + d][cc],  m1);
            m2 = fmaf(hs[rr][64 + d],  ws[64 + d][cc],  m2);
            m3 = fmaf(hs[rr][96 + d],  ws[96 + d][cc],  m3);
            m4 = fmaf(hs[rr][128 + d], ws[128 + d][cc], m4);
        }
        int bt  = rowBase + rr;
        int t   = bt % Tt;
        int b   = bt / Tt;
        int idx = bt * Cc + c;
        float xval = x[idx];
        float prev = (t == 0) ? shift[b * Cc + c] : x[idx - Cc];
        float dx   = prev - xval;
        g_xr [idx] = xval + dx * (tr  + m0);
        g_xk [idx] = xval + dx * (tk  + m1);
        g_xv [idx] = xval + dx * (tv  + m2);
        g_xw [idx] = xval + dx * (tw  + m3);
        g_xv2[idx] = xval + dx * (tv2 + m4);
    }
}

// ---------------- E3+E4 fused: decay & v2 epilogues -------------------------
__global__ __launch_bounds__(256)
void k_epi(const float* __restrict__ tdec,
           const float* __restrict__ w2d,
           const float* __restrict__ w2v) {
    __shared__ float tw[32][64];
    __shared__ float tv[32][64];
    __shared__ float wd[64][64];
    __shared__ float wv[64][64];
    int rowBase = blockIdx.x * 32;
    int colBase = blockIdx.y * 64;
    int tid = threadIdx.x;

    for (int l = tid; l < 32 * 64; l += 256) {
        int rr = l / 64, d = l % 64;
        tw[rr][d] = g_tmpw[(rowBase + rr) * 64 + d];
        tv[rr][d] = g_tmpv[(rowBase + rr) * 64 + d];
    }
    for (int l = tid; l < 64 * 64; l += 256) {
        int d = l / 64, cc = l % 64;
        wd[d][cc] = w2d[d * Cc + colBase + cc];
        wv[d][cc] = w2v[d * Cc + colBase + cc];
    }
    __syncthreads();

    int cc = tid % 64;
    int r0 = tid / 64;
    float td = tdec[colBase + cc];
    for (int rr = r0; rr < 32; rr += 4) {
        float sd = td, sv = 0.f;
#pragma unroll 16
        for (int d = 0; d < 64; d++) {
            sd = fmaf(tw[rr][d], wd[d][cc], sd);
            sv = fmaf(tv[rr][d], wv[d][cc], sv);
        }
        int idx = (rowBase + rr) * Cc + colBase + cc;
        g_decay[idx] = expf(-expf(sd));
        g_v2[idx] += sv;
    }
}

// ---------------- S: WKV scan, 256 threads, 4 lanes/column ------------------
#define CHUNK 8
__device__ __forceinline__ void cpasync16(unsigned int daddr, const void* gp) {
    asm volatile("cp.async.ca.shared.global [%0], [%1], 16;"
                 :: "r"(daddr), "l"(gp));
}
__global__ __launch_bounds__(256)
void k_scan(const float* __restrict__ wkv_in,
            float* __restrict__ wkv_out) {
    const int h = blockIdx.x, b = blockIdx.y;
    const int tid  = threadIdx.x;
    const int lane = tid & 31;
    const int wid  = tid >> 5;
    const int jj   = wid * 8 + (lane >> 2);
    const int q    = lane & 3;

    __shared__ float sbuf[2][4][CHUNK][64];
    const unsigned int sb = (unsigned int)__cvta_generic_to_shared(&sbuf[0][0][0][0]);

    float state[16];
#pragma unroll
    for (int i = 0; i < 16; i++)
        state[i] = wkv_in[(size_t)((b * Hh + h) * Nn + q * 16 + i) * Nn + jj];

    const float* srcs[4] = { g_r, g_k, g_decay, g_v };
    const size_t rowOff = (size_t)h * Nn;

    auto issue = [&](int buf, int t0) {
#pragma unroll
        for (int p = 0; p < 2; p++) {
            int l   = tid + 256 * p;
            int arr = l >> 7;
            int rem = l & 127;
            int t   = rem >> 4;
            int seg = rem & 15;
            const float* gp = srcs[arr] +
                (size_t)(b * Tt + t0 + t) * Cc + rowOff + seg * 4;
            unsigned int da = sb +
                (unsigned int)((((buf * 4 + arr) * CHUNK + t) * 64) + seg * 4) * 4;
            cpasync16(da, gp);
        }
        asm volatile("cp.async.commit_group;");
    };

    issue(0, 0);
    asm volatile("cp.async.wait_group 0;" ::: "memory");
    __syncthreads();

    const int nch = Tt / CHUNK;
    for (int ch = 0; ch < nch; ch++) {
        const int cur = ch & 1;
        if (ch + 1 < nch) issue(cur ^ 1, (ch + 1) * CHUNK);

        const int t0 = ch * CHUNK;
#pragma unroll
        for (int tt = 0; tt < CHUNK; tt++) {
            const float4* rs4 = (const float4*)&sbuf[cur][0][tt][q * 16];
            const float4* ks4 = (const float4*)&sbuf[cur][1][tt][q * 16];
            const float4* ds4 = (const float4*)&sbuf[cur][2][tt][q * 16];
            const float vj = sbuf[cur][3][tt][jj];

            float y = 0.f;
#pragma unroll
            for (int i4 = 0; i4 < 4; i4++) {
                float4 r4 = rs4[i4], k4 = ks4[i4], d4 = ds4[i4];
                float kx, kv;
                float s0 = state[4*i4+0], s1 = state[4*i4+1];
                float s2 = state[4*i4+2], s3 = state[4*i4+3];
                y = fmaf(r4.x, s0, y);
                kx = fmaf(-k4.x, d4.x, k4.x); kv = kx * vj;
                state[4*i4+0] = fmaf(s0, d4.x, kv);
                y = fmaf(r4.y, s1, y);
                kx = fmaf(-k4.y, d4.y, k4.y); kv = kx * vj;
                state[4*i4+1] = fmaf(s1, d4.y, kv);
                y = fmaf(r4.z, s2, y);
                kx = fmaf(-k4.z, d4.z, k4.z); kv = kx * vj;
                state[4*i4+2] = fmaf(s2, d4.z, kv);
                y = fmaf(r4.w, s3, y);
                kx = fmaf(-k4.w, d4.w, k4.w); kv = kx * vj;
                state[4*i4+3] = fmaf(s3, d4.w, kv);
            }
            y += __shfl_xor_sync(0xffffffffu, y, 1);
            y += __shfl_xor_sync(0xffffffffu, y, 2);
            if (q == 0)
                g_ys[(size_t)(b * Tt + t0 + tt) * Cc + rowOff + jj] = y;
        }

        asm volatile("cp.async.wait_group 0;" ::: "memory");
        __syncthreads();
    }

#pragma unroll
    for (int i = 0; i < 16; i++)
        wkv_out[(size_t)((b * Hh + h) * Nn + q * 16 + i) * Nn + jj] = state[i];
}

// ---------------- E5: y = LN(ys + v2) ---------------------------------------
__global__ void k_ln(const float* __restrict__ lnw,
                     const float* __restrict__ lnb) {
    int row = blockIdx.x;
    int tid = threadIdx.x;
    const float* a  = g_ys + (size_t)row * Cc;
    const float* bp = g_v2 + (size_t)row * Cc;
    float s = 0.f, ss = 0.f;
    for (int c = tid; c < Cc; c += 256) {
        float v = a[c] + bp[c];
        s += v; ss += v * v;
    }
    __shared__ float sh1[256], sh2[256];
    sh1[tid] = s; sh2[tid] = ss;
    __syncthreads();
    for (int st = 128; st > 0; st >>= 1) {
        if (tid < st) { sh1[tid] += sh1[tid + st]; sh2[tid] += sh2[tid + st]; }
        __syncthreads();
    }
    float mu  = sh1[0] / Cc;
    float var = sh2[0] / Cc - mu * mu;
    float rstd = rsqrtf(var + 1e-5f);
    for (int c = tid; c < Cc; c += 256) {
        float v = a[c] + bp[c];
        g_ynorm[(size_t)row * Cc + c] = (v - mu) * rstd * lnw[c] + lnb[c];
    }
}

// ---------------- E6: shift_state_out ---------------------------------------
__global__ void k_copyshift(const float* __restrict__ x, float* __restrict__ out) {
    int i = blockIdx.x * 256 + threadIdx.x;
    if (i >= Bb * Cc) return;
    int b = i / Cc, c = i % Cc;
    out[i] = x[(size_t)(b * Tt + Tt - 1) * Cc + c];
}

// ---------------- launcher ---------------------------------------------------
extern "C" void kernel_launch(void* const* d_in, const int* in_sizes, int n_in,
                              void* d_out, int out_size) {
    const float* x        = (const float*)d_in[0];
    const float* shift_in = (const float*)d_in[1];
    const float* wkv_in   = (const float*)d_in[2];
    const float* maa_x    = (const float*)d_in[3];
    const float* maa_r    = (const float*)d_in[4];
    const float* maa_k    = (const float*)d_in[5];
    const float* maa_v    = (const float*)d_in[6];
    const float* maa_w    = (const float*)d_in[7];
    const float* maa_v2   = (const float*)d_in[8];
    const float* maa_w1   = (const float*)d_in[9];
    const float* maa_w2   = (const float*)d_in[10];
    const float* tdecay   = (const float*)d_in[11];
    const float* dec_w1   = (const float*)d_in[12];
    const float* dec_w2   = (const float*)d_in[13];
    const float* v2_w1    = (const float*)d_in[14];
    const float* v2_w2    = (const float*)d_in[15];
    const float* W_r      = (const float*)d_in[16];
    const float* W_k      = (const float*)d_in[17];
    const float* W_v      = (const float*)d_in[18];
    const float* W_o      = (const float*)d_in[19];
    const float* ln_w     = (const float*)d_in[20];
    const float* ln_b     = (const float*)d_in[21];

    float* out_y     = (float*)d_out;
    float* out_shift = out_y + (size_t)BT * Cc;
    float* out_wkv   = out_shift + (size_t)Bb * Cc;

    float *xxx = 0, *xr = 0, *xk = 0, *xv = 0, *xw = 0, *xv2 = 0;
    float *rb = 0, *kb = 0, *vb = 0, *v2b = 0;
    float *hpre = 0, *tmpw = 0, *tmpv = 0, *ynorm = 0;
    __nv_bfloat16 *pWr = 0, *pWk = 0, *pWv = 0, *pWo = 0;
    __nv_bfloat16 *pW1 = 0, *pWd = 0, *pWe = 0;
    cudaGetSymbolAddress((void**)&xxx,   g_xxx);
    cudaGetSymbolAddress((void**)&xr,    g_xr);
    cudaGetSymbolAddress((void**)&xk,    g_xk);
    cudaGetSymbolAddress((void**)&xv,    g_xv);
    cudaGetSymbolAddress((void**)&xw,    g_xw);
    cudaGetSymbolAddress((void**)&xv2,   g_xv2);
    cudaGetSymbolAddress((void**)&rb,    g_r);
    cudaGetSymbolAddress((void**)&kb,    g_k);
    cudaGetSymbolAddress((void**)&vb,    g_v);
    cudaGetSymbolAddress((void**)&v2b,   g_v2);
    cudaGetSymbolAddress((void**)&hpre,  g_hpre);
    cudaGetSymbolAddress((void**)&tmpw,  g_tmpw);
    cudaGetSymbolAddress((void**)&tmpv,  g_tmpv);
    cudaGetSymbolAddress((void**)&ynorm, g_ynorm);
    cudaGetSymbolAddress((void**)&pWr,   g_pWr);
    cudaGetSymbolAddress((void**)&pWk,   g_pWk);
    cudaGetSymbolAddress((void**)&pWv,   g_pWv);
    cudaGetSymbolAddress((void**)&pWo,   g_pWo);
    cudaGetSymbolAddress((void**)&pW1,   g_pW1);
    cudaGetSymbolAddress((void**)&pWd,   g_pWd);
    cudaGetSymbolAddress((void**)&pWe,   g_pWe);

    cudaFuncSetAttribute(k_gemm2,
                         cudaFuncAttributeMaxDynamicSharedMemorySize,
                         2 * STG_BYTES);

    const dim3 gemmGrid(Cc / 128, BT / 128, 1);
    const int  gemmSmem = 2 * STG_BYTES;

    // weight conversions (every launch; deterministic)
    k_conv<<<WN / 256, 256>>>(W_r, pWr, WN);
    k_conv<<<WN / 256, 256>>>(W_k, pWk, WN);
    k_conv<<<WN / 256, 256>>>(W_v, pWv, WN);
    k_conv<<<WN / 256, 256>>>(W_o, pWo, WN);
    k_conv<<<(Cc * 160) / 256, 256>>>(maa_w1, pW1, Cc * 160);
    k_conv<<<(Cc * 64) / 256, 256>>>(dec_w1, pWd, Cc * 64);
    k_conv<<<(Cc * 64) / 256, 256>>>(v2_w1, pWe, Cc * 64);

    // E1: token shift -> xxx
    k_shift<<<BIGN / 256, 256>>>(x, shift_in, maa_x);

    // G1: hpre = tanh(xxx @ maa_w1)  [8192,160]
    k_gemm2<<<dim3(2, BT / 128, 1), 256, gemmSmem>>>(
        xxx, pW1, hpre, xxx, pW1, hpre,
        (size_t)Cc * 160, BT, 160, Cc, 160, 1);

    // E2: 5-way mix
    k_mix<<<dim3(BT / 32, Cc / 32), 256>>>(x, shift_in, maa_w2,
                                           maa_r, maa_k, maa_v, maa_w, maa_v2);

    // Big GEMMs (bf16x3, B via cp.async planes)
    k_gemm2<<<gemmGrid, 256, gemmSmem>>>(xr,  pWr, rb,  xr,  pWr, rb,
                                         (size_t)WN, BT, Cc, Cc, Cc, 0);
    k_gemm2<<<gemmGrid, 256, gemmSmem>>>(xk,  pWk, kb,  xk,  pWk, kb,
                                         (size_t)WN, BT, Cc, Cc, Cc, 0);
    k_gemm2<<<gemmGrid, 256, gemmSmem>>>(xv,  pWv, vb,  xv,  pWv, vb,
                                         (size_t)WN, BT, Cc, Cc, Cc, 0);
    k_gemm2<<<gemmGrid, 256, gemmSmem>>>(xv2, pWv, v2b, xv2, pWv, v2b,
                                         (size_t)WN, BT, Cc, Cc, Cc, 0);

    // Small LoRA GEMMs (dual problem via gridDim.z=2, fused tanh)
    k_gemm2<<<dim3(1, BT / 128, 2), 256, gemmSmem>>>(
        xw, pWd, tmpw, xv2, pWe, tmpv,
        (size_t)Cc * 64, BT, 64, Cc, 64, 1);

    // E3+E4 fused epilogues
    k_epi<<<dim3(BT / 32, Cc / 64), 256>>>(tdecay, dec_w2, v2_w2);

    // WKV scan (k * (1-decay) fused)
    k_scan<<<dim3(Hh, Bb), 256>>>(wkv_in, out_wkv);

    // LayerNorm(ys + v2)
    k_ln<<<BT, 256>>>(ln_w, ln_b);

    // Output GEMM: y = ynorm @ W_o
    k_gemm2<<<gemmGrid, 256, gemmSmem>>>(ynorm, pWo, out_y, ynorm, pWo, out_y,
                                         (size_t)WN, BT, Cc, Cc, Cc, 0);

    // shift state out
    k_copyshift<<<(Bb * Cc + 255) / 256, 256>>>(x, out_shift);
}

// round 9
// speedup vs baseline: 1.3886x; 1.0012x over previous
#include <cuda_runtime.h>
#include <cuda_bf16.h>
#include <cstdint>
#include <math.h>

// Problem constants
#define Bb   4
#define Tt   2048
#define Cc   2048
#define Hh   32
#define Nn   64
#define BT   (Bb*Tt)          // 8192
#define DMIX 32
#define DDEC 64
#define BIGN (BT*Cc)          // 16,777,216
#define WN   (Cc*Cc)          // 4,194,304

// ---------------- scratch (device globals; no runtime allocation) ----------
__device__ float g_r    [BIGN];
__device__ float g_k    [BIGN];
__device__ float g_v    [BIGN];
__device__ float g_v2   [BIGN];
__device__ float g_decay[BIGN];
__device__ float g_ys   [BIGN];
__device__ float g_hpre [BT*160];
__device__ float g_tmpw [BT*DDEC];
__device__ float g_tmpv [BT*DDEC];

// bf16 hi/lo planes (activations): [0..BIGN) hi, [BIGN..2*BIGN) lo
__device__ __nv_bfloat16 g_pxxx[2*BIGN];
__device__ __nv_bfloat16 g_pxr [2*BIGN];
__device__ __nv_bfloat16 g_pxk [2*BIGN];
__device__ __nv_bfloat16 g_pxv [2*BIGN];
__device__ __nv_bfloat16 g_pxw [2*BIGN];
__device__ __nv_bfloat16 g_pxv2[2*BIGN];
__device__ __nv_bfloat16 g_pyn [2*BIGN];
// weight planes
__device__ __nv_bfloat16 g_pWr[2*WN];
__device__ __nv_bfloat16 g_pWk[2*WN];
__device__ __nv_bfloat16 g_pWv[2*WN];
__device__ __nv_bfloat16 g_pWo[2*WN];
__device__ __nv_bfloat16 g_pW1[2*Cc*160];
__device__ __nv_bfloat16 g_pWd[2*Cc*64];
__device__ __nv_bfloat16 g_pWe[2*Cc*64];

__device__ __forceinline__ void split2(float f, __nv_bfloat16& h, __nv_bfloat16& l) {
    h = __float2bfloat16_rn(f);
    l = __float2bfloat16_rn(f - __bfloat162float(h));
}

// ---------------- E1: token shift -> xxx planes -----------------------------
__global__ void k_shift(const float* __restrict__ x,
                        const float* __restrict__ shift,
                        const float* __restrict__ maa_x) {
    int idx = blockIdx.x * 256 + threadIdx.x;
    if (idx >= BIGN) return;
    int c  = idx % Cc;
    int bt = idx / Cc;
    int t  = bt % Tt;
    int b  = bt / Tt;
    float xv   = x[idx];
    float prev = (t == 0) ? shift[b * Cc + c] : x[idx - Cc];
    float r    = xv + (prev - xv) * maa_x[c];
    __nv_bfloat16 h, l;
    split2(r, h, l);
    g_pxxx[idx] = h; g_pxxx[BIGN + idx] = l;
}

// ---------------- weight fp32 -> bf16 hi/lo planes --------------------------
__global__ void k_conv(const float* __restrict__ src,
                       __nv_bfloat16* __restrict__ dst, int n) {
    int i = blockIdx.x * 256 + threadIdx.x;
    if (i >= n) return;
    __nv_bfloat16 h, l;
    split2(src[i], h, l);
    dst[i]     = h;
    dst[n + i] = l;
}

// =============================================================================
// Tensor-core GEMM v3 (bf16x3, fp32 accumulate):
//   A bf16 hi/lo planes [M,K], B bf16 hi/lo planes [K,N], all via cp.async.
//   C = act(A*B). M%128==0, K%32==0, N%8==0. Tile 128x128, BK=32, 4 stages.
//   gridDim.z==2 selects (A2,B2,C2) for z=1.
// =============================================================================
#define ASTR 40
#define BSTR 136
#define SA_H 0
#define SA_L 5120
#define SB_H 10240
#define SB_L 14592
#define STG  18944
#define STG_BYTES (STG*2)
#define NSTAGE 4

__device__ __forceinline__ void ldsm4(unsigned int* r, unsigned int addr) {
    asm volatile("ldmatrix.sync.aligned.m8n8.x4.shared.b16 {%0,%1,%2,%3},[%4];"
                 : "=r"(r[0]), "=r"(r[1]), "=r"(r[2]), "=r"(r[3]) : "r"(addr));
}
__device__ __forceinline__ void ldsm4t(unsigned int* r, unsigned int addr) {
    asm volatile("ldmatrix.sync.aligned.m8n8.x4.trans.shared.b16 {%0,%1,%2,%3},[%4];"
                 : "=r"(r[0]), "=r"(r[1]), "=r"(r[2]), "=r"(r[3]) : "r"(addr));
}
__device__ __forceinline__ void mma16816(float* c, const unsigned int* a,
                                         unsigned int b0, unsigned int b1) {
    asm volatile("mma.sync.aligned.m16n8k16.row.col.f32.bf16.bf16.f32 "
                 "{%0,%1,%2,%3},{%4,%5,%6,%7},{%8,%9},{%0,%1,%2,%3};"
                 : "+f"(c[0]), "+f"(c[1]), "+f"(c[2]), "+f"(c[3])
                 : "r"(a[0]), "r"(a[1]), "r"(a[2]), "r"(a[3]), "r"(b0), "r"(b1));
}
__device__ __forceinline__ void cpasync16z(unsigned int daddr, const void* gp, int sz) {
    asm volatile("cp.async.ca.shared.global [%0], [%1], 16, %2;"
                 :: "r"(daddr), "l"(gp), "r"(sz));
}

__global__ __launch_bounds__(256, 1)
void k_gemm3(const __nv_bfloat16* __restrict__ A1,
             const __nv_bfloat16* __restrict__ B1,
             float* __restrict__ C1,
             const __nv_bfloat16* __restrict__ A2,
             const __nv_bfloat16* __restrict__ B2,
             float* __restrict__ C2,
             size_t aPlane, size_t bPlane,
             int M, int N, int K, int ldc, int act) {
    const __nv_bfloat16* A = (blockIdx.z == 0) ? A1 : A2;
    const __nv_bfloat16* B = (blockIdx.z == 0) ? B1 : B2;
    float* C               = (blockIdx.z == 0) ? C1 : C2;

    extern __shared__ __nv_bfloat16 smbuf[];
    const int tid  = threadIdx.x;
    const int lane = tid & 31;
    const int wid  = tid >> 5;
    const int wm   = wid >> 2;
    const int wn   = wid & 3;
    const int mBase = blockIdx.y * 128;
    const int nBase = blockIdx.x * 128;

    const unsigned int smB = (unsigned int)__cvta_generic_to_shared(smbuf);

    const __nv_bfloat16* Ah = A;
    const __nv_bfloat16* Al = A + aPlane;
    const __nv_bfloat16* Bh = B;
    const __nv_bfloat16* Bl = B + bPlane;

    const int kChunks = K >> 5;

    // 8 x 16B cp.async per thread per stage:
    //   A: 2 planes x 128 rows x 4 segs = 1024 chunks
    //   B: 2 planes x  32 rows x 16 segs = 1024 chunks
    auto issue = [&](int ch) {
        if (ch < kChunks) {
            const unsigned int base = smB + (unsigned int)(ch % NSTAGE) * STG_BYTES;
#pragma unroll
            for (int q2 = 0; q2 < 4; q2++) {   // A chunks
                int idx = tid + 256 * q2;
                int pl  = idx >> 9;
                int rem = idx & 511;
                int row = rem >> 2;            // 0..127
                int seg = rem & 3;             // 0..3
                const __nv_bfloat16* gp = (pl ? Al : Ah) +
                    (size_t)(mBase + row) * K + ch * 32 + seg * 8;
                unsigned int da = base +
                    (unsigned int)((pl ? SA_L : SA_H) + row * ASTR + seg * 8) * 2;
                cpasync16z(da, gp, 16);
            }
#pragma unroll
            for (int q2 = 0; q2 < 4; q2++) {   // B chunks
                int idx = tid + 256 * q2;
                int pl  = idx >> 9;
                int rem = idx & 511;
                int row = rem >> 4;            // 0..31
                int seg = rem & 15;            // 0..15
                int gcol = nBase + seg * 8;
                int ok = gcol < N;
                const __nv_bfloat16* gp = (pl ? Bl : Bh) +
                    (ok ? ((size_t)(ch * 32 + row) * N + gcol) : (size_t)0);
                unsigned int da = base +
                    (unsigned int)((pl ? SB_L : SB_H) + row * BSTR + seg * 8) * 2;
                cpasync16z(da, gp, ok ? 16 : 0);
            }
        }
        asm volatile("cp.async.commit_group;");
    };

    float acc[4][4][4];
#pragma unroll
    for (int i = 0; i < 4; i++)
#pragma unroll
        for (int j = 0; j < 4; j++)
#pragma unroll
            for (int q = 0; q < 4; q++) acc[i][j][q] = 0.f;

    // prologue: 3 stages in flight
    issue(0); issue(1); issue(2);

#pragma unroll 1
    for (int ch = 0; ch < kChunks; ch++) {
        asm volatile("cp.async.wait_group 2;" ::: "memory");
        __syncthreads();
        issue(ch + 3);   // stage (ch+3)%4 == (ch-1)%4, free after the sync above

        const unsigned int sb = smB + (unsigned int)(ch % NSTAGE) * STG_BYTES;
#pragma unroll
        for (int ks = 0; ks < 2; ks++) {
            const int k0 = ks * 16;
            unsigned int ah[4][4], al[4][4], bh[2][4], bl[2][4];
#pragma unroll
            for (int mf = 0; mf < 4; mf++) {
                int row = wm * 64 + mf * 16 + (lane & 15);
                int col = k0 + (lane >> 4) * 8;
                unsigned int ad = sb + (unsigned int)(row * ASTR + col) * 2;
                ldsm4(ah[mf], ad + SA_H * 2);
                ldsm4(al[mf], ad + SA_L * 2);
            }
#pragma unroll
            for (int nf2 = 0; nf2 < 2; nf2++) {
                int rowk = k0 + (lane & 15);
                int coln = wn * 32 + nf2 * 16 + (lane >> 4) * 8;
                unsigned int bd = sb + (unsigned int)(rowk * BSTR + coln) * 2;
                ldsm4t(bh[nf2], bd + SB_H * 2);
                ldsm4t(bl[nf2], bd + SB_L * 2);
            }
#pragma unroll
            for (int mf = 0; mf < 4; mf++) {
#pragma unroll
                for (int nf = 0; nf < 4; nf++) {
                    unsigned int b0h = bh[nf >> 1][(nf & 1) * 2];
                    unsigned int b1h = bh[nf >> 1][(nf & 1) * 2 + 1];
                    unsigned int b0l = bl[nf >> 1][(nf & 1) * 2];
                    unsigned int b1l = bl[nf >> 1][(nf & 1) * 2 + 1];
                    mma16816(acc[mf][nf], ah[mf], b0h, b1h);
                    mma16816(acc[mf][nf], ah[mf], b0l, b1l);
                    mma16816(acc[mf][nf], al[mf], b0h, b1h);
                }
            }
        }
    }

    // epilogue
#pragma unroll
    for (int mf = 0; mf < 4; mf++) {
#pragma unroll
        for (int nf = 0; nf < 4; nf++) {
            int r = mBase + wm * 64 + mf * 16 + (lane >> 2);
            int c = nBase + wn * 32 + nf * 8 + (lane & 3) * 2;
            if (c < N) {
                float a0 = acc[mf][nf][0], a1 = acc[mf][nf][1];
                float a2 = acc[mf][nf][2], a3 = acc[mf][nf][3];
                if (act == 1) {
                    a0 = tanhf(a0); a1 = tanhf(a1);
                    a2 = tanhf(a2); a3 = tanhf(a3);
                }
                *(float2*)&C[(size_t)r * ldc + c] = make_float2(a0, a1);
                *(float2*)&C[(size_t)(r + 8) * ldc + c] = make_float2(a2, a3);
            }
        }
    }
}

// ---------------- E2: 5-way LoRA mix -> bf16 planes -------------------------
__global__ __launch_bounds__(256, 3)
void k_mix(const float* __restrict__ x,
           const float* __restrict__ shift,
           const float* __restrict__ w2,
           const float* __restrict__ mr, const float* __restrict__ mk,
           const float* __restrict__ mv, const float* __restrict__ mw,
           const float* __restrict__ mv2) {
    __shared__ float hs[32][160];
    __shared__ float ws[160][32];
    int rowBase = blockIdx.x * 32;
    int colBase = blockIdx.y * 32;
    int tid = threadIdx.x;

    for (int l = tid; l < 32 * 160; l += 256) {
        int rr = l / 160, d = l % 160;
        hs[rr][d] = g_hpre[(rowBase + rr) * 160 + d];
    }
    for (int l = tid; l < 160 * 32; l += 256) {
        int fd = l / 32, cc = l % 32;
        ws[fd][cc] = w2[fd * Cc + colBase + cc];
    }
    __syncthreads();

    int cc = tid % 32;
    int r0 = tid / 32;
    int c  = colBase + cc;
    float tr = mr[c], tk = mk[c], tv = mv[c], tw = mw[c], tv2 = mv2[c];

    for (int rr = r0; rr < 32; rr += 8) {
        float m0 = 0, m1 = 0, m2 = 0, m3 = 0, m4 = 0;
#pragma unroll 8
        for (int d = 0; d < 32; d++) {
            m0 = fmaf(hs[rr][d],       ws[d][cc],       m0);
            m1 = fmaf(hs[rr][32 + d],  ws[32 + d][cc],  m1);
            m2 = fmaf(hs[rr][64 + d],  ws[64 + d][cc],  m2);
            m3 = fmaf(hs[rr][96 + d],  ws[96 + d][cc],  m3);
            m4 = fmaf(hs[rr][128 + d], ws[128 + d][cc], m4);
        }
        int bt  = rowBase + rr;
        int t   = bt % Tt;
        int b   = bt / Tt;
        int idx = bt * Cc + c;
        float xval = x[idx];
        float prev = (t == 0) ? shift[b * Cc + c] : x[idx - Cc];
        float dx   = prev - xval;
        float vr  = xval + dx * (tr  + m0);
        float vk  = xval + dx * (tk  + m1);
        float vv  = xval + dx * (tv  + m2);
        float vw  = xval + dx * (tw  + m3);
        float vv2 = xval + dx * (tv2 + m4);
        __nv_bfloat16 h, l;
        split2(vr,  h, l); g_pxr [idx] = h; g_pxr [BIGN + idx] = l;
        split2(vk,  h, l); g_pxk [idx] = h; g_pxk [BIGN + idx] = l;
        split2(vv,  h, l); g_pxv [idx] = h; g_pxv [BIGN + idx] = l;
        split2(vw,  h, l); g_pxw [idx] = h; g_pxw [BIGN + idx] = l;
        split2(vv2, h, l); g_pxv2[idx] = h; g_pxv2[BIGN + idx] = l;
    }
}

// ---------------- E3+E4 fused: decay & v2 epilogues -------------------------
__global__ __launch_bounds__(256)
void k_epi(const float* __restrict__ tdec,
           const float* __restrict__ w2d,
           const float* __restrict__ w2v) {
    __shared__ float tw[32][64];
    __shared__ float tv[32][64];
    __shared__ float wd[64][64];
    __shared__ float wv[64][64];
    int rowBase = blockIdx.x * 32;
    int colBase = blockIdx.y * 64;
    int tid = threadIdx.x;

    for (int l = tid; l < 32 * 64; l += 256) {
        int rr = l / 64, d = l % 64;
        tw[rr][d] = g_tmpw[(rowBase + rr) * 64 + d];
        tv[rr][d] = g_tmpv[(rowBase + rr) * 64 + d];
    }
    for (int l = tid; l < 64 * 64; l += 256) {
        int d = l / 64, cc = l % 64;
        wd[d][cc] = w2d[d * Cc + colBase + cc];
        wv[d][cc] = w2v[d * Cc + colBase + cc];
    }
    __syncthreads();

    int cc = tid % 64;
    int r0 = tid / 64;
    float td = tdec[colBase + cc];
    for (int rr = r0; rr < 32; rr += 4) {
        float sd = td, sv = 0.f;
#pragma unroll 16
        for (int d = 0; d < 64; d++) {
            sd = fmaf(tw[rr][d], wd[d][cc], sd);
            sv = fmaf(tv[rr][d], wv[d][cc], sv);
        }
        int idx = (rowBase + rr) * Cc + colBase + cc;
        g_decay[idx] = expf(-expf(sd));
        g_v2[idx] += sv;
    }
}

// ---------------- S: WKV scan, 256 threads, 4 lanes/column ------------------
#define CHUNK 8
__device__ __forceinline__ void cpasync16(unsigned int daddr, const void* gp) {
    asm volatile("cp.async.ca.shared.global [%0], [%1], 16;"
                 :: "r"(daddr), "l"(gp));
}
__global__ __launch_bounds__(256)
void k_scan(const float* __restrict__ wkv_in,
            float* __restrict__ wkv_out) {
    const int h = blockIdx.x, b = blockIdx.y;
    const int tid  = threadIdx.x;
    const int lane = tid & 31;
    const int wid  = tid >> 5;
    const int jj   = wid * 8 + (lane >> 2);
    const int q    = lane & 3;

    __shared__ float sbuf[2][4][CHUNK][64];
    const unsigned int sb = (unsigned int)__cvta_generic_to_shared(&sbuf[0][0][0][0]);

    float state[16];
#pragma unroll
    for (int i = 0; i < 16; i++)
        state[i] = wkv_in[(size_t)((b * Hh + h) * Nn + q * 16 + i) * Nn + jj];

    const float* srcs[4] = { g_r, g_k, g_decay, g_v };
    const size_t rowOff = (size_t)h * Nn;

    auto issue = [&](int buf, int t0) {
#pragma unroll
        for (int p = 0; p < 2; p++) {
            int l   = tid + 256 * p;
            int arr = l >> 7;
            int rem = l & 127;
            int t   = rem >> 4;
            int seg = rem & 15;
            const float* gp = srcs[arr] +
                (size_t)(b * Tt + t0 + t) * Cc + rowOff + seg * 4;
            unsigned int da = sb +
                (unsigned int)((((buf * 4 + arr) * CHUNK + t) * 64) + seg * 4) * 4;
            cpasync16(da, gp);
        }
        asm volatile("cp.async.commit_group;");
    };

    issue(0, 0);
    asm volatile("cp.async.wait_group 0;" ::: "memory");
    __syncthreads();

    const int nch = Tt / CHUNK;
    for (int ch = 0; ch < nch; ch++) {
        const int cur = ch & 1;
        if (ch + 1 < nch) issue(cur ^ 1, (ch + 1) * CHUNK);

        const int t0 = ch * CHUNK;
#pragma unroll
        for (int tt = 0; tt < CHUNK; tt++) {
            const float4* rs4 = (const float4*)&sbuf[cur][0][tt][q * 16];
            const float4* ks4 = (const float4*)&sbuf[cur][1][tt][q * 16];
            const float4* ds4 = (const float4*)&sbuf[cur][2][tt][q * 16];
            const float vj = sbuf[cur][3][tt][jj];

            float y = 0.f;
#pragma unroll
            for (int i4 = 0; i4 < 4; i4++) {
                float4 r4 = rs4[i4], k4 = ks4[i4], d4 = ds4[i4];
                float kx, kv;
                float s0 = state[4*i4+0], s1 = state[4*i4+1];
                float s2 = state[4*i4+2], s3 = state[4*i4+3];
                y = fmaf(r4.x, s0, y);
                kx = fmaf(-k4.x, d4.x, k4.x); kv = kx * vj;
                state[4*i4+0] = fmaf(s0, d4.x, kv);
                y = fmaf(r4.y, s1, y);
                kx = fmaf(-k4.y, d4.y, k4.y); kv = kx * vj;
                state[4*i4+1] = fmaf(s1, d4.y, kv);
                y = fmaf(r4.z, s2, y);
                kx = fmaf(-k4.z, d4.z, k4.z); kv = kx * vj;
                state[4*i4+2] = fmaf(s2, d4.z, kv);
                y = fmaf(r4.w, s3, y);
                kx = fmaf(-k4.w, d4.w, k4.w); kv = kx * vj;
                state[4*i4+3] = fmaf(s3, d4.w, kv);
            }
            y += __shfl_xor_sync(0xffffffffu, y, 1);
            y += __shfl_xor_sync(0xffffffffu, y, 2);
            if (q == 0)
                g_ys[(size_t)(b * Tt + t0 + tt) * Cc + rowOff + jj] = y;
        }

        asm volatile("cp.async.wait_group 0;" ::: "memory");
        __syncthreads();
    }

#pragma unroll
    for (int i = 0; i < 16; i++)
        wkv_out[(size_t)((b * Hh + h) * Nn + q * 16 + i) * Nn + jj] = state[i];
}

// ---------------- E5: y = LN(ys + v2) -> bf16 planes -------------------------
__global__ void k_ln(const float* __restrict__ lnw,
                     const float* __restrict__ lnb) {
    int row = blockIdx.x;
    int tid = threadIdx.x;
    const float* a  = g_ys + (size_t)row * Cc;
    const float* bp = g_v2 + (size_t)row * Cc;
    float s = 0.f, ss = 0.f;
    for (int c = tid; c < Cc; c += 256) {
        float v = a[c] + bp[c];
        s += v; ss += v * v;
    }
    __shared__ float sh1[256], sh2[256];
    sh1[tid] = s; sh2[tid] = ss;
    __syncthreads();
    for (int st = 128; st > 0; st >>= 1) {
        if (tid < st) { sh1[tid] += sh1[tid + st]; sh2[tid] += sh2[tid + st]; }
        __syncthreads();
    }
    float mu  = sh1[0] / Cc;
    float var = sh2[0] / Cc - mu * mu;
    float rstd = rsqrtf(var + 1e-5f);
    for (int c = tid; c < Cc; c += 256) {
        float v = a[c] + bp[c];
        float res = (v - mu) * rstd * lnw[c] + lnb[c];
        __nv_bfloat16 h, l;
        split2(res, h, l);
        size_t idx = (size_t)row * Cc + c;
        g_pyn[idx] = h; g_pyn[BIGN + idx] = l;
    }
}

// ---------------- E6: shift_state_out ---------------------------------------
__global__ void k_copyshift(const float* __restrict__ x, float* __restrict__ out) {
    int i = blockIdx.x * 256 + threadIdx.x;
    if (i >= Bb * Cc) return;
    int b = i / Cc, c = i % Cc;
    out[i] = x[(size_t)(b * Tt + Tt - 1) * Cc + c];
}

// ---------------- launcher ---------------------------------------------------
extern "C" void kernel_launch(void* const* d_in, const int* in_sizes, int n_in,
                              void* d_out, int out_size) {
    const float* x        = (const float*)d_in[0];
    const float* shift_in = (const float*)d_in[1];
    const float* wkv_in   = (const float*)d_in[2];
    const float* maa_x    = (const float*)d_in[3];
    const float* maa_r    = (const float*)d_in[4];
    const float* maa_k    = (const float*)d_in[5];
    const float* maa_v    = (const float*)d_in[6];
    const float* maa_w    = (const float*)d_in[7];
    const float* maa_v2   = (const float*)d_in[8];
    const float* maa_w1   = (const float*)d_in[9];
    const float* maa_w2   = (const float*)d_in[10];
    const float* tdecay   = (const float*)d_in[11];
    const float* dec_w1   = (const float*)d_in[12];
    const float* dec_w2   = (const float*)d_in[13];
    const float* v2_w1    = (const float*)d_in[14];
    const float* v2_w2    = (const float*)d_in[15];
    const float* W_r      = (const float*)d_in[16];
    const float* W_k      = (const float*)d_in[17];
    const float* W_v      = (const float*)d_in[18];
    const float* W_o      = (const float*)d_in[19];
    const float* ln_w     = (const float*)d_in[20];
    const float* ln_b     = (const float*)d_in[21];

    float* out_y     = (float*)d_out;
    float* out_shift = out_y + (size_t)BT * Cc;
    float* out_wkv   = out_shift + (size_t)Bb * Cc;

    float *rb = 0, *kb = 0, *vb = 0, *v2b = 0;
    float *hpre = 0, *tmpw = 0, *tmpv = 0;
    __nv_bfloat16 *pxxx = 0, *pxr = 0, *pxk = 0, *pxv = 0, *pxw = 0, *pxv2 = 0, *pyn = 0;
    __nv_bfloat16 *pWr = 0, *pWk = 0, *pWv = 0, *pWo = 0;
    __nv_bfloat16 *pW1 = 0, *pWd = 0, *pWe = 0;
    cudaGetSymbolAddress((void**)&rb,    g_r);
    cudaGetSymbolAddress((void**)&kb,    g_k);
    cudaGetSymbolAddress((void**)&vb,    g_v);
    cudaGetSymbolAddress((void**)&v2b,   g_v2);
    cudaGetSymbolAddress((void**)&hpre,  g_hpre);
    cudaGetSymbolAddress((void**)&tmpw,  g_tmpw);
    cudaGetSymbolAddress((void**)&tmpv,  g_tmpv);
    cudaGetSymbolAddress((void**)&pxxx,  g_pxxx);
    cudaGetSymbolAddress((void**)&pxr,   g_pxr);
    cudaGetSymbolAddress((void**)&pxk,   g_pxk);
    cudaGetSymbolAddress((void**)&pxv,   g_pxv);
    cudaGetSymbolAddress((void**)&pxw,   g_pxw);
    cudaGetSymbolAddress((void**)&pxv2,  g_pxv2);
    cudaGetSymbolAddress((void**)&pyn,   g_pyn);
    cudaGetSymbolAddress((void**)&pWr,   g_pWr);
    cudaGetSymbolAddress((void**)&pWk,   g_pWk);
    cudaGetSymbolAddress((void**)&pWv,   g_pWv);
    cudaGetSymbolAddress((void**)&pWo,   g_pWo);
    cudaGetSymbolAddress((void**)&pW1,   g_pW1);
    cudaGetSymbolAddress((void**)&pWd,   g_pWd);
    cudaGetSymbolAddress((void**)&pWe,   g_pWe);

    cudaFuncSetAttribute(k_gemm3,
                         cudaFuncAttributeMaxDynamicSharedMemorySize,
                         NSTAGE * STG_BYTES);

    const dim3 gemmGrid(Cc / 128, BT / 128, 1);
    const int  gemmSmem = NSTAGE * STG_BYTES;

    // weight conversions
    k_conv<<<WN / 256, 256>>>(W_r, pWr, WN);
    k_conv<<<WN / 256, 256>>>(W_k, pWk, WN);
    k_conv<<<WN / 256, 256>>>(W_v, pWv, WN);
    k_conv<<<WN / 256, 256>>>(W_o, pWo, WN);
    k_conv<<<(Cc * 160) / 256, 256>>>(maa_w1, pW1, Cc * 160);
    k_conv<<<(Cc * 64) / 256, 256>>>(dec_w1, pWd, Cc * 64);
    k_conv<<<(Cc * 64) / 256, 256>>>(v2_w1, pWe, Cc * 64);

    // E1: token shift -> xxx planes
    k_shift<<<BIGN / 256, 256>>>(x, shift_in, maa_x);

    // G1: hpre = tanh(xxx @ maa_w1)  [8192,160]
    k_gemm3<<<dim3(2, BT / 128, 1), 256, gemmSmem>>>(
        pxxx, pW1, hpre, pxxx, pW1, hpre,
        (size_t)BIGN, (size_t)Cc * 160, BT, 160, Cc, 160, 1);

    // E2: 5-way mix -> planes
    k_mix<<<dim3(BT / 32, Cc / 32), 256>>>(x, shift_in, maa_w2,
                                           maa_r, maa_k, maa_v, maa_w, maa_v2);

    // Big GEMMs (bf16x3, A+B via cp.async planes)
    k_gemm3<<<gemmGrid, 256, gemmSmem>>>(pxr,  pWr, rb,  pxr,  pWr, rb,
                                         (size_t)BIGN, (size_t)WN, BT, Cc, Cc, Cc, 0);
    k_gemm3<<<gemmGrid, 256, gemmSmem>>>(pxk,  pWk, kb,  pxk,  pWk, kb,
                                         (size_t)BIGN, (size_t)WN, BT, Cc, Cc, Cc, 0);
    k_gemm3<<<gemmGrid, 256, gemmSmem>>>(pxv,  pWv, vb,  pxv,  pWv, vb,
                                         (size_t)BIGN, (size_t)WN, BT, Cc, Cc, Cc, 0);
    k_gemm3<<<gemmGrid, 256, gemmSmem>>>(pxv2, pWv, v2b, pxv2, pWv, v2b,
                                         (size_t)BIGN, (size_t)WN, BT, Cc, Cc, Cc, 0);

    // Small LoRA GEMMs (dual problem via gridDim.z=2, fused tanh)
    k_gemm3<<<dim3(1, BT / 128, 2), 256, gemmSmem>>>(
        pxw, pWd, tmpw, pxv2, pWe, tmpv,
        (size_t)BIGN, (size_t)Cc * 64, BT, 64, Cc, 64, 1);

    // E3+E4 fused epilogues
    k_epi<<<dim3(BT / 32, Cc / 64), 256>>>(tdecay, dec_w2, v2_w2);

    // WKV scan (k * (1-decay) fused)
    k_scan<<<dim3(Hh, Bb), 256>>>(wkv_in, out_wkv);

    // LayerNorm(ys + v2) -> planes
    k_ln<<<BT, 256>>>(ln_w, ln_b);

    // Output GEMM: y = ynorm @ W_o
    k_gemm3<<<gemmGrid, 256, gemmSmem>>>(pyn, pWo, out_y, pyn, pWo, out_y,
                                         (size_t)BIGN, (size_t)WN, BT, Cc, Cc, Cc, 0);

    // shift state out
    k_copyshift<<<(Bb * Cc + 255) / 256, 256>>>(x, out_shift);
}

// round 10
// speedup vs baseline: 1.4267x; 1.0274x over previous
#include <cuda_runtime.h>
#include <cuda_bf16.h>
#include <cstdint>
#include <math.h>

// Problem constants
#define Bb   4
#define Tt   2048
#define Cc   2048
#define Hh   32
#define Nn   64
#define BT   (Bb*Tt)          // 8192
#define DMIX 32
#define DDEC 64
#define BIGN (BT*Cc)          // 16,777,216
#define WN   (Cc*Cc)          // 4,194,304

// ---------------- scratch (device globals; no runtime allocation) ----------
__device__ float g_r    [BIGN];
__device__ float g_k    [BIGN];
__device__ float g_v    [BIGN];
__device__ float g_v2   [BIGN];
__device__ float g_decay[BIGN];
__device__ float g_ys   [BIGN];
__device__ float g_hpre [BT*160];
__device__ float g_tmpw [BT*DDEC];
__device__ float g_tmpv [BT*DDEC];

// bf16 hi/lo planes (activations): [0..BIGN) hi, [BIGN..2*BIGN) lo
__device__ __nv_bfloat16 g_pxxx[2*BIGN];
__device__ __nv_bfloat16 g_pxr [2*BIGN];
__device__ __nv_bfloat16 g_pxk [2*BIGN];
__device__ __nv_bfloat16 g_pxv [2*BIGN];
__device__ __nv_bfloat16 g_pxw [2*BIGN];
__device__ __nv_bfloat16 g_pxv2[2*BIGN];
__device__ __nv_bfloat16 g_pyn [2*BIGN];
// weight planes
__device__ __nv_bfloat16 g_pWr[2*WN];
__device__ __nv_bfloat16 g_pWk[2*WN];
__device__ __nv_bfloat16 g_pWv[2*WN];
__device__ __nv_bfloat16 g_pWo[2*WN];
__device__ __nv_bfloat16 g_pW1[2*Cc*160];
__device__ __nv_bfloat16 g_pWd[2*Cc*64];
__device__ __nv_bfloat16 g_pWe[2*Cc*64];

__device__ __forceinline__ void split2(float f, __nv_bfloat16& h, __nv_bfloat16& l) {
    h = __float2bfloat16_rn(f);
    l = __float2bfloat16_rn(f - __bfloat162float(h));
}

// ---------------- E1: token shift -> xxx planes -----------------------------
__global__ void k_shift(const float* __restrict__ x,
                        const float* __restrict__ shift,
                        const float* __restrict__ maa_x) {
    int idx = blockIdx.x * 256 + threadIdx.x;
    if (idx >= BIGN) return;
    int c  = idx % Cc;
    int bt = idx / Cc;
    int t  = bt % Tt;
    int b  = bt / Tt;
    float xv   = x[idx];
    float prev = (t == 0) ? shift[b * Cc + c] : x[idx - Cc];
    float r    = xv + (prev - xv) * maa_x[c];
    __nv_bfloat16 h, l;
    split2(r, h, l);
    g_pxxx[idx] = h; g_pxxx[BIGN + idx] = l;
}

// ---------------- weight fp32 -> bf16 hi/lo planes --------------------------
__global__ void k_conv(const float* __restrict__ src,
                       __nv_bfloat16* __restrict__ dst, int n) {
    int i = blockIdx.x * 256 + threadIdx.x;
    if (i >= n) return;
    __nv_bfloat16 h, l;
    split2(src[i], h, l);
    dst[i]     = h;
    dst[n + i] = l;
}

// =============================================================================
// Tensor-core GEMM v4 (bf16x3, fp32 accumulate):
//   A/B bf16 hi/lo planes via cp.async. Tile 128x128, BK=32.
//   3-stage ring, 2 CTAs/SM (16 warps/SM) to hide latency.
// =============================================================================
#define ASTR 40
#define BSTR 136
#define SA_H 0
#define SA_L 5120
#define SB_H 10240
#define SB_L 14592
#define STG  18944
#define STG_BYTES (STG*2)
#define NSTAGE 3

__device__ __forceinline__ void ldsm4(unsigned int* r, unsigned int addr) {
    asm volatile("ldmatrix.sync.aligned.m8n8.x4.shared.b16 {%0,%1,%2,%3},[%4];"
                 : "=r"(r[0]), "=r"(r[1]), "=r"(r[2]), "=r"(r[3]) : "r"(addr));
}
__device__ __forceinline__ void ldsm4t(unsigned int* r, unsigned int addr) {
    asm volatile("ldmatrix.sync.aligned.m8n8.x4.trans.shared.b16 {%0,%1,%2,%3},[%4];"
                 : "=r"(r[0]), "=r"(r[1]), "=r"(r[2]), "=r"(r[3]) : "r"(addr));
}
__device__ __forceinline__ void mma16816(float* c, const unsigned int* a,
                                         unsigned int b0, unsigned int b1) {
    asm volatile("mma.sync.aligned.m16n8k16.row.col.f32.bf16.bf16.f32 "
                 "{%0,%1,%2,%3},{%4,%5,%6,%7},{%8,%9},{%0,%1,%2,%3};"
                 : "+f"(c[0]), "+f"(c[1]), "+f"(c[2]), "+f"(c[3])
                 : "r"(a[0]), "r"(a[1]), "r"(a[2]), "r"(a[3]), "r"(b0), "r"(b1));
}
__device__ __forceinline__ void cpasync16z(unsigned int daddr, const void* gp, int sz) {
    asm volatile("cp.async.ca.shared.global [%0], [%1], 16, %2;"
                 :: "r"(daddr), "l"(gp), "r"(sz));
}

__global__ __launch_bounds__(256, 2)
void k_gemm4(const __nv_bfloat16* __restrict__ A1,
             const __nv_bfloat16* __restrict__ B1,
             float* __restrict__ C1,
             const __nv_bfloat16* __restrict__ A2,
             const __nv_bfloat16* __restrict__ B2,
             float* __restrict__ C2,
             size_t aPlane, size_t bPlane,
             int M, int N, int K, int ldc, int act) {
    const __nv_bfloat16* A = (blockIdx.z == 0) ? A1 : A2;
    const __nv_bfloat16* B = (blockIdx.z == 0) ? B1 : B2;
    float* C               = (blockIdx.z == 0) ? C1 : C2;

    extern __shared__ __nv_bfloat16 smbuf[];
    const int tid  = threadIdx.x;
    const int lane = tid & 31;
    const int wid  = tid >> 5;
    const int wm   = wid >> 2;
    const int wn   = wid & 3;
    const int mBase = blockIdx.y * 128;
    const int nBase = blockIdx.x * 128;

    const unsigned int smB = (unsigned int)__cvta_generic_to_shared(smbuf);

    const __nv_bfloat16* Ah = A;
    const __nv_bfloat16* Al = A + aPlane;
    const __nv_bfloat16* Bh = B;
    const __nv_bfloat16* Bl = B + bPlane;

    const int kChunks = K >> 5;

    // 8 x 16B cp.async per thread per stage
    auto issue = [&](int ch) {
        if (ch < kChunks) {
            const unsigned int base = smB + (unsigned int)(ch % NSTAGE) * STG_BYTES;
#pragma unroll
            for (int q2 = 0; q2 < 4; q2++) {   // A chunks
                int idx = tid + 256 * q2;
                int pl  = idx >> 9;
                int rem = idx & 511;
                int row = rem >> 2;
                int seg = rem & 3;
                const __nv_bfloat16* gp = (pl ? Al : Ah) +
                    (size_t)(mBase + row) * K + ch * 32 + seg * 8;
                unsigned int da = base +
                    (unsigned int)((pl ? SA_L : SA_H) + row * ASTR + seg * 8) * 2;
                cpasync16z(da, gp, 16);
            }
#pragma unroll
            for (int q2 = 0; q2 < 4; q2++) {   // B chunks
                int idx = tid + 256 * q2;
                int pl  = idx >> 9;
                int rem = idx & 511;
                int row = rem >> 4;
                int seg = rem & 15;
                int gcol = nBase + seg * 8;
                int ok = gcol < N;
                const __nv_bfloat16* gp = (pl ? Bl : Bh) +
                    (ok ? ((size_t)(ch * 32 + row) * N + gcol) : (size_t)0);
                unsigned int da = base +
                    (unsigned int)((pl ? SB_L : SB_H) + row * BSTR + seg * 8) * 2;
                cpasync16z(da, gp, ok ? 16 : 0);
            }
        }
        asm volatile("cp.async.commit_group;");
    };

    float acc[4][4][4];
#pragma unroll
    for (int i = 0; i < 4; i++)
#pragma unroll
        for (int j = 0; j < 4; j++)
#pragma unroll
            for (int q = 0; q < 4; q++) acc[i][j][q] = 0.f;

    // prologue: 2 stages in flight
    issue(0); issue(1);

#pragma unroll 1
    for (int ch = 0; ch < kChunks; ch++) {
        asm volatile("cp.async.wait_group 1;" ::: "memory");
        __syncthreads();
        issue(ch + 2);   // stage (ch+2)%3 == (ch-1)%3, free after the sync above

        const unsigned int sb = smB + (unsigned int)(ch % NSTAGE) * STG_BYTES;
#pragma unroll
        for (int ks = 0; ks < 2; ks++) {
            const int k0 = ks * 16;
            unsigned int ah[4][4], al[4][4], bh[2][4], bl[2][4];
#pragma unroll
            for (int mf = 0; mf < 4; mf++) {
                int row = wm * 64 + mf * 16 + (lane & 15);
                int col = k0 + (lane >> 4) * 8;
                unsigned int ad = sb + (unsigned int)(row * ASTR + col) * 2;
                ldsm4(ah[mf], ad + SA_H * 2);
                ldsm4(al[mf], ad + SA_L * 2);
            }
#pragma unroll
            for (int nf2 = 0; nf2 < 2; nf2++) {
                int rowk = k0 + (lane & 15);
                int coln = wn * 32 + nf2 * 16 + (lane >> 4) * 8;
                unsigned int bd = sb + (unsigned int)(rowk * BSTR + coln) * 2;
                ldsm4t(bh[nf2], bd + SB_H * 2);
                ldsm4t(bl[nf2], bd + SB_L * 2);
            }
#pragma unroll
            for (int mf = 0; mf < 4; mf++) {
#pragma unroll
                for (int nf = 0; nf < 4; nf++) {
                    unsigned int b0h = bh[nf >> 1][(nf & 1) * 2];
                    unsigned int b1h = bh[nf >> 1][(nf & 1) * 2 + 1];
                    unsigned int b0l = bl[nf >> 1][(nf & 1) * 2];
                    unsigned int b1l = bl[nf >> 1][(nf & 1) * 2 + 1];
                    mma16816(acc[mf][nf], ah[mf], b0h, b1h);
                    mma16816(acc[mf][nf], ah[mf], b0l, b1l);
                    mma16816(acc[mf][nf], al[mf], b0h, b1h);
                }
            }
        }
    }

    // epilogue
#pragma unroll
    for (int mf = 0; mf < 4; mf++) {
#pragma unroll
        for (int nf = 0; nf < 4; nf++) {
            int r = mBase + wm * 64 + mf * 16 + (lane >> 2);
            int c = nBase + wn * 32 + nf * 8 + (lane & 3) * 2;
            if (c < N) {
                float a0 = acc[mf][nf][0], a1 = acc[mf][nf][1];
                float a2 = acc[mf][nf][2], a3 = acc[mf][nf][3];
                if (act == 1) {
                    a0 = tanhf(a0); a1 = tanhf(a1);
                    a2 = tanhf(a2); a3 = tanhf(a3);
                }
                *(float2*)&C[(size_t)r * ldc + c] = make_float2(a0, a1);
                *(float2*)&C[(size_t)(r + 8) * ldc + c] = make_float2(a2, a3);
            }
        }
    }
}

// ---------------- E2: 5-way LoRA mix -> bf16 planes -------------------------
__global__ __launch_bounds__(256, 3)
void k_mix(const float* __restrict__ x,
           const float* __restrict__ shift,
           const float* __restrict__ w2,
           const float* __restrict__ mr, const float* __restrict__ mk,
           const float* __restrict__ mv, const float* __restrict__ mw,
           const float* __restrict__ mv2) {
    __shared__ float hs[32][160];
    __shared__ float ws[160][32];
    int rowBase = blockIdx.x * 32;
    int colBase = blockIdx.y * 32;
    int tid = threadIdx.x;

    for (int l = tid; l < 32 * 160; l += 256) {
        int rr = l / 160, d = l % 160;
        hs[rr][d] = g_hpre[(rowBase + rr) * 160 + d];
    }
    for (int l = tid; l < 160 * 32; l += 256) {
        int fd = l / 32, cc = l % 32;
        ws[fd][cc] = w2[fd * Cc + colBase + cc];
    }
    __syncthreads();

    int cc = tid % 32;
    int r0 = tid / 32;
    int c  = colBase + cc;
    float tr = mr[c], tk = mk[c], tv = mv[c], tw = mw[c], tv2 = mv2[c];

    for (int rr = r0; rr < 32; rr += 8) {
        float m0 = 0, m1 = 0, m2 = 0, m3 = 0, m4 = 0;
#pragma unroll 8
        for (int d = 0; d < 32; d++) {
            m0 = fmaf(hs[rr][d],       ws[d][cc],       m0);
            m1 = fmaf(hs[rr][32 + d],  ws[32 + d][cc],  m1);
            m2 = fmaf(hs[rr][64 + d],  ws[64 + d][cc],  m2);
            m3 = fmaf(hs[rr][96 + d],  ws[96 + d][cc],  m3);
            m4 = fmaf(hs[rr][128 + d], ws[128 + d][cc], m4);
        }
        int bt  = rowBase + rr;
        int t   = bt % Tt;
        int b   = bt / Tt;
        int idx = bt * Cc + c;
        float xval = x[idx];
        float prev = (t == 0) ? shift[b * Cc + c] : x[idx - Cc];
        float dx   = prev - xval;
        float vr  = xval + dx * (tr  + m0);
        float vk  = xval + dx * (tk  + m1);
        float vv  = xval + dx * (tv  + m2);
        float vw  = xval + dx * (tw  + m3);
        float vv2 = xval + dx * (tv2 + m4);
        __nv_bfloat16 h, l;
        split2(vr,  h, l); g_pxr [idx] = h; g_pxr [BIGN + idx] = l;
        split2(vk,  h, l); g_pxk [idx] = h; g_pxk [BIGN + idx] = l;
        split2(vv,  h, l); g_pxv [idx] = h; g_pxv [BIGN + idx] = l;
        split2(vw,  h, l); g_pxw [idx] = h; g_pxw [BIGN + idx] = l;
        split2(vv2, h, l); g_pxv2[idx] = h; g_pxv2[BIGN + idx] = l;
    }
}

// ---------------- E3+E4 fused: decay & v2 epilogues -------------------------
__global__ __launch_bounds__(256)
void k_epi(const float* __restrict__ tdec,
           const float* __restrict__ w2d,
           const float* __restrict__ w2v) {
    __shared__ float tw[32][64];
    __shared__ float tv[32][64];
    __shared__ float wd[64][64];
    __shared__ float wv[64][64];
    int rowBase = blockIdx.x * 32;
    int colBase = blockIdx.y * 64;
    int tid = threadIdx.x;

    for (int l = tid; l < 32 * 64; l += 256) {
        int rr = l / 64, d = l % 64;
        tw[rr][d] = g_tmpw[(rowBase + rr) * 64 + d];
        tv[rr][d] = g_tmpv[(rowBase + rr) * 64 + d];
    }
    for (int l = tid; l < 64 * 64; l += 256) {
        int d = l / 64, cc = l % 64;
        wd[d][cc] = w2d[d * Cc + colBase + cc];
        wv[d][cc] = w2v[d * Cc + colBase + cc];
    }
    __syncthreads();

    int cc = tid % 64;
    int r0 = tid / 64;
    float td = tdec[colBase + cc];
    for (int rr = r0; rr < 32; rr += 4) {
        float sd = td, sv = 0.f;
#pragma unroll 16
        for (int d = 0; d < 64; d++) {
            sd = fmaf(tw[rr][d], wd[d][cc], sd);
            sv = fmaf(tv[rr][d], wv[d][cc], sv);
        }
        int idx = (rowBase + rr) * Cc + colBase + cc;
        g_decay[idx] = expf(-expf(sd));
        g_v2[idx] += sv;
    }
}

// ---------------- S: WKV scan, 256 threads, 4 lanes/column ------------------
#define CHUNK 8
__device__ __forceinline__ void cpasync16(unsigned int daddr, const void* gp) {
    asm volatile("cp.async.ca.shared.global [%0], [%1], 16;"
                 :: "r"(daddr), "l"(gp));
}
__global__ __launch_bounds__(256)
void k_scan(const float* __restrict__ wkv_in,
            float* __restrict__ wkv_out) {
    const int h = blockIdx.x, b = blockIdx.y;
    const int tid  = threadIdx.x;
    const int lane = tid & 31;
    const int wid  = tid >> 5;
    const int jj   = wid * 8 + (lane >> 2);
    const int q    = lane & 3;

    __shared__ float sbuf[2][4][CHUNK][64];
    const unsigned int sb = (unsigned int)__cvta_generic_to_shared(&sbuf[0][0][0][0]);

    float state[16];
#pragma unroll
    for (int i = 0; i < 16; i++)
        state[i] = wkv_in[(size_t)((b * Hh + h) * Nn + q * 16 + i) * Nn + jj];

    const float* srcs[4] = { g_r, g_k, g_decay, g_v };
    const size_t rowOff = (size_t)h * Nn;

    auto issue = [&](int buf, int t0) {
#pragma unroll
        for (int p = 0; p < 2; p++) {
            int l   = tid + 256 * p;
            int arr = l >> 7;
            int rem = l & 127;
            int t   = rem >> 4;
            int seg = rem & 15;
            const float* gp = srcs[arr] +
                (size_t)(b * Tt + t0 + t) * Cc + rowOff + seg * 4;
            unsigned int da = sb +
                (unsigned int)((((buf * 4 + arr) * CHUNK + t) * 64) + seg * 4) * 4;
            cpasync16(da, gp);
        }
        asm volatile("cp.async.commit_group;");
    };

    issue(0, 0);
    asm volatile("cp.async.wait_group 0;" ::: "memory");
    __syncthreads();

    const int nch = Tt / CHUNK;
    for (int ch = 0; ch < nch; ch++) {
        const int cur = ch & 1;
        if (ch + 1 < nch) issue(cur ^ 1, (ch + 1) * CHUNK);

        const int t0 = ch * CHUNK;
#pragma unroll
        for (int tt = 0; tt < CHUNK; tt++) {
            const float4* rs4 = (const float4*)&sbuf[cur][0][tt][q * 16];
            const float4* ks4 = (const float4*)&sbuf[cur][1][tt][q * 16];
            const float4* ds4 = (const float4*)&sbuf[cur][2][tt][q * 16];
            const float vj = sbuf[cur][3][tt][jj];

            float y = 0.f;
#pragma unroll
            for (int i4 = 0; i4 < 4; i4++) {
                float4 r4 = rs4[i4], k4 = ks4[i4], d4 = ds4[i4];
                float kx, kv;
                float s0 = state[4*i4+0], s1 = state[4*i4+1];
                float s2 = state[4*i4+2], s3 = state[4*i4+3];
                y = fmaf(r4.x, s0, y);
                kx = fmaf(-k4.x, d4.x, k4.x); kv = kx * vj;
                state[4*i4+0] = fmaf(s0, d4.x, kv);
                y = fmaf(r4.y, s1, y);
                kx = fmaf(-k4.y, d4.y, k4.y); kv = kx * vj;
                state[4*i4+1] = fmaf(s1, d4.y, kv);
                y = fmaf(r4.z, s2, y);
                kx = fmaf(-k4.z, d4.z, k4.z); kv = kx * vj;
                state[4*i4+2] = fmaf(s2, d4.z, kv);
                y = fmaf(r4.w, s3, y);
                kx = fmaf(-k4.w, d4.w, k4.w); kv = kx * vj;
                state[4*i4+3] = fmaf(s3, d4.w, kv);
            }
            y += __shfl_xor_sync(0xffffffffu, y, 1);
            y += __shfl_xor_sync(0xffffffffu, y, 2);
            if (q == 0)
                g_ys[(size_t)(b * Tt + t0 + tt) * Cc + rowOff + jj] = y;
        }

        asm volatile("cp.async.wait_group 0;" ::: "memory");
        __syncthreads();
    }

#pragma unroll
    for (int i = 0; i < 16; i++)
        wkv_out[(size_t)((b * Hh + h) * Nn + q * 16 + i) * Nn + jj] = state[i];
}

// ---------------- E5: y = LN(ys + v2) -> bf16 planes -------------------------
__global__ void k_ln(const float* __restrict__ lnw,
                     const float* __restrict__ lnb) {
    int row = blockIdx.x;
    int tid = threadIdx.x;
    const float* a  = g_ys + (size_t)row * Cc;
    const float* bp = g_v2 + (size_t)row * Cc;
    float s = 0.f, ss = 0.f;
    for (int c = tid; c < Cc; c += 256) {
        float v = a[c] + bp[c];
        s += v; ss += v * v;
    }
    __shared__ float sh1[256], sh2[256];
    sh1[tid] = s; sh2[tid] = ss;
    __syncthreads();
    for (int st = 128; st > 0; st >>= 1) {
        if (tid < st) { sh1[tid] += sh1[tid + st]; sh2[tid] += sh2[tid + st]; }
        __syncthreads();
    }
    float mu  = sh1[0] / Cc;
    float var = sh2[0] / Cc - mu * mu;
    float rstd = rsqrtf(var + 1e-5f);
    for (int c = tid; c < Cc; c += 256) {
        float v = a[c] + bp[c];
        float res = (v - mu) * rstd * lnw[c] + lnb[c];
        __nv_bfloat16 h, l;
        split2(res, h, l);
        size_t idx = (size_t)row * Cc + c;
        g_pyn[idx] = h; g_pyn[BIGN + idx] = l;
    }
}

// ---------------- E6: shift_state_out ---------------------------------------
__global__ void k_copyshift(const float* __restrict__ x, float* __restrict__ out) {
    int i = blockIdx.x * 256 + threadIdx.x;
    if (i >= Bb * Cc) return;
    int b = i / Cc, c = i % Cc;
    out[i] = x[(size_t)(b * Tt + Tt - 1) * Cc + c];
}

// ---------------- launcher ---------------------------------------------------
extern "C" void kernel_launch(void* const* d_in, const int* in_sizes, int n_in,
                              void* d_out, int out_size) {
    const float* x        = (const float*)d_in[0];
    const float* shift_in = (const float*)d_in[1];
    const float* wkv_in   = (const float*)d_in[2];
    const float* maa_x    = (const float*)d_in[3];
    const float* maa_r    = (const float*)d_in[4];
    const float* maa_k    = (const float*)d_in[5];
    const float* maa_v    = (const float*)d_in[6];
    const float* maa_w    = (const float*)d_in[7];
    const float* maa_v2   = (const float*)d_in[8];
    const float* maa_w1   = (const float*)d_in[9];
    const float* maa_w2   = (const float*)d_in[10];
    const float* tdecay   = (const float*)d_in[11];
    const float* dec_w1   = (const float*)d_in[12];
    const float* dec_w2   = (const float*)d_in[13];
    const float* v2_w1    = (const float*)d_in[14];
    const float* v2_w2    = (const float*)d_in[15];
    const float* W_r      = (const float*)d_in[16];
    const float* W_k      = (const float*)d_in[17];
    const float* W_v      = (const float*)d_in[18];
    const float* W_o      = (const float*)d_in[19];
    const float* ln_w     = (const float*)d_in[20];
    const float* ln_b     = (const float*)d_in[21];

    float* out_y     = (float*)d_out;
    float* out_shift = out_y + (size_t)BT * Cc;
    float* out_wkv   = out_shift + (size_t)Bb * Cc;

    float *rb = 0, *kb = 0, *vb = 0, *v2b = 0;
    float *hpre = 0, *tmpw = 0, *tmpv = 0;
    __nv_bfloat16 *pxxx = 0, *pxr = 0, *pxk = 0, *pxv = 0, *pxw = 0, *pxv2 = 0, *pyn = 0;
    __nv_bfloat16 *pWr = 0, *pWk = 0, *pWv = 0, *pWo = 0;
    __nv_bfloat16 *pW1 = 0, *pWd = 0, *pWe = 0;
    cudaGetSymbolAddress((void**)&rb,    g_r);
    cudaGetSymbolAddress((void**)&kb,    g_k);
    cudaGetSymbolAddress((void**)&vb,    g_v);
    cudaGetSymbolAddress((void**)&v2b,   g_v2);
    cudaGetSymbolAddress((void**)&hpre,  g_hpre);
    cudaGetSymbolAddress((void**)&tmpw,  g_tmpw);
    cudaGetSymbolAddress((void**)&tmpv,  g_tmpv);
    cudaGetSymbolAddress((void**)&pxxx,  g_pxxx);
    cudaGetSymbolAddress((void**)&pxr,   g_pxr);
    cudaGetSymbolAddress((void**)&pxk,   g_pxk);
    cudaGetSymbolAddress((void**)&pxv,   g_pxv);
    cudaGetSymbolAddress((void**)&pxw,   g_pxw);
    cudaGetSymbolAddress((void**)&pxv2,  g_pxv2);
    cudaGetSymbolAddress((void**)&pyn,   g_pyn);
    cudaGetSymbolAddress((void**)&pWr,   g_pWr);
    cudaGetSymbolAddress((void**)&pWk,   g_pWk);
    cudaGetSymbolAddress((void**)&pWv,   g_pWv);
    cudaGetSymbolAddress((void**)&pWo,   g_pWo);
    cudaGetSymbolAddress((void**)&pW1,   g_pW1);
    cudaGetSymbolAddress((void**)&pWd,   g_pWd);
    cudaGetSymbolAddress((void**)&pWe,   g_pWe);

    cudaFuncSetAttribute(k_gemm4,
                         cudaFuncAttributeMaxDynamicSharedMemorySize,
                         NSTAGE * STG_BYTES);

    const dim3 gemmGrid(Cc / 128, BT / 128, 1);
    const int  gemmSmem = NSTAGE * STG_BYTES;

    // weight conversions
    k_conv<<<WN / 256, 256>>>(W_r, pWr, WN);
    k_conv<<<WN / 256, 256>>>(W_k, pWk, WN);
    k_conv<<<WN / 256, 256>>>(W_v, pWv, WN);
    k_conv<<<WN / 256, 256>>>(W_o, pWo, WN);
    k_conv<<<(Cc * 160) / 256, 256>>>(maa_w1, pW1, Cc * 160);
    k_conv<<<(Cc * 64) / 256, 256>>>(dec_w1, pWd, Cc * 64);
    k_conv<<<(Cc * 64) / 256, 256>>>(v2_w1, pWe, Cc * 64);

    // E1: token shift -> xxx planes
    k_shift<<<BIGN / 256, 256>>>(x, shift_in, maa_x);

    // G1: hpre = tanh(xxx @ maa_w1)  [8192,160]
    k_gemm4<<<dim3(2, BT / 128, 1), 256, gemmSmem>>>(
        pxxx, pW1, hpre, pxxx, pW1, hpre,
        (size_t)BIGN, (size_t)Cc * 160, BT, 160, Cc, 160, 1);

    // E2: 5-way mix -> planes
    k_mix<<<dim3(BT / 32, Cc / 32), 256>>>(x, shift_in, maa_w2,
                                           maa_r, maa_k, maa_v, maa_w, maa_v2);

    // Big GEMMs (bf16x3, A+B via cp.async planes, 2 CTAs/SM)
    k_gemm4<<<gemmGrid, 256, gemmSmem>>>(pxr,  pWr, rb,  pxr,  pWr, rb,
                                         (size_t)BIGN, (size_t)WN, BT, Cc, Cc, Cc, 0);
    k_gemm4<<<gemmGrid, 256, gemmSmem>>>(pxk,  pWk, kb,  pxk,  pWk, kb,
                                         (size_t)BIGN, (size_t)WN, BT, Cc, Cc, Cc, 0);
    k_gemm4<<<gemmGrid, 256, gemmSmem>>>(pxv,  pWv, vb,  pxv,  pWv, vb,
                                         (size_t)BIGN, (size_t)WN, BT, Cc, Cc, Cc, 0);
    k_gemm4<<<gemmGrid, 256, gemmSmem>>>(pxv2, pWv, v2b, pxv2, pWv, v2b,
                                         (size_t)BIGN, (size_t)WN, BT, Cc, Cc, Cc, 0);

    // Small LoRA GEMMs (dual problem via gridDim.z=2, fused tanh)
    k_gemm4<<<dim3(1, BT / 128, 2), 256, gemmSmem>>>(
        pxw, pWd, tmpw, pxv2, pWe, tmpv,
        (size_t)BIGN, (size_t)Cc * 64, BT, 64, Cc, 64, 1);

    // E3+E4 fused epilogues
    k_epi<<<dim3(BT / 32, Cc / 64), 256>>>(tdecay, dec_w2, v2_w2);

    // WKV scan (k * (1-decay) fused)
    k_scan<<<dim3(Hh, Bb), 256>>>(wkv_in, out_wkv);

    // LayerNorm(ys + v2) -> planes
    k_ln<<<BT, 256>>>(ln_w, ln_b);

    // Output GEMM: y = ynorm @ W_o
    k_gemm4<<<gemmGrid, 256, gemmSmem>>>(pyn, pWo, out_y, pyn, pWo, out_y,
                                         (size_t)BIGN, (size_t)WN, BT, Cc, Cc, Cc, 0);

    // shift state out
    k_copyshift<<<(Bb * Cc + 255) / 256, 256>>>(x, out_shift);
}

// round 12
// speedup vs baseline: 1.7730x; 1.2428x over previous
#include <cuda_runtime.h>
#include <cuda_fp16.h>
#include <cstdint>
#include <math.h>

// Problem constants
#define Bb   4
#define Tt   2048
#define Cc   2048
#define Hh   32
#define Nn   64
#define BT   (Bb*Tt)          // 8192
#define DDEC 64
#define BIGN (BT*Cc)          // 16,777,216
#define WN   (Cc*Cc)          // 4,194,304

// ---------------- scratch (device globals; no runtime allocation) ----------
__device__ float g_r    [BIGN];
__device__ float g_k    [BIGN];
__device__ float g_v    [BIGN];
__device__ float g_v2   [BIGN];
__device__ float g_decay[BIGN];
__device__ float g_ys   [BIGN];
__device__ float g_hpre [BT*160];
__device__ float g_tmpw [BT*DDEC];
__device__ float g_tmpv [BT*DDEC];

// fp16 hi/lo planes (activations, A operands): [0..BIGN) hi, [BIGN..2N) lo
__device__ __half g_pxxx[2*BIGN];
__device__ __half g_pxr [2*BIGN];
__device__ __half g_pxk [2*BIGN];
__device__ __half g_pxv [2*BIGN];
__device__ __half g_pxw [2*BIGN];
__device__ __half g_pxv2[2*BIGN];
__device__ __half g_pyn [2*BIGN];
// fp16 weight planes (B operands): hi only
__device__ __half g_pWr[WN];
__device__ __half g_pWk[WN];
__device__ __half g_pWv[WN];
__device__ __half g_pWo[WN];
__device__ __half g_pW1[Cc*160];
__device__ __half g_pWd[Cc*64];
__device__ __half g_pWe[Cc*64];

__device__ __forceinline__ void split2h(float f, __half& h, __half& l) {
    h = __float2half_rn(f);
    l = __float2half_rn(f - __half2float(h));
}

// ---------------- E1: token shift -> xxx planes -----------------------------
__global__ void k_shift(const float* __restrict__ x,
                        const float* __restrict__ shift,
                        const float* __restrict__ maa_x) {
    int idx = blockIdx.x * 256 + threadIdx.x;
    if (idx >= BIGN) return;
    int c  = idx % Cc;
    int bt = idx / Cc;
    int t  = bt % Tt;
    int b  = bt / Tt;
    float xv   = x[idx];
    float prev = (t == 0) ? shift[b * Cc + c] : x[idx - Cc];
    float r    = xv + (prev - xv) * maa_x[c];
    __half h, l;
    split2h(r, h, l);
    g_pxxx[idx] = h; g_pxxx[BIGN + idx] = l;
}

// ---------------- weight fp32 -> fp16 hi plane -------------------------------
__global__ void k_conv(const float* __restrict__ src,
                       __half* __restrict__ dst, int n) {
    int i = blockIdx.x * 256 + threadIdx.x;
    if (i >= n) return;
    dst[i] = __float2half_rn(src[i]);
}

// =============================================================================
// Tensor-core GEMM v5 (fp16x2: A hi/lo planes, B hi plane; fp32 accumulate):
//   C = act(A*B). M%128==0, K%32==0, N%8==0. Tile 128x128, BK=32.
//   3-stage cp.async ring, 2 CTAs/SM. 2 MMAs per k-step: ah*bh + al*bh.
//   gridDim.z==2 selects (A2,B2,C2) for z=1.
// =============================================================================
#define ASTR 40
#define BSTR 136
#define SA_H 0
#define SA_L 5120
#define SB_H 10240
#define STG  14592          // halfs per stage (10240 + 32*136)
#define STG_BYTES (STG*2)   // 29184
#define NSTAGE 3

__device__ __forceinline__ void ldsm4(unsigned int* r, unsigned int addr) {
    asm volatile("ldmatrix.sync.aligned.m8n8.x4.shared.b16 {%0,%1,%2,%3},[%4];"
                 : "=r"(r[0]), "=r"(r[1]), "=r"(r[2]), "=r"(r[3]) : "r"(addr));
}
__device__ __forceinline__ void ldsm4t(unsigned int* r, unsigned int addr) {
    asm volatile("ldmatrix.sync.aligned.m8n8.x4.trans.shared.b16 {%0,%1,%2,%3},[%4];"
                 : "=r"(r[0]), "=r"(r[1]), "=r"(r[2]), "=r"(r[3]) : "r"(addr));
}
__device__ __forceinline__ void mma16816h(float* c, const unsigned int* a,
                                          unsigned int b0, unsigned int b1) {
    asm volatile("mma.sync.aligned.m16n8k16.row.col.f32.f16.f16.f32 "
                 "{%0,%1,%2,%3},{%4,%5,%6,%7},{%8,%9},{%0,%1,%2,%3};"
                 : "+f"(c[0]), "+f"(c[1]), "+f"(c[2]), "+f"(c[3])
                 : "r"(a[0]), "r"(a[1]), "r"(a[2]), "r"(a[3]), "r"(b0), "r"(b1));
}
__device__ __forceinline__ void cpasync16z(unsigned int daddr, const void* gp, int sz) {
    asm volatile("cp.async.ca.shared.global [%0], [%1], 16, %2;"
                 :: "r"(daddr), "l"(gp), "r"(sz));
}

__global__ __launch_bounds__(256, 2)
void k_gemm5(const __half* __restrict__ A1,
             const __half* __restrict__ B1,
             float* __restrict__ C1,
             const __half* __restrict__ A2,
             const __half* __restrict__ B2,
             float* __restrict__ C2,
             size_t aPlane, int M, int N, int K, int ldc, int act) {
    const __half* A = (blockIdx.z == 0) ? A1 : A2;
    const __half* B = (blockIdx.z == 0) ? B1 : B2;
    float* C        = (blockIdx.z == 0) ? C1 : C2;

    extern __shared__ __half smbuf[];
    const int tid  = threadIdx.x;
    const int lane = tid & 31;
    const int wid  = tid >> 5;
    const int wm   = wid >> 2;
    const int wn   = wid & 3;
    const int mBase = blockIdx.y * 128;
    const int nBase = blockIdx.x * 128;

    const unsigned int smB = (unsigned int)__cvta_generic_to_shared(smbuf);

    const __half* Ah = A;
    const __half* Al = A + aPlane;

    const int kChunks = K >> 5;

    // per stage: A = 2 planes x 128 rows x 4 segs = 1024 x 16B
    //            B = 1 plane  x  32 rows x 16 segs =  512 x 16B
    auto issue = [&](int ch) {
        if (ch < kChunks) {
            const unsigned int base = smB + (unsigned int)(ch % NSTAGE) * STG_BYTES;
#pragma unroll
            for (int q2 = 0; q2 < 4; q2++) {   // A chunks
                int idx = tid + 256 * q2;
                int pl  = idx >> 9;
                int rem = idx & 511;
                int row = rem >> 2;
                int seg = rem & 3;
                const __half* gp = (pl ? Al : Ah) +
                    (size_t)(mBase + row) * K + ch * 32 + seg * 8;
                unsigned int da = base +
                    (unsigned int)((pl ? SA_L : SA_H) + row * ASTR + seg * 8) * 2;
                cpasync16z(da, gp, 16);
            }
#pragma unroll
            for (int q2 = 0; q2 < 2; q2++) {   // B chunks
                int idx = tid + 256 * q2;      // 0..511
                int row = idx >> 4;
                int seg = idx & 15;
                int gcol = nBase + seg * 8;
                int ok = gcol < N;
                const __half* gp = B +
                    (ok ? ((size_t)(ch * 32 + row) * N + gcol) : (size_t)0);
                unsigned int da = base +
                    (unsigned int)(SB_H + row * BSTR + seg * 8) * 2;
                cpasync16z(da, gp, ok ? 16 : 0);
            }
        }
        asm volatile("cp.async.commit_group;");
    };

    float acc[4][4][4];
#pragma unroll
    for (int i = 0; i < 4; i++)
#pragma unroll
        for (int j = 0; j < 4; j++)
#pragma unroll
            for (int q = 0; q < 4; q++) acc[i][j][q] = 0.f;

    issue(0); issue(1);

#pragma unroll 1
    for (int ch = 0; ch < kChunks; ch++) {
        asm volatile("cp.async.wait_group 1;" ::: "memory");
        __syncthreads();
        issue(ch + 2);

        const unsigned int sb = smB + (unsigned int)(ch % NSTAGE) * STG_BYTES;
#pragma unroll
        for (int ks = 0; ks < 2; ks++) {
            const int k0 = ks * 16;
            unsigned int ah[4][4], al[4][4], bh[2][4];
#pragma unroll
            for (int mf = 0; mf < 4; mf++) {
                int row = wm * 64 + mf * 16 + (lane & 15);
                int col = k0 + (lane >> 4) * 8;
                unsigned int ad = sb + (unsigned int)(row * ASTR + col) * 2;
                ldsm4(ah[mf], ad + SA_H * 2);
                ldsm4(al[mf], ad + SA_L * 2);
            }
#pragma unroll
            for (int nf2 = 0; nf2 < 2; nf2++) {
                int rowk = k0 + (lane & 15);
                int coln = wn * 32 + nf2 * 16 + (lane >> 4) * 8;
                unsigned int bd = sb + (unsigned int)(rowk * BSTR + coln) * 2;
                ldsm4t(bh[nf2], bd + SB_H * 2);
            }
#pragma unroll
            for (int mf = 0; mf < 4; mf++) {
#pragma unroll
                for (int nf = 0; nf < 4; nf++) {
                    unsigned int b0 = bh[nf >> 1][(nf & 1) * 2];
                    unsigned int b1 = bh[nf >> 1][(nf & 1) * 2 + 1];
                    mma16816h(acc[mf][nf], ah[mf], b0, b1);
                    mma16816h(acc[mf][nf], al[mf], b0, b1);
                }
            }
        }
    }

    // epilogue
#pragma unroll
    for (int mf = 0; mf < 4; mf++) {
#pragma unroll
        for (int nf = 0; nf < 4; nf++) {
            int r = mBase + wm * 64 + mf * 16 + (lane >> 2);
            int c = nBase + wn * 32 + nf * 8 + (lane & 3) * 2;
            if (c < N) {
                float a0 = acc[mf][nf][0], a1 = acc[mf][nf][1];
                float a2 = acc[mf][nf][2], a3 = acc[mf][nf][3];
                if (act == 1) {
                    a0 = tanhf(a0); a1 = tanhf(a1);
                    a2 = tanhf(a2); a3 = tanhf(a3);
                }
                *(float2*)&C[(size_t)r * ldc + c] = make_float2(a0, a1);
                *(float2*)&C[(size_t)(r + 8) * ldc + c] = make_float2(a2, a3);
            }
        }
    }
}

// ---------------- E2: 5-way LoRA mix -> fp16 planes -------------------------
__global__ __launch_bounds__(256, 3)
void k_mix(const float* __restrict__ x,
           const float* __restrict__ shift,
           const float* __restrict__ w2,
           const float* __restrict__ mr, const float* __restrict__ mk,
           const float* __restrict__ mv, const float* __restrict__ mw,
           const float* __restrict__ mv2) {
    __shared__ float hs[32][160];
    __shared__ float ws[160][32];
    int rowBase = blockIdx.x * 32;
    int colBase = blockIdx.y * 32;
    int tid = threadIdx.x;

    for (int l = tid; l < 32 * 160; l += 256) {
        int rr = l / 160, d = l % 160;
        hs[rr][d] = g_hpre[(rowBase + rr) * 160 + d];
    }
    for (int l = tid; l < 160 * 32; l += 256) {
        int fd = l / 32, cc = l % 32;
        ws[fd][cc] = w2[fd * Cc + colBase + cc];
    }
    __syncthreads();

    int cc = tid % 32;
    int r0 = tid / 32;
    int c  = colBase + cc;
    float tr = mr[c], tk = mk[c], tv = mv[c], tw = mw[c], tv2 = mv2[c];

    for (int rr = r0; rr < 32; rr += 8) {
        float m0 = 0, m1 = 0, m2 = 0, m3 = 0, m4 = 0;
#pragma unroll 8
        for (int d = 0; d < 32; d++) {
            m0 = fmaf(hs[rr][d],       ws[d][cc],       m0);
            m1 = fmaf(hs[rr][32 + d],  ws[32 + d][cc],  m1);
            m2 = fmaf(hs[rr][64 + d],  ws[64 + d][cc],  m2);
            m3 = fmaf(hs[rr][96 + d],  ws[96 + d][cc],  m3);
            m4 = fmaf(hs[rr][128 + d], ws[128 + d][cc], m4);
        }
        int bt  = rowBase + rr;
        int t   = bt % Tt;
        int b   = bt / Tt;
        int idx = bt * Cc + c;
        float xval = x[idx];
        float prev = (t == 0) ? shift[b * Cc + c] : x[idx - Cc];
        float dx   = prev - xval;
        float vr  = xval + dx * (tr  + m0);
        float vk  = xval + dx * (tk  + m1);
        float vv  = xval + dx * (tv  + m2);
        float vw  = xval + dx * (tw  + m3);
        float vv2 = xval + dx * (tv2 + m4);
        __half h, l;
        split2h(vr,  h, l); g_pxr [idx] = h; g_pxr [BIGN + idx] = l;
        split2h(vk,  h, l); g_pxk [idx] = h; g_pxk [BIGN + idx] = l;
        split2h(vv,  h, l); g_pxv [idx] = h; g_pxv [BIGN + idx] = l;
        split2h(vw,  h, l); g_pxw [idx] = h; g_pxw [BIGN + idx] = l;
        split2h(vv2, h, l); g_pxv2[idx] = h; g_pxv2[BIGN + idx] = l;
    }
}

// ---------------- E3+E4 fused: decay & v2 epilogues -------------------------
__global__ __launch_bounds__(256)
void k_epi(const float* __restrict__ tdec,
           const float* __restrict__ w2d,
           const float* __restrict__ w2v) {
    __shared__ float tw[32][64];
    __shared__ float tv[32][64];
    __shared__ float wd[64][64];
    __shared__ float wv[64][64];
    int rowBase = blockIdx.x * 32;
    int colBase = blockIdx.y * 64;
    int tid = threadIdx.x;

    for (int l = tid; l < 32 * 64; l += 256) {
        int rr = l / 64, d = l % 64;
        tw[rr][d] = g_tmpw[(rowBase + rr) * 64 + d];
        tv[rr][d] = g_tmpv[(rowBase + rr) * 64 + d];
    }
    for (int l = tid; l < 64 * 64; l += 256) {
        int d = l / 64, cc = l % 64;
        wd[d][cc] = w2d[d * Cc + colBase + cc];
        wv[d][cc] = w2v[d * Cc + colBase + cc];
    }
    __syncthreads();

    int cc = tid % 64;
    int r0 = tid / 64;
    float td = tdec[colBase + cc];
    for (int rr = r0; rr < 32; rr += 4) {
        float sd = td, sv = 0.f;
#pragma unroll 16
        for (int d = 0; d < 64; d++) {
            sd = fmaf(tw[rr][d], wd[d][cc], sd);
            sv = fmaf(tv[rr][d], wv[d][cc], sv);
        }
        int idx = (rowBase + rr) * Cc + colBase + cc;
        g_decay[idx] = expf(-expf(sd));
        g_v2[idx] += sv;
    }
}

// ---------------- S: WKV scan, 256 threads, 4 lanes/column ------------------
#define CHUNK 8
__device__ __forceinline__ void cpasync16(unsigned int daddr, const void* gp) {
    asm volatile("cp.async.ca.shared.global [%0], [%1], 16;"
                 :: "r"(daddr), "l"(gp));
}
__global__ __launch_bounds__(256)
void k_scan(const float* __restrict__ wkv_in,
            float* __restrict__ wkv_out) {
    const int h = blockIdx.x, b = blockIdx.y;
    const int tid  = threadIdx.x;
    const int lane = tid & 31;
    const int wid  = tid >> 5;
    const int jj   = wid * 8 + (lane >> 2);
    const int q    = lane & 3;

    __shared__ float sbuf[2][4][CHUNK][64];
    const unsigned int sb = (unsigned int)__cvta_generic_to_shared(&sbuf[0][0][0][0]);

    float state[16];
#pragma unroll
    for (int i = 0; i < 16; i++)
        state[i] = wkv_in[(size_t)((b * Hh + h) * Nn + q * 16 + i) * Nn + jj];

    const float* srcs[4] = { g_r, g_k, g_decay, g_v };
    const size_t rowOff = (size_t)h * Nn;

    auto issue = [&](int buf, int t0) {
#pragma unroll
        for (int p = 0; p < 2; p++) {
            int l   = tid + 256 * p;
            int arr = l >> 7;
            int rem = l & 127;
            int t   = rem >> 4;
            int seg = rem & 15;
            const float* gp = srcs[arr] +
                (size_t)(b * Tt + t0 + t) * Cc + rowOff + seg * 4;
            unsigned int da = sb +
                (unsigned int)((((buf * 4 + arr) * CHUNK + t) * 64) + seg * 4) * 4;
            cpasync16(da, gp);
        }
        asm volatile("cp.async.commit_group;");
    };

    issue(0, 0);
    asm volatile("cp.async.wait_group 0;" ::: "memory");
    __syncthreads();

    const int nch = Tt / CHUNK;
    for (int ch = 0; ch < nch; ch++) {
        const int cur = ch & 1;
        if (ch + 1 < nch) issue(cur ^ 1, (ch + 1) * CHUNK);

        const int t0 = ch * CHUNK;
#pragma unroll
        for (int tt = 0; tt < CHUNK; tt++) {
            const float4* rs4 = (const float4*)&sbuf[cur][0][tt][q * 16];
            const float4* ks4 = (const float4*)&sbuf[cur][1][tt][q * 16];
            const float4* ds4 = (const float4*)&sbuf[cur][2][tt][q * 16];
            const float vj = sbuf[cur][3][tt][jj];

            float y = 0.f;
#pragma unroll
            for (int i4 = 0; i4 < 4; i4++) {
                float4 r4 = rs4[i4], k4 = ks4[i4], d4 = ds4[i4];
                float kx, kv;
                float s0 = state[4*i4+0], s1 = state[4*i4+1];
                float s2 = state[4*i4+2], s3 = state[4*i4+3];
                y = fmaf(r4.x, s0, y);
                kx = fmaf(-k4.x, d4.x, k4.x); kv = kx * vj;
                state[4*i4+0] = fmaf(s0, d4.x, kv);
                y = fmaf(r4.y, s1, y);
                kx = fmaf(-k4.y, d4.y, k4.y); kv = kx * vj;
                state[4*i4+1] = fmaf(s1, d4.y, kv);
                y = fmaf(r4.z, s2, y);
                kx = fmaf(-k4.z, d4.z, k4.z); kv = kx * vj;
                state[4*i4+2] = fmaf(s2, d4.z, kv);
                y = fmaf(r4.w, s3, y);
                kx = fmaf(-k4.w, d4.w, k4.w); kv = kx * vj;
                state[4*i4+3] = fmaf(s3, d4.w, kv);
            }
            y += __shfl_xor_sync(0xffffffffu, y, 1);
            y += __shfl_xor_sync(0xffffffffu, y, 2);
            if (q == 0)
                g_ys[(size_t)(b * Tt + t0 + tt) * Cc + rowOff + jj] = y;
        }

        asm volatile("cp.async.wait_group 0;" ::: "memory");
        __syncthreads();
    }

#pragma unroll
    for (int i = 0; i < 16; i++)
        wkv_out[(size_t)((b * Hh + h) * Nn + q * 16 + i) * Nn + jj] = state[i];
}

// ---------------- E5: y = LN(ys + v2) -> fp16 planes -------------------------
__global__ void k_ln(const float* __restrict__ lnw,
                     const float* __restrict__ lnb) {
    int row = blockIdx.x;
    int tid = threadIdx.x;
    const float* a  = g_ys + (size_t)row * Cc;
    const float* bp = g_v2 + (size_t)row * Cc;
    float s = 0.f, ss = 0.f;
    for (int c = tid; c < Cc; c += 256) {
        float v = a[c] + bp[c];
        s += v; ss += v * v;
    }
    __shared__ float sh1[256], sh2[256];
    sh1[tid] = s; sh2[tid] = ss;
    __syncthreads();
    for (int st = 128; st > 0; st >>= 1) {
        if (tid < st) { sh1[tid] += sh1[tid + st]; sh2[tid] += sh2[tid + st]; }
        __syncthreads();
    }
    float mu  = sh1[0] / Cc;
    float var = sh2[0] / Cc - mu * mu;
    float rstd = rsqrtf(var + 1e-5f);
    for (int c = tid; c < Cc; c += 256) {
        float v = a[c] + bp[c];
        float res = (v - mu) * rstd * lnw[c] + lnb[c];
        __half h, l;
        split2h(res, h, l);
        size_t idx = (size_t)row * Cc + c;
        g_pyn[idx] = h; g_pyn[BIGN + idx] = l;
    }
}

// ---------------- E6: shift_state_out ---------------------------------------
__global__ void k_copyshift(const float* __restrict__ x, float* __restrict__ out) {
    int i = blockIdx.x * 256 + threadIdx.x;
    if (i >= Bb * Cc) return;
    int b = i / Cc, c = i % Cc;
    out[i] = x[(size_t)(b * Tt + Tt - 1) * Cc + c];
}

// ---------------- launcher ---------------------------------------------------
extern "C" void kernel_launch(void* const* d_in, const int* in_sizes, int n_in,
                              void* d_out, int out_size) {
    const float* x        = (const float*)d_in[0];
    const float* shift_in = (const float*)d_in[1];
    const float* wkv_in   = (const float*)d_in[2];
    const float* maa_x    = (const float*)d_in[3];
    const float* maa_r    = (const float*)d_in[4];
    const float* maa_k    = (const float*)d_in[5];
    const float* maa_v    = (const float*)d_in[6];
    const float* maa_w    = (const float*)d_in[7];
    const float* maa_v2   = (const float*)d_in[8];
    const float* maa_w1   = (const float*)d_in[9];
    const float* maa_w2   = (const float*)d_in[10];
    const float* tdecay   = (const float*)d_in[11];
    const float* dec_w1   = (const float*)d_in[12];
    const float* dec_w2   = (const float*)d_in[13];
    const float* v2_w1    = (const float*)d_in[14];
    const float* v2_w2    = (const float*)d_in[15];
    const float* W_r      = (const float*)d_in[16];
    const float* W_k      = (const float*)d_in[17];
    const float* W_v      = (const float*)d_in[18];
    const float* W_o      = (const float*)d_in[19];
    const float* ln_w     = (const float*)d_in[20];
    const float* ln_b     = (const float*)d_in[21];

    float* out_y     = (float*)d_out;
    float* out_shift = out_y + (size_t)BT * Cc;
    float* out_wkv   = out_shift + (size_t)Bb * Cc;

    float *rb = 0, *kb = 0, *vb = 0, *v2b = 0;
    float *hpre = 0, *tmpw = 0, *tmpv = 0;
    __half *pxxx = 0, *pxr = 0, *pxk = 0, *pxv = 0, *pxw = 0, *pxv2 = 0, *pyn = 0;
    __half *pWr = 0, *pWk = 0, *pWv = 0, *pWo = 0;
    __half *pW1 = 0, *pWd = 0, *pWe = 0;
    cudaGetSymbolAddress((void**)&rb,    g_r);
    cudaGetSymbolAddress((void**)&kb,    g_k);
    cudaGetSymbolAddress((void**)&vb,    g_v);
    cudaGetSymbolAddress((void**)&v2b,   g_v2);
    cudaGetSymbolAddress((void**)&hpre,  g_hpre);
    cudaGetSymbolAddress((void**)&tmpw,  g_tmpw);
    cudaGetSymbolAddress((void**)&tmpv,  g_tmpv);
    cudaGetSymbolAddress((void**)&pxxx,  g_pxxx);
    cudaGetSymbolAddress((void**)&pxr,   g_pxr);
    cudaGetSymbolAddress((void**)&pxk,   g_pxk);
    cudaGetSymbolAddress((void**)&pxv,   g_pxv);
    cudaGetSymbolAddress((void**)&pxw,   g_pxw);
    cudaGetSymbolAddress((void**)&pxv2,  g_pxv2);
    cudaGetSymbolAddress((void**)&pyn,   g_pyn);
    cudaGetSymbolAddress((void**)&pWr,   g_pWr);
    cudaGetSymbolAddress((void**)&pWk,   g_pWk);
    cudaGetSymbolAddress((void**)&pWv,   g_pWv);
    cudaGetSymbolAddress((void**)&pWo,   g_pWo);
    cudaGetSymbolAddress((void**)&pW1,   g_pW1);
    cudaGetSymbolAddress((void**)&pWd,   g_pWd);
    cudaGetSymbolAddress((void**)&pWe,   g_pWe);

    cudaFuncSetAttribute(k_gemm5,
                         cudaFuncAttributeMaxDynamicSharedMemorySize,
                         NSTAGE * STG_BYTES);

    const dim3 gemmGrid(Cc / 128, BT / 128, 1);
    const int  gemmSmem = NSTAGE * STG_BYTES;

    // weight conversions (fp16 hi only)
    k_conv<<<WN / 256, 256>>>(W_r, pWr, WN);
    k_conv<<<WN / 256, 256>>>(W_k, pWk, WN);
    k_conv<<<WN / 256, 256>>>(W_v, pWv, WN);
    k_conv<<<WN / 256, 256>>>(W_o, pWo, WN);
    k_conv<<<(Cc * 160) / 256, 256>>>(maa_w1, pW1, Cc * 160);
    k_conv<<<(Cc * 64) / 256, 256>>>(dec_w1, pWd, Cc * 64);
    k_conv<<<(Cc * 64) / 256, 256>>>(v2_w1, pWe, Cc * 64);

    // E1: token shift -> xxx planes
    k_shift<<<BIGN / 256, 256>>>(x, shift_in, maa_x);

    // G1: hpre = tanh(xxx @ maa_w1)  [8192,160]
    k_gemm5<<<dim3(2, BT / 128, 1), 256, gemmSmem>>>(
        pxxx, pW1, hpre, pxxx, pW1, hpre,
        (size_t)BIGN, BT, 160, Cc, 160, 1);

    // E2: 5-way mix -> planes
    k_mix<<<dim3(BT / 32, Cc / 32), 256>>>(x, shift_in, maa_w2,
                                           maa_r, maa_k, maa_v, maa_w, maa_v2);

    // Big GEMMs (fp16x2, 2 MMAs/k-step)
    k_gemm5<<<gemmGrid, 256, gemmSmem>>>(pxr,  pWr, rb,  pxr,  pWr, rb,
                                         (size_t)BIGN, BT, Cc, Cc, Cc, 0);
    k_gemm5<<<gemmGrid, 256, gemmSmem>>>(pxk,  pWk, kb,  pxk,  pWk, kb,
                                         (size_t)BIGN, BT, Cc, Cc, Cc, 0);
    k_gemm5<<<gemmGrid, 256, gemmSmem>>>(pxv,  pWv, vb,  pxv,  pWv, vb,
                                         (size_t)BIGN, BT, Cc, Cc, Cc, 0);
    k_gemm5<<<gemmGrid, 256, gemmSmem>>>(pxv2, pWv, v2b, pxv2, pWv, v2b,
                                         (size_t)BIGN, BT, Cc, Cc, Cc, 0);

    // Small LoRA GEMMs (dual problem via gridDim.z=2, fused tanh)
    k_gemm5<<<dim3(1, BT / 128, 2), 256, gemmSmem>>>(
        pxw, pWd, tmpw, pxv2, pWe, tmpv,
        (size_t)BIGN, BT, 64, Cc, 64, 1);

    // E3+E4 fused epilogues
    k_epi<<<dim3(BT / 32, Cc / 64), 256>>>(tdecay, dec_w2, v2_w2);

    // WKV scan (k * (1-decay) fused)
    k_scan<<<dim3(Hh, Bb), 256>>>(wkv_in, out_wkv);

    // LayerNorm(ys + v2) -> planes
    k_ln<<<BT, 256>>>(ln_w, ln_b);

    // Output GEMM: y = ynorm @ W_o
    k_gemm5<<<gemmGrid, 256, gemmSmem>>>(pyn, pWo, out_y, pyn, pWo, out_y,
                                         (size_t)BIGN, BT, Cc, Cc, Cc, 0);

    // shift state out
    k_copyshift<<<(Bb * Cc + 255) / 256, 256>>>(x, out_shift);
}

// round 15
// speedup vs baseline: 1.9861x; 1.1202x over previous
#include <cuda_runtime.h>
#include <cuda_fp16.h>
#include <cstdint>
#include <math.h>

// Problem constants
#define Bb   4
#define Tt   2048
#define Cc   2048
#define Hh   32
#define Nn   64
#define BT   (Bb*Tt)          // 8192
#define BIGN (BT*Cc)          // 16,777,216
#define WN   (Cc*Cc)          // 4,194,304

// ---------------- scratch ----------------------------------------------------
__device__ float g_r    [BIGN];
__device__ float g_k    [BIGN];
__device__ float g_v    [BIGN];
__device__ float g_v2   [BIGN];
__device__ float g_decay[BIGN];
__device__ float g_ys   [BIGN];
__device__ float g_hpre [BT*160];

// fp16 hi/lo planes (A operands): [0..n) hi, [n..2n) lo
__device__ __half g_pxxx[2*BIGN];
__device__ __half g_pxr [2*BIGN];
__device__ __half g_pxk [2*BIGN];
__device__ __half g_pxv [2*BIGN];
__device__ __half g_pxw [2*BIGN];
__device__ __half g_pxv2[2*BIGN];
__device__ __half g_pyn [2*BIGN];
__device__ __half g_ptw [2*BT*64];   // tanh(xw@dec_w1) hi/lo
__device__ __half g_ptv [2*BT*64];   // tanh(xv2@v2_w1) hi/lo
// fp16 weight planes (B operands, hi only)
__device__ __half g_pWr[WN];
__device__ __half g_pWk[WN];
__device__ __half g_pWv[WN];
__device__ __half g_pWo[WN];
__device__ __half g_pW1[Cc*160];
__device__ __half g_pWd[Cc*64];
__device__ __half g_pWe[Cc*64];
__device__ __half g_pWd2[64*Cc];
__device__ __half g_pWe2[64*Cc];

__device__ __forceinline__ void split2h(float f, __half& h, __half& l) {
    h = __float2half_rn(f);
    l = __float2half_rn(f - __half2float(h));
}

// ---------------- E1: token shift -> xxx planes -----------------------------
__global__ void k_shift(const float* __restrict__ x,
                        const float* __restrict__ shift,
                        const float* __restrict__ maa_x) {
    int idx = blockIdx.x * 256 + threadIdx.x;
    if (idx >= BIGN) return;
    int c  = idx % Cc;
    int bt = idx / Cc;
    int t  = bt % Tt;
    int b  = bt / Tt;
    float xv   = x[idx];
    float prev = (t == 0) ? shift[b * Cc + c] : x[idx - Cc];
    float r    = xv + (prev - xv) * maa_x[c];
    __half h, l;
    split2h(r, h, l);
    g_pxxx[idx] = h; g_pxxx[BIGN + idx] = l;
}

// ---------------- weight fp32 -> fp16 hi -------------------------------------
__global__ void k_conv(const float* __restrict__ src,
                       __half* __restrict__ dst, int n) {
    int i = blockIdx.x * 256 + threadIdx.x;
    if (i >= n) return;
    dst[i] = __float2half_rn(src[i]);
}

// =============================================================================
// Tensor-core GEMM v6 (fp16x2: A hi/lo planes, B hi plane; fp32 accumulate):
//   4-problem batch via blockIdx.z. Tile 128x128, BK=32, 3-stage, 2 CTAs/SM.
//   Epilogue modes (per-z): 0 float, 1 tanh->float, 2 tanh->half planes,
//   3 exp(-exp(acc+bias[c]))->float, 4 float +=.
// =============================================================================
#define ASTR 40
#define BSTR 136
#define SA_H 0
#define SA_L 5120
#define SB_H 10240
#define STG  14592
#define STG_BYTES (STG*2)
#define NSTAGE 3

__device__ __forceinline__ void ldsm4(unsigned int* r, unsigned int addr) {
    asm volatile("ldmatrix.sync.aligned.m8n8.x4.shared.b16 {%0,%1,%2,%3},[%4];"
                 : "=r"(r[0]), "=r"(r[1]), "=r"(r[2]), "=r"(r[3]) : "r"(addr));
}
__device__ __forceinline__ void ldsm4t(unsigned int* r, unsigned int addr) {
    asm volatile("ldmatrix.sync.aligned.m8n8.x4.trans.shared.b16 {%0,%1,%2,%3},[%4];"
                 : "=r"(r[0]), "=r"(r[1]), "=r"(r[2]), "=r"(r[3]) : "r"(addr));
}
__device__ __forceinline__ void mma16816h(float* c, const unsigned int* a,
                                          unsigned int b0, unsigned int b1) {
    asm volatile("mma.sync.aligned.m16n8k16.row.col.f32.f16.f16.f32 "
                 "{%0,%1,%2,%3},{%4,%5,%6,%7},{%8,%9},{%0,%1,%2,%3};"
                 : "+f"(c[0]), "+f"(c[1]), "+f"(c[2]), "+f"(c[3])
                 : "r"(a[0]), "r"(a[1]), "r"(a[2]), "r"(a[3]), "r"(b0), "r"(b1));
}
__device__ __forceinline__ void cpasync16z(unsigned int daddr, const void* gp, int sz) {
    asm volatile("cp.async.ca.shared.global [%0], [%1], 16, %2;"
                 :: "r"(daddr), "l"(gp), "r"(sz));
}

__global__ __launch_bounds__(256, 2)
void k_gemm6(const __half* __restrict__ A1, const __half* __restrict__ A2,
             const __half* __restrict__ A3, const __half* __restrict__ A4,
             const __half* __restrict__ B1, const __half* __restrict__ B2,
             const __half* __restrict__ B3, const __half* __restrict__ B4,
             void* C1, void* C2, void* C3, void* C4,
             const float* __restrict__ bias,
             size_t aPlane, size_t cPlane,
             int M, int N, int K, int ldc, int4 modes) {
    const int z = blockIdx.z;
    const __half* A = (z == 0) ? A1 : (z == 1) ? A2 : (z == 2) ? A3 : A4;
    const __half* B = (z == 0) ? B1 : (z == 1) ? B2 : (z == 2) ? B3 : B4;
    void* C         = (z == 0) ? C1 : (z == 1) ? C2 : (z == 2) ? C3 : C4;
    const int mode  = (z == 0) ? modes.x : (z == 1) ? modes.y
                    : (z == 2) ? modes.z : modes.w;

    extern __shared__ __half smbuf[];
    const int tid  = threadIdx.x;
    const int lane = tid & 31;
    const int wid  = tid >> 5;
    const int wm   = wid >> 2;
    const int wn   = wid & 3;
    const int mBase = blockIdx.y * 128;
    const int nBase = blockIdx.x * 128;

    const unsigned int smB = (unsigned int)__cvta_generic_to_shared(smbuf);

    const __half* Ah = A;
    const __half* Al = A + aPlane;

    const int kChunks = K >> 5;

    auto issue = [&](int ch) {
        if (ch < kChunks) {
            const unsigned int base = smB + (unsigned int)(ch % NSTAGE) * STG_BYTES;
#pragma unroll
            for (int q2 = 0; q2 < 4; q2++) {   // A: 2 planes x 128 rows x 4 segs
                int idx = tid + 256 * q2;
                int pl  = idx >> 9;
                int rem = idx & 511;
                int row = rem >> 2;
                int seg = rem & 3;
                const __half* gp = (pl ? Al : Ah) +
                    (size_t)(mBase + row) * K + ch * 32 + seg * 8;
                unsigned int da = base +
                    (unsigned int)((pl ? SA_L : SA_H) + row * ASTR + seg * 8) * 2;
                cpasync16z(da, gp, 16);
            }
#pragma unroll
            for (int q2 = 0; q2 < 2; q2++) {   // B: 32 rows x 16 segs
                int idx = tid + 256 * q2;
                int row = idx >> 4;
                int seg = idx & 15;
                int gcol = nBase + seg * 8;
                int ok = gcol < N;
                const __half* gp = B +
                    (ok ? ((size_t)(ch * 32 + row) * N + gcol) : (size_t)0);
                unsigned int da = base +
                    (unsigned int)(SB_H + row * BSTR + seg * 8) * 2;
                cpasync16z(da, gp, ok ? 16 : 0);
            }
        }
        asm volatile("cp.async.commit_group;");
    };

    float acc[4][4][4];
#pragma unroll
    for (int i = 0; i < 4; i++)
#pragma unroll
        for (int j = 0; j < 4; j++)
#pragma unroll
            for (int q = 0; q < 4; q++) acc[i][j][q] = 0.f;

    issue(0); issue(1);

#pragma unroll 1
    for (int ch = 0; ch < kChunks; ch++) {
        asm volatile("cp.async.wait_group 1;" ::: "memory");
        __syncthreads();
        issue(ch + 2);

        const unsigned int sb = smB + (unsigned int)(ch % NSTAGE) * STG_BYTES;
#pragma unroll
        for (int ks = 0; ks < 2; ks++) {
            const int k0 = ks * 16;
            unsigned int ah[4][4], al[4][4], bh[2][4];
#pragma unroll
            for (int mf = 0; mf < 4; mf++) {
                int row = wm * 64 + mf * 16 + (lane & 15);
                int col = k0 + (lane >> 4) * 8;
                unsigned int ad = sb + (unsigned int)(row * ASTR + col) * 2;
                ldsm4(ah[mf], ad + SA_H * 2);
                ldsm4(al[mf], ad + SA_L * 2);
            }
#pragma unroll
            for (int nf2 = 0; nf2 < 2; nf2++) {
                int rowk = k0 + (lane & 15);
                int coln = wn * 32 + nf2 * 16 + (lane >> 4) * 8;
                unsigned int bd = sb + (unsigned int)(rowk * BSTR + coln) * 2;
                ldsm4t(bh[nf2], bd + SB_H * 2);
            }
#pragma unroll
            for (int mf = 0; mf < 4; mf++) {
#pragma unroll
                for (int nf = 0; nf < 4; nf++) {
                    unsigned int b0 = bh[nf >> 1][(nf & 1) * 2];
                    unsigned int b1 = bh[nf >> 1][(nf & 1) * 2 + 1];
                    mma16816h(acc[mf][nf], ah[mf], b0, b1);
                    mma16816h(acc[mf][nf], al[mf], b0, b1);
                }
            }
        }
    }

    // epilogue
#pragma unroll
    for (int mf = 0; mf < 4; mf++) {
#pragma unroll
        for (int nf = 0; nf < 4; nf++) {
            int r = mBase + wm * 64 + mf * 16 + (lane >> 2);
            int c = nBase + wn * 32 + nf * 8 + (lane & 3) * 2;
            if (c < N) {
                float a0 = acc[mf][nf][0], a1 = acc[mf][nf][1];
                float a2 = acc[mf][nf][2], a3 = acc[mf][nf][3];
                size_t i0 = (size_t)r * ldc + c;
                size_t i1 = (size_t)(r + 8) * ldc + c;
                if (mode == 0) {
                    float* Cf = (float*)C;
                    *(float2*)&Cf[i0] = make_float2(a0, a1);
                    *(float2*)&Cf[i1] = make_float2(a2, a3);
                } else if (mode == 1) {
                    float* Cf = (float*)C;
                    *(float2*)&Cf[i0] = make_float2(tanhf(a0), tanhf(a1));
                    *(float2*)&Cf[i1] = make_float2(tanhf(a2), tanhf(a3));
                } else if (mode == 2) {
                    __half* Chp = (__half*)C;
                    a0 = tanhf(a0); a1 = tanhf(a1);
                    a2 = tanhf(a2); a3 = tanhf(a3);
                    __half h0,l0,h1,l1,h2,l2,h3,l3;
                    split2h(a0,h0,l0); split2h(a1,h1,l1);
                    split2h(a2,h2,l2); split2h(a3,h3,l3);
                    *(__half2*)&Chp[i0] = __halves2half2(h0, h1);
                    *(__half2*)&Chp[i1] = __halves2half2(h2, h3);
                    *(__half2*)&Chp[cPlane + i0] = __halves2half2(l0, l1);
                    *(__half2*)&Chp[cPlane + i1] = __halves2half2(l2, l3);
                } else if (mode == 3) {
                    float b0 = bias[c], b1 = bias[c + 1];
                    float* Cf = (float*)C;
                    *(float2*)&Cf[i0] =
                        make_float2(expf(-expf(a0 + b0)), expf(-expf(a1 + b1)));
                    *(float2*)&Cf[i1] =
                        make_float2(expf(-expf(a2 + b0)), expf(-expf(a3 + b1)));
                } else {   // 4: accumulate
                    float* Cf = (float*)C;
                    Cf[i0] += a0; Cf[i0 + 1] += a1;
                    Cf[i1] += a2; Cf[i1 + 1] += a3;
                }
            }
        }
    }
}

// ---------------- E2: 5-way LoRA mix -> fp16 planes -------------------------
__global__ __launch_bounds__(256, 3)
void k_mix(const float* __restrict__ x,
           const float* __restrict__ shift,
           const float* __restrict__ w2,
           const float* __restrict__ mr, const float* __restrict__ mk,
           const float* __restrict__ mv, const float* __restrict__ mw,
           const float* __restrict__ mv2) {
    __shared__ float hs[32][160];
    __shared__ float ws[160][32];
    int rowBase = blockIdx.x * 32;
    int colBase = blockIdx.y * 32;
    int tid = threadIdx.x;

    for (int l = tid; l < 32 * 160; l += 256) {
        int rr = l / 160, d = l % 160;
        hs[rr][d] = g_hpre[(rowBase + rr) * 160 + d];
    }
    for (int l = tid; l < 160 * 32; l += 256) {
        int fd = l / 32, cc = l % 32;
        ws[fd][cc] = w2[fd * Cc + colBase + cc];
    }
    __syncthreads();

    int cc = tid % 32;
    int r0 = tid / 32;
    int c  = colBase + cc;
    float tr = mr[c], tk = mk[c], tv = mv[c], tw = mw[c], tv2 = mv2[c];

    for (int rr = r0; rr < 32; rr += 8) {
        float m0 = 0, m1 = 0, m2 = 0, m3 = 0, m4 = 0;
#pragma unroll 8
        for (int d = 0; d < 32; d++) {
            m0 = fmaf(hs[rr][d],       ws[d][cc],       m0);
            m1 = fmaf(hs[rr][32 + d],  ws[32 + d][cc],  m1);
            m2 = fmaf(hs[rr][64 + d],  ws[64 + d][cc],  m2);
            m3 = fmaf(hs[rr][96 + d],  ws[96 + d][cc],  m3);
            m4 = fmaf(hs[rr][128 + d], ws[128 + d][cc], m4);
        }
        int bt  = rowBase + rr;
        int t   = bt % Tt;
        int b   = bt / Tt;
        int idx = bt * Cc + c;
        float xval = x[idx];
        float prev = (t == 0) ? shift[b * Cc + c] : x[idx - Cc];
        float dx   = prev - xval;
        float vr  = xval + dx * (tr  + m0);
        float vk  = xval + dx * (tk  + m1);
        float vv  = xval + dx * (tv  + m2);
        float vw  = xval + dx * (tw  + m3);
        float vv2 = xval + dx * (tv2 + m4);
        __half h, l;
        split2h(vr,  h, l); g_pxr [idx] = h; g_pxr [BIGN + idx] = l;
        split2h(vk,  h, l); g_pxk [idx] = h; g_pxk [BIGN + idx] = l;
        split2h(vv,  h, l); g_pxv [idx] = h; g_pxv [BIGN + idx] = l;
        split2h(vw,  h, l); g_pxw [idx] = h; g_pxw [BIGN + idx] = l;
        split2h(vv2, h, l); g_pxv2[idx] = h; g_pxv2[BIGN + idx] = l;
    }
}

// ---------------- S: WKV scan, 256 threads, 4 lanes/column ------------------
#define CHUNK 8
__device__ __forceinline__ void cpasync16(unsigned int daddr, const void* gp) {
    asm volatile("cp.async.ca.shared.global [%0], [%1], 16;"
                 :: "r"(daddr), "l"(gp));
}
__global__ __launch_bounds__(256)
void k_scan(const float* __restrict__ wkv_in,
            float* __restrict__ wkv_out) {
    const int h = blockIdx.x, b = blockIdx.y;
    const int tid  = threadIdx.x;
    const int lane = tid & 31;
    const int wid  = tid >> 5;
    const int jj   = wid * 8 + (lane >> 2);
    const int q    = lane & 3;

    __shared__ float sbuf[2][4][CHUNK][64];
    const unsigned int sb = (unsigned int)__cvta_generic_to_shared(&sbuf[0][0][0][0]);

    float state[16];
#pragma unroll
    for (int i = 0; i < 16; i++)
        state[i] = wkv_in[(size_t)((b * Hh + h) * Nn + q * 16 + i) * Nn + jj];

    const float* srcs[4] = { g_r, g_k, g_decay, g_v };
    const size_t rowOff = (size_t)h * Nn;

    auto issue = [&](int buf, int t0) {
#pragma unroll
        for (int p = 0; p < 2; p++) {
            int l   = tid + 256 * p;
            int arr = l >> 7;
            int rem = l & 127;
            int t   = rem >> 4;
            int seg = rem & 15;
            const float* gp = srcs[arr] +
                (size_t)(b * Tt + t0 + t) * Cc + rowOff + seg * 4;
            unsigned int da = sb +
                (unsigned int)((((buf * 4 + arr) * CHUNK + t) * 64) + seg * 4) * 4;
            cpasync16(da, gp);
        }
        asm volatile("cp.async.commit_group;");
    };

    issue(0, 0);
    asm volatile("cp.async.wait_group 0;" ::: "memory");
    __syncthreads();

    const int nch = Tt / CHUNK;
    for (int ch = 0; ch < nch; ch++) {
        const int cur = ch & 1;
        if (ch + 1 < nch) issue(cur ^ 1, (ch + 1) * CHUNK);

        const int t0 = ch * CHUNK;
#pragma unroll
        for (int tt = 0; tt < CHUNK; tt++) {
            const float4* rs4 = (const float4*)&sbuf[cur][0][tt][q * 16];
            const float4* ks4 = (const float4*)&sbuf[cur][1][tt][q * 16];
            const float4* ds4 = (const float4*)&sbuf[cur][2][tt][q * 16];
            const float vj = sbuf[cur][3][tt][jj];

            float y = 0.f;
#pragma unroll
            for (int i4 = 0; i4 < 4; i4++) {
                float4 r4 = rs4[i4], k4 = ks4[i4], d4 = ds4[i4];
                float kx, kv;
                float s0 = state[4*i4+0], s1 = state[4*i4+1];
                float s2 = state[4*i4+2], s3 = state[4*i4+3];
                y = fmaf(r4.x, s0, y);
                kx = fmaf(-k4.x, d4.x, k4.x); kv = kx * vj;
                state[4*i4+0] = fmaf(s0, d4.x, kv);
                y = fmaf(r4.y, s1, y);
                kx = fmaf(-k4.y, d4.y, k4.y); kv = kx * vj;
                state[4*i4+1] = fmaf(s1, d4.y, kv);
                y = fmaf(r4.z, s2, y);
                kx = fmaf(-k4.z, d4.z, k4.z); kv = kx * vj;
                state[4*i4+2] = fmaf(s2, d4.z, kv);
                y = fmaf(r4.w, s3, y);
                kx = fmaf(-k4.w, d4.w, k4.w); kv = kx * vj;
                state[4*i4+3] = fmaf(s3, d4.w, kv);
            }
            y += __shfl_xor_sync(0xffffffffu, y, 1);
            y += __shfl_xor_sync(0xffffffffu, y, 2);
            if (q == 0)
                g_ys[(size_t)(b * Tt + t0 + tt) * Cc + rowOff + jj] = y;
        }

        asm volatile("cp.async.wait_group 0;" ::: "memory");
        __syncthreads();
    }

#pragma unroll
    for (int i = 0; i < 16; i++)
        wkv_out[(size_t)((b * Hh + h) * Nn + q * 16 + i) * Nn + jj] = state[i];
}

// ---------------- E5: y = LN(ys + v2) -> fp16 planes -------------------------
__global__ void k_ln(const float* __restrict__ lnw,
                     const float* __restrict__ lnb) {
    int row = blockIdx.x;
    int tid = threadIdx.x;
    const float* a  = g_ys + (size_t)row * Cc;
    const float* bp = g_v2 + (size_t)row * Cc;
    float s = 0.f, ss = 0.f;
    for (int c = tid; c < Cc; c += 256) {
        float v = a[c] + bp[c];
        s += v; ss += v * v;
    }
    __shared__ float sh1[256], sh2[256];
    sh1[tid] = s; sh2[tid] = ss;
    __syncthreads();
    for (int st = 128; st > 0; st >>= 1) {
        if (tid < st) { sh1[tid] += sh1[tid + st]; sh2[tid] += sh2[tid + st]; }
        __syncthreads();
    }
    float mu  = sh1[0] / Cc;
    float var = sh2[0] / Cc - mu * mu;
    float rstd = rsqrtf(var + 1e-5f);
    for (int c = tid; c < Cc; c += 256) {
        float v = a[c] + bp[c];
        float res = (v - mu) * rstd * lnw[c] + lnb[c];
        __half h, l;
        split2h(res, h, l);
        size_t idx = (size_t)row * Cc + c;
        g_pyn[idx] = h; g_pyn[BIGN + idx] = l;
    }
}

// ---------------- E6: shift_state_out ---------------------------------------
__global__ void k_copyshift(const float* __restrict__ x, float* __restrict__ out) {
    int i = blockIdx.x * 256 + threadIdx.x;
    if (i >= Bb * Cc) return;
    int b = i / Cc, c = i % Cc;
    out[i] = x[(size_t)(b * Tt + Tt - 1) * Cc + c];
}

// ---------------- launcher ---------------------------------------------------
extern "C" void kernel_launch(void* const* d_in, const int* in_sizes, int n_in,
                              void* d_out, int out_size) {
    const float* x        = (const float*)d_in[0];
    const float* shift_in = (const float*)d_in[1];
    const float* wkv_in   = (const float*)d_in[2];
    const float* maa_x    = (const float*)d_in[3];
    const float* maa_r    = (const float*)d_in[4];
    const float* maa_k    = (const float*)d_in[5];
    const float* maa_v    = (const float*)d_in[6];
    const float* maa_w    = (const float*)d_in[7];
    const float* maa_v2   = (const float*)d_in[8];
    const float* maa_w1   = (const float*)d_in[9];
    const float* maa_w2   = (const float*)d_in[10];
    const float* tdecay   = (const float*)d_in[11];
    const float* dec_w1   = (const float*)d_in[12];
    const float* dec_w2   = (const float*)d_in[13];
    const float* v2_w1    = (const float*)d_in[14];
    const float* v2_w2    = (const float*)d_in[15];
    const float* W_r      = (const float*)d_in[16];
    const float* W_k      = (const float*)d_in[17];
    const float* W_v      = (const float*)d_in[18];
    const float* W_o      = (const float*)d_in[19];
    const float* ln_w     = (const float*)d_in[20];
    const float* ln_b     = (const float*)d_in[21];

    float* out_y     = (float*)d_out;
    float* out_shift = out_y + (size_t)BT * Cc;
    float* out_wkv   = out_shift + (size_t)Bb * Cc;

    float *rb = 0, *kb = 0, *vb = 0, *v2b = 0, *decay = 0, *hpre = 0;
    __half *pxxx = 0, *pxr = 0, *pxk = 0, *pxv = 0, *pxw = 0, *pxv2 = 0, *pyn = 0;
    __half *ptw = 0, *ptv = 0;
    __half *pWr = 0, *pWk = 0, *pWv = 0, *pWo = 0;
    __half *pW1 = 0, *pWd = 0, *pWe = 0, *pWd2 = 0, *pWe2 = 0;
    cudaGetSymbolAddress((void**)&rb,    g_r);
    cudaGetSymbolAddress((void**)&kb,    g_k);
    cudaGetSymbolAddress((void**)&vb,    g_v);
    cudaGetSymbolAddress((void**)&v2b,   g_v2);
    cudaGetSymbolAddress((void**)&decay, g_decay);
    cudaGetSymbolAddress((void**)&hpre,  g_hpre);
    cudaGetSymbolAddress((void**)&pxxx,  g_pxxx);
    cudaGetSymbolAddress((void**)&pxr,   g_pxr);
    cudaGetSymbolAddress((void**)&pxk,   g_pxk);
    cudaGetSymbolAddress((void**)&pxv,   g_pxv);
    cudaGetSymbolAddress((void**)&pxw,   g_pxw);
    cudaGetSymbolAddress((void**)&pxv2,  g_pxv2);
    cudaGetSymbolAddress((void**)&pyn,   g_pyn);
    cudaGetSymbolAddress((void**)&ptw,   g_ptw);
    cudaGetSymbolAddress((void**)&ptv,   g_ptv);
    cudaGetSymbolAddress((void**)&pWr,   g_pWr);
    cudaGetSymbolAddress((void**)&pWk,   g_pWk);
    cudaGetSymbolAddress((void**)&pWv,   g_pWv);
    cudaGetSymbolAddress((void**)&pWo,   g_pWo);
    cudaGetSymbolAddress((void**)&pW1,   g_pW1);
    cudaGetSymbolAddress((void**)&pWd,   g_pWd);
    cudaGetSymbolAddress((void**)&pWe,   g_pWe);
    cudaGetSymbolAddress((void**)&pWd2,  g_pWd2);
    cudaGetSymbolAddress((void**)&pWe2,  g_pWe2);

    cudaFuncSetAttribute(k_gemm6,
                         cudaFuncAttributeMaxDynamicSharedMemorySize,
                         NSTAGE * STG_BYTES);
    const int gemmSmem = NSTAGE * STG_BYTES;

    // weight conversions (fp16 hi only)
    k_conv<<<WN / 256, 256>>>(W_r, pWr, WN);
    k_conv<<<WN / 256, 256>>>(W_k, pWk, WN);
    k_conv<<<WN / 256, 256>>>(W_v, pWv, WN);
    k_conv<<<WN / 256, 256>>>(W_o, pWo, WN);
    k_conv<<<(Cc * 160) / 256, 256>>>(maa_w1, pW1, Cc * 160);
    k_conv<<<(Cc * 64) / 256, 256>>>(dec_w1, pWd, Cc * 64);
    k_conv<<<(Cc * 64) / 256, 256>>>(v2_w1, pWe, Cc * 64);
    k_conv<<<(Cc * 64) / 256, 256>>>(dec_w2, pWd2, Cc * 64);
    k_conv<<<(Cc * 64) / 256, 256>>>(v2_w2, pWe2, Cc * 64);

    // E1: token shift -> xxx planes
    k_shift<<<BIGN / 256, 256>>>(x, shift_in, maa_x);

    // G1: hpre = tanh(xxx @ maa_w1) [8192,160] (mode 1)
    k_gemm6<<<dim3(2, BT / 128, 1), 256, gemmSmem>>>(
        pxxx, pxxx, pxxx, pxxx, pW1, pW1, pW1, pW1,
        hpre, hpre, hpre, hpre, tdecay,
        (size_t)BIGN, 0, BT, 160, Cc, 160, make_int4(1, 1, 1, 1));

    // E2: 5-way mix -> planes
    k_mix<<<dim3(BT / 32, Cc / 32), 256>>>(x, shift_in, maa_w2,
                                           maa_r, maa_k, maa_v, maa_w, maa_v2);

    // Projections batched (z=4, mode 0)
    k_gemm6<<<dim3(16, BT / 128, 4), 256, gemmSmem>>>(
        pxr, pxk, pxv, pxv2, pWr, pWk, pWv, pWv,
        rb, kb, vb, v2b, tdecay,
        (size_t)BIGN, 0, BT, Cc, Cc, Cc, make_int4(0, 0, 0, 0));

    // LoRA GEMMs (z=2, mode 2: tanh -> half planes)
    k_gemm6<<<dim3(1, BT / 128, 2), 256, gemmSmem>>>(
        pxw, pxv2, pxv2, pxv2, pWd, pWe, pWe, pWe,
        ptw, ptv, ptv, ptv, tdecay,
        (size_t)BIGN, (size_t)BT * 64, BT, 64, Cc, 64, make_int4(2, 2, 2, 2));

    // Epilogue GEMMs (z=2): decay (mode 3) and v2 += (mode 4), K=64
    k_gemm6<<<dim3(16, BT / 128, 2), 256, gemmSmem>>>(
        ptw, ptv, ptv, ptv, pWd2, pWe2, pWe2, pWe2,
        decay, v2b, v2b, v2b, tdecay,
        (size_t)BT * 64, 0, BT, Cc, 64, Cc, make_int4(3, 4, 4, 4));

    // WKV scan (k * (1-decay) fused)
    k_scan<<<dim3(Hh, Bb), 256>>>(wkv_in, out_wkv);

    // LayerNorm(ys + v2) -> planes
    k_ln<<<BT, 256>>>(ln_w, ln_b);

    // Output GEMM: y = ynorm @ W_o (mode 0)
    k_gemm6<<<dim3(16, BT / 128, 1), 256, gemmSmem>>>(
        pyn, pyn, pyn, pyn, pWo, pWo, pWo, pWo,
        out_y, out_y, out_y, out_y, tdecay,
        (size_t)BIGN, 0, BT, Cc, Cc, Cc, make_int4(0, 0, 0, 0));

    // shift state out
    k_copyshift<<<(Bb * Cc + 255) / 256, 256>>>(x, out_shift);
}